// round 2
// baseline (speedup 1.0000x reference)
#include <cuda_runtime.h>
#include <math.h>

#define BB 2
#define SS 2048
#define DD 1024
#define HH 16
#define MM (BB*SS)          // 4096 rows
#define KD 64               // key dim per head
#define HD 128              // head dim per head

// ---------------- scratch (device globals; no allocation allowed) ----------
__device__ float g_q[(size_t)MM * DD];
__device__ float g_k[(size_t)MM * DD];
__device__ float g_v[(size_t)MM * 2 * DD];
__device__ float g_g[(size_t)MM * 2 * DD];
__device__ float g_pre[(size_t)MM * 2 * DD];

// ---------------- generic fp32 GEMM: C = (A@B + bias) * scale --------------
// A: MxK row-major, B: KxN row-major, bias: N. 128x128 tile, 8x8 microtile.
__global__ __launch_bounds__(256) void gemm_bias(
    const float* __restrict__ A, const float* __restrict__ B,
    const float* __restrict__ bias, float* __restrict__ C,
    int M, int N, int K, float scale)
{
    const int BK = 16;
    __shared__ float As[16][128];
    __shared__ float Bs[16][128];
    int tid = threadIdx.x;
    int tx = tid & 15, ty = tid >> 4;
    int row0 = blockIdx.y * 128;
    int col0 = blockIdx.x * 128;

    float acc[8][8];
#pragma unroll
    for (int i = 0; i < 8; i++)
#pragma unroll
        for (int j = 0; j < 8; j++) acc[i][j] = 0.f;

    for (int k0 = 0; k0 < K; k0 += BK) {
        // Load A tile 128xBK, store transposed As[k][m]
#pragma unroll
        for (int l = 0; l < 2; l++) {
            int idx = tid + 256 * l;           // float4 index, 512 total
            int r  = idx >> 2;                 // 0..127
            int c4 = (idx & 3) * 4;            // 0,4,8,12
            float4 a4 = *(const float4*)&A[(size_t)(row0 + r) * K + k0 + c4];
            As[c4 + 0][r] = a4.x; As[c4 + 1][r] = a4.y;
            As[c4 + 2][r] = a4.z; As[c4 + 3][r] = a4.w;
        }
        // Load B tile BKx128
#pragma unroll
        for (int l = 0; l < 2; l++) {
            int idx = tid + 256 * l;
            int r  = idx >> 5;                 // 0..15
            int c4 = (idx & 31) * 4;           // 0..124
            *(float4*)&Bs[r][c4] =
                *(const float4*)&B[(size_t)(k0 + r) * N + col0 + c4];
        }
        __syncthreads();
#pragma unroll
        for (int kk = 0; kk < BK; kk++) {
            float4 a0 = *(float4*)&As[kk][ty * 8];
            float4 a1 = *(float4*)&As[kk][ty * 8 + 4];
            float4 b0 = *(float4*)&Bs[kk][tx * 8];
            float4 b1 = *(float4*)&Bs[kk][tx * 8 + 4];
            float av[8] = {a0.x,a0.y,a0.z,a0.w,a1.x,a1.y,a1.z,a1.w};
            float bv[8] = {b0.x,b0.y,b0.z,b0.w,b1.x,b1.y,b1.z,b1.w};
#pragma unroll
            for (int i = 0; i < 8; i++)
#pragma unroll
                for (int j = 0; j < 8; j++) acc[i][j] += av[i] * bv[j];
        }
        __syncthreads();
    }
#pragma unroll
    for (int i = 0; i < 8; i++) {
        int r = row0 + ty * 8 + i;
#pragma unroll
        for (int j0 = 0; j0 < 8; j0 += 4) {
            int c = col0 + tx * 8 + j0;
            float4 o;
            o.x = (acc[i][j0 + 0] + bias[c + 0]) * scale;
            o.y = (acc[i][j0 + 1] + bias[c + 1]) * scale;
            o.z = (acc[i][j0 + 2] + bias[c + 2]) * scale;
            o.w = (acc[i][j0 + 3] + bias[c + 3]) * scale;
            *(float4*)&C[(size_t)r * N + c] = o;
        }
    }
}

// ---------------- rotary (applied in place to q and k) ---------------------
// pair index layout: row m (0..4095), pair pp (0..511), d = 2*pp
__global__ void rotary_kernel(float* __restrict__ q, float* __restrict__ k)
{
    int idx = blockIdx.x * blockDim.x + threadIdx.x;
    if (idx >= MM * (DD / 2)) return;
    int m  = idx >> 9;            // / 512
    int pp = idx & 511;
    int d  = pp * 2;
    int s  = m & (SS - 1);        // m % 2048
    int p  = pp & 31;             // pair index within head (0..31)
    double ang = pow(10000.0, -(double)p / 31.0);
    double th  = (double)s * ang;
    double sd, cd;
    sincos(th, &sd, &cd);
    float c = (float)cd, sn = (float)sd;
    size_t off = (size_t)m * DD + d;
    float q0 = q[off], q1 = q[off + 1];
    q[off]     = q0 * c - q1 * sn;
    q[off + 1] = q1 * c + q0 * sn;
    float k0 = k[off], k1 = k[off + 1];
    k[off]     = k0 * c - k1 * sn;
    k[off + 1] = k1 * c + k0 * sn;
}

// ---------------- retention core + layernorm + silu gate -------------------
// grid: (S/64, H, B). block: 256 threads = 16x16.
// Streams causal t-tiles of 64; accumulates out(64x128) and row-sum of weights.
#define RET_SMEM_FLOATS (64*65 + 64*65 + 64*128 + 64*65)   // qs,ks,vs,sc
#define RET_SMEM_BYTES  (RET_SMEM_FLOATS * 4)

__global__ __launch_bounds__(256) void retention_kernel(
    const float* __restrict__ q, const float* __restrict__ k,
    const float* __restrict__ v, const float* __restrict__ g,
    float* __restrict__ outp)
{
    extern __shared__ float smem[];
    float (*qs)[65]  = (float(*)[65])(smem);                  // 64x65
    float (*ks)[65]  = (float(*)[65])(smem + 64 * 65);        // 64x65
    float (*vs)[128] = (float(*)[128])(smem + 2 * 64 * 65);   // 64x128
    float (*sc)[65]  = (float(*)[65])(smem + 2 * 64 * 65 + 64 * 128);

    __shared__ float erow[64];     // exp(decay*r) * invnorm(row)
    __shared__ float etab[64];     // exp(-decay*t)
    __shared__ float denom_s[64];
    __shared__ float psum[64][16];
    __shared__ float psq[64][16];

    const int sblk = blockIdx.x;          // 0..31
    const int h    = blockIdx.y;
    const int b    = blockIdx.z;
    const int tid  = threadIdx.x;
    const int tx   = tid & 15, ty = tid >> 4;
    const int ty4  = ty * 4, tx4 = tx * 4;
    const int s0   = sblk * 64;

    const float decay = log1pf(-exp2f(-5.0f - (float)h));

    // load q tile (64 x 64) for this (b, h)
    {
        const size_t qbase = ((size_t)b * SS + s0) * DD + h * KD;
        for (int i = tid; i < 64 * 16; i += 256) {   // float4 units
            int r  = i >> 4;
            int c4 = (i & 15) * 4;
            float4 t4 = *(const float4*)&q[qbase + (size_t)r * DD + c4];
            qs[r][c4 + 0] = t4.x; qs[r][c4 + 1] = t4.y;
            qs[r][c4 + 2] = t4.z; qs[r][c4 + 3] = t4.w;
        }
    }
    if (tid < 64) {
        int gs = s0 + tid;
        float rowsum = expm1f(decay * (float)(gs + 1)) / expm1f(decay);
        float iv = rsqrtf(rowsum);
        erow[tid] = expf(decay * (float)tid) * iv;
        etab[tid] = expf(-decay * (float)tid);
    }

    float acc[4][8];
#pragma unroll
    for (int i = 0; i < 4; i++)
#pragma unroll
        for (int j = 0; j < 8; j++) acc[i][j] = 0.f;
    float rowacc = 0.f;   // valid for tid < 64 (row tid)

    __syncthreads();

    for (int tb = 0; tb <= sblk; tb++) {
        const int t0 = tb * 64;
        // load k tile (64x64) and v tile (64x128)
        {
            const size_t kbase = ((size_t)b * SS + t0) * DD + h * KD;
            for (int i = tid; i < 64 * 16; i += 256) {
                int r  = i >> 4;
                int c4 = (i & 15) * 4;
                float4 t4 = *(const float4*)&k[kbase + (size_t)r * DD + c4];
                ks[r][c4 + 0] = t4.x; ks[r][c4 + 1] = t4.y;
                ks[r][c4 + 2] = t4.z; ks[r][c4 + 3] = t4.w;
            }
            const size_t vbase = ((size_t)b * SS + t0) * (2 * DD) + h * HD;
            for (int i = tid; i < 64 * 32; i += 256) {
                int r  = i >> 5;
                int c4 = (i & 31) * 4;
                *(float4*)&vs[r][c4] =
                    *(const float4*)&v[vbase + (size_t)r * (2 * DD) + c4];
            }
        }
        __syncthreads();

        // scores: 4x4 microtile per thread
        float dot[4][4];
#pragma unroll
        for (int i = 0; i < 4; i++)
#pragma unroll
            for (int j = 0; j < 4; j++) dot[i][j] = 0.f;
#pragma unroll 8
        for (int d = 0; d < 64; d++) {
            float qa[4], kb[4];
#pragma unroll
            for (int i = 0; i < 4; i++) qa[i] = qs[ty4 + i][d];
#pragma unroll
            for (int j = 0; j < 4; j++) kb[j] = ks[tx4 + j][d];
#pragma unroll
            for (int i = 0; i < 4; i++)
#pragma unroll
                for (int j = 0; j < 4; j++) dot[i][j] += qa[i] * kb[j];
        }
        const float E0 = expf(decay * (float)(s0 - t0));
#pragma unroll
        for (int i = 0; i < 4; i++) {
            int gs = s0 + ty4 + i;
            float ai = E0 * erow[ty4 + i];
#pragma unroll
            for (int j = 0; j < 4; j++) {
                int gt = t0 + tx4 + j;
                float m = (gt <= gs) ? ai * etab[tx4 + j] : 0.f;
                sc[ty4 + i][tx4 + j] = dot[i][j] * m;
            }
        }
        __syncthreads();

        // denominator partial (row sums of masked weights)
        if (tid < 64) {
            float s = 0.f;
#pragma unroll 8
            for (int t = 0; t < 64; t++) s += sc[tid][t];
            rowacc += s;
        }
        // accumulate out += sc @ v
#pragma unroll 4
        for (int t = 0; t < 64; t++) {
            float4 v0 = *(float4*)&vs[t][tx * 8];
            float4 v1 = *(float4*)&vs[t][tx * 8 + 4];
#pragma unroll
            for (int i = 0; i < 4; i++) {
                float a = sc[ty4 + i][t];
                acc[i][0] += a * v0.x; acc[i][1] += a * v0.y;
                acc[i][2] += a * v0.z; acc[i][3] += a * v0.w;
                acc[i][4] += a * v1.x; acc[i][5] += a * v1.y;
                acc[i][6] += a * v1.z; acc[i][7] += a * v1.w;
            }
        }
        __syncthreads();
    }

    if (tid < 64) denom_s[tid] = fmaxf(fabsf(rowacc), 1.0f);
    __syncthreads();

    // divide by denom; layernorm partials across the 16 col-threads per row
#pragma unroll
    for (int i = 0; i < 4; i++) {
        float inv = 1.0f / denom_s[ty4 + i];
        float s = 0.f, s2 = 0.f;
#pragma unroll
        for (int j = 0; j < 8; j++) {
            acc[i][j] *= inv;
            s  += acc[i][j];
            s2 += acc[i][j] * acc[i][j];
        }
        psum[ty4 + i][tx] = s;
        psq [ty4 + i][tx] = s2;
    }
    __syncthreads();

    const size_t obase = ((size_t)b * SS + s0) * (2 * DD) + h * HD;
#pragma unroll
    for (int i = 0; i < 4; i++) {
        int r = ty4 + i;
        float s = 0.f, s2 = 0.f;
#pragma unroll
        for (int p = 0; p < 16; p++) { s += psum[r][p]; s2 += psq[r][p]; }
        float mu  = s * (1.0f / 128.0f);
        float var = s2 * (1.0f / 128.0f) - mu * mu;
        float inv = rsqrtf(var + 1e-5f);

        size_t go = obase + (size_t)r * (2 * DD) + tx * 8;
        float4 g0 = *(const float4*)&g[go];
        float4 g1 = *(const float4*)&g[go + 4];
        float gg[8] = {g0.x,g0.y,g0.z,g0.w,g1.x,g1.y,g1.z,g1.w};
        float o[8];
#pragma unroll
        for (int j = 0; j < 8; j++) {
            float nv = (acc[i][j] - mu) * inv;
            float gv = gg[j];
            o[j] = nv * (gv / (1.0f + expf(-gv)));   // silu(g) * norm(out)
        }
        float4 o0 = {o[0], o[1], o[2], o[3]};
        float4 o1 = {o[4], o[5], o[6], o[7]};
        *(float4*)&outp[go]     = o0;
        *(float4*)&outp[go + 4] = o1;
    }
}

// ---------------- launch ---------------------------------------------------
extern "C" void kernel_launch(void* const* d_in, const int* in_sizes, int n_in,
                              void* d_out, int out_size)
{
    (void)in_sizes; (void)n_in; (void)out_size;
    const float* x  = (const float*)d_in[0];
    const float* Wq = (const float*)d_in[1];
    const float* bq = (const float*)d_in[2];
    const float* Wk = (const float*)d_in[3];
    const float* bk = (const float*)d_in[4];
    const float* Wv = (const float*)d_in[5];
    const float* bv = (const float*)d_in[6];
    const float* Wg = (const float*)d_in[7];
    const float* bg = (const float*)d_in[8];
    const float* Wo = (const float*)d_in[9];
    const float* bo = (const float*)d_in[10];
    float* out = (float*)d_out;

    float *q, *k, *v, *g, *pre;
    cudaGetSymbolAddress((void**)&q,   g_q);
    cudaGetSymbolAddress((void**)&k,   g_k);
    cudaGetSymbolAddress((void**)&v,   g_v);
    cudaGetSymbolAddress((void**)&g,   g_g);
    cudaGetSymbolAddress((void**)&pre, g_pre);

    cudaFuncSetAttribute(retention_kernel,
                         cudaFuncAttributeMaxDynamicSharedMemorySize,
                         RET_SMEM_BYTES);

    const float kscale = 0.125f;   // key_dim^-0.5, 64^-0.5
    dim3 thr(256);

    gemm_bias<<<dim3(DD / 128,     MM / 128), thr>>>(x, Wq, bq, q,  MM, DD,     DD,     1.0f);
    gemm_bias<<<dim3(DD / 128,     MM / 128), thr>>>(x, Wk, bk, k,  MM, DD,     DD,     kscale);
    gemm_bias<<<dim3(2 * DD / 128, MM / 128), thr>>>(x, Wv, bv, v,  MM, 2 * DD, DD,     1.0f);
    gemm_bias<<<dim3(2 * DD / 128, MM / 128), thr>>>(x, Wg, bg, g,  MM, 2 * DD, DD,     1.0f);

    rotary_kernel<<<(MM * (DD / 2) + 255) / 256, 256>>>(q, k);

    retention_kernel<<<dim3(SS / 64, HH, BB), 256, RET_SMEM_BYTES>>>(q, k, v, g, pre);

    gemm_bias<<<dim3(DD / 128, MM / 128), thr>>>(pre, Wo, bo, out, MM, DD, 2 * DD, 1.0f);
}

// round 3
// speedup vs baseline: 1.6281x; 1.6281x over previous
#include <cuda_runtime.h>
#include <math.h>
#include <stdint.h>

#define BB 2
#define SS 2048
#define DD 1024
#define HH 16
#define MM (BB*SS)          // 4096 rows
#define KD 64               // key dim per head
#define HD 128              // head dim per head

// ---------------- scratch (device globals; no allocation allowed) ----------
__device__ float g_q[(size_t)MM * DD];
__device__ float g_k[(size_t)MM * DD];
__device__ float g_v[(size_t)MM * 2 * DD];
__device__ float g_g[(size_t)MM * 2 * DD];
__device__ float g_pre[(size_t)MM * 2 * DD];

// ---------------- tf32 helpers ---------------------------------------------
__device__ __forceinline__ uint32_t f2tf32(float x) {
    uint32_t r;
    asm("cvt.rna.tf32.f32 %0, %1;" : "=r"(r) : "f"(x));
    return r;
}

__device__ __forceinline__ void mma_tf32(float c[4], const uint32_t a[4],
                                         const uint32_t b[2]) {
    asm volatile(
        "mma.sync.aligned.m16n8k8.row.col.f32.tf32.tf32.f32 "
        "{%0,%1,%2,%3}, {%4,%5,%6,%7}, {%8,%9}, {%0,%1,%2,%3};"
        : "+f"(c[0]), "+f"(c[1]), "+f"(c[2]), "+f"(c[3])
        : "r"(a[0]), "r"(a[1]), "r"(a[2]), "r"(a[3]),
          "r"(b[0]), "r"(b[1]));
}

// ---------------- tf32 tensor-core GEMM: C = (A@B + bias) * scale ----------
// A: MxK row-major fp32, B: KxN row-major fp32, bias: N.
// Block tile 128x128, BK=32. 8 warps: warp (wm,wn) owns 64x32.
// Each warp: 4 m-tiles (16) x 4 n-tiles (8) of m16n8k8 tf32 mma.
__global__ __launch_bounds__(256, 2) void gemm_tf32(
    const float* __restrict__ A, const float* __restrict__ B,
    const float* __restrict__ bias, float* __restrict__ C,
    int M, int N, int K, float scale)
{
    __shared__ uint32_t As[128][36];   // [m][k], pad 36 -> bank = m*4+k (cf-free)
    __shared__ uint32_t Bs[32][136];   // [k][n], pad 136 -> bank = k*8+n (cf-free)

    const int tid  = threadIdx.x;
    const int warp = tid >> 5, lane = tid & 31;
    const int wm = warp & 1, wn = warp >> 1;       // 2 x 4 warp grid
    const int row0 = blockIdx.y * 128;
    const int col0 = blockIdx.x * 128;
    const int lr = lane >> 2;      // 0..7
    const int lc = lane & 3;       // 0..3

    float acc[4][4][4];
#pragma unroll
    for (int mt = 0; mt < 4; mt++)
#pragma unroll
        for (int nt = 0; nt < 4; nt++)
#pragma unroll
            for (int r = 0; r < 4; r++) acc[mt][nt][r] = 0.f;

    for (int k0 = 0; k0 < K; k0 += 32) {
        // stage A tile 128x32 (cvt to tf32)
#pragma unroll
        for (int l = 0; l < 4; l++) {
            int f  = tid + 256 * l;          // 0..1023 float4 units
            int r  = f >> 3;                 // 0..127
            int c4 = (f & 7) * 4;            // 0..28
            float4 a4 = *(const float4*)&A[(size_t)(row0 + r) * K + k0 + c4];
            uint4 u;
            u.x = f2tf32(a4.x); u.y = f2tf32(a4.y);
            u.z = f2tf32(a4.z); u.w = f2tf32(a4.w);
            *(uint4*)&As[r][c4] = u;
        }
        // stage B tile 32x128
#pragma unroll
        for (int l = 0; l < 4; l++) {
            int f  = tid + 256 * l;
            int r  = f >> 5;                 // 0..31
            int c4 = (f & 31) * 4;           // 0..124
            float4 b4 = *(const float4*)&B[(size_t)(k0 + r) * N + col0 + c4];
            uint4 u;
            u.x = f2tf32(b4.x); u.y = f2tf32(b4.y);
            u.z = f2tf32(b4.z); u.w = f2tf32(b4.w);
            *(uint4*)&Bs[r][c4] = u;
        }
        __syncthreads();

#pragma unroll
        for (int ks = 0; ks < 4; ks++) {
            const int kb = ks * 8;
            uint32_t afr[4][4];
#pragma unroll
            for (int mt = 0; mt < 4; mt++) {
                int mrow = wm * 64 + mt * 16 + lr;
                afr[mt][0] = As[mrow    ][kb + lc];
                afr[mt][1] = As[mrow + 8][kb + lc];
                afr[mt][2] = As[mrow    ][kb + 4 + lc];
                afr[mt][3] = As[mrow + 8][kb + 4 + lc];
            }
            uint32_t bfr[4][2];
#pragma unroll
            for (int nt = 0; nt < 4; nt++) {
                int ncol = wn * 32 + nt * 8 + lr;
                bfr[nt][0] = Bs[kb + lc    ][ncol];
                bfr[nt][1] = Bs[kb + 4 + lc][ncol];
            }
#pragma unroll
            for (int mt = 0; mt < 4; mt++)
#pragma unroll
                for (int nt = 0; nt < 4; nt++)
                    mma_tf32(acc[mt][nt], afr[mt], bfr[nt]);
        }
        __syncthreads();
    }

    // epilogue: (acc + bias) * scale
#pragma unroll
    for (int mt = 0; mt < 4; mt++) {
        int r0 = row0 + wm * 64 + mt * 16 + lr;
        int r1 = r0 + 8;
#pragma unroll
        for (int nt = 0; nt < 4; nt++) {
            int c = col0 + wn * 32 + nt * 8 + 2 * lc;
            float b0 = bias[c], b1 = bias[c + 1];
            float2 o0 = { (acc[mt][nt][0] + b0) * scale,
                          (acc[mt][nt][1] + b1) * scale };
            float2 o1 = { (acc[mt][nt][2] + b0) * scale,
                          (acc[mt][nt][3] + b1) * scale };
            *(float2*)&C[(size_t)r0 * N + c] = o0;
            *(float2*)&C[(size_t)r1 * N + c] = o1;
        }
    }
}

// ---------------- rotary (applied in place to q and k) ---------------------
__global__ void rotary_kernel(float* __restrict__ q, float* __restrict__ k)
{
    int idx = blockIdx.x * blockDim.x + threadIdx.x;
    if (idx >= MM * (DD / 2)) return;
    int m  = idx >> 9;            // / 512
    int pp = idx & 511;
    int d  = pp * 2;
    int s  = m & (SS - 1);        // m % 2048
    int p  = pp & 31;             // pair index within head (0..31)
    double ang = pow(10000.0, -(double)p / 31.0);
    double th  = (double)s * ang;
    double sd, cd;
    sincos(th, &sd, &cd);
    float c = (float)cd, sn = (float)sd;
    size_t off = (size_t)m * DD + d;
    float q0 = q[off], q1 = q[off + 1];
    q[off]     = q0 * c - q1 * sn;
    q[off + 1] = q1 * c + q0 * sn;
    float k0 = k[off], k1 = k[off + 1];
    k[off]     = k0 * c - k1 * sn;
    k[off + 1] = k1 * c + k0 * sn;
}

// ---------------- retention core + layernorm + silu gate -------------------
// grid: (S/64, H, B). block: 256 threads = 16x16.
#define RET_SMEM_FLOATS (64*65 + 64*65 + 64*128 + 64*65)   // qs,ks,vs,sc
#define RET_SMEM_BYTES  (RET_SMEM_FLOATS * 4)

__global__ __launch_bounds__(256) void retention_kernel(
    const float* __restrict__ q, const float* __restrict__ k,
    const float* __restrict__ v, const float* __restrict__ g,
    float* __restrict__ outp)
{
    extern __shared__ float smem[];
    float (*qs)[65]  = (float(*)[65])(smem);                  // 64x65
    float (*ks)[65]  = (float(*)[65])(smem + 64 * 65);        // 64x65
    float (*vs)[128] = (float(*)[128])(smem + 2 * 64 * 65);   // 64x128
    float (*sc)[65]  = (float(*)[65])(smem + 2 * 64 * 65 + 64 * 128);

    __shared__ float erow[64];     // exp(decay*r) * invnorm(row)
    __shared__ float etab[64];     // exp(-decay*t)
    __shared__ float denom_s[64];
    __shared__ float psum[64][16];
    __shared__ float psq[64][16];

    const int sblk = blockIdx.x;          // 0..31
    const int h    = blockIdx.y;
    const int b    = blockIdx.z;
    const int tid  = threadIdx.x;
    const int tx   = tid & 15, ty = tid >> 4;
    const int ty4  = ty * 4, tx4 = tx * 4;
    const int s0   = sblk * 64;

    const float decay = log1pf(-exp2f(-5.0f - (float)h));

    // load q tile (64 x 64) for this (b, h)
    {
        const size_t qbase = ((size_t)b * SS + s0) * DD + h * KD;
        for (int i = tid; i < 64 * 16; i += 256) {   // float4 units
            int r  = i >> 4;
            int c4 = (i & 15) * 4;
            float4 t4 = *(const float4*)&q[qbase + (size_t)r * DD + c4];
            qs[r][c4 + 0] = t4.x; qs[r][c4 + 1] = t4.y;
            qs[r][c4 + 2] = t4.z; qs[r][c4 + 3] = t4.w;
        }
    }
    if (tid < 64) {
        int gs = s0 + tid;
        float rowsum = expm1f(decay * (float)(gs + 1)) / expm1f(decay);
        float iv = rsqrtf(rowsum);
        erow[tid] = expf(decay * (float)tid) * iv;
        etab[tid] = expf(-decay * (float)tid);
    }

    float acc[4][8];
#pragma unroll
    for (int i = 0; i < 4; i++)
#pragma unroll
        for (int j = 0; j < 8; j++) acc[i][j] = 0.f;
    float rowacc = 0.f;   // valid for tid < 64 (row tid)

    __syncthreads();

    for (int tb = 0; tb <= sblk; tb++) {
        const int t0 = tb * 64;
        // load k tile (64x64) and v tile (64x128)
        {
            const size_t kbase = ((size_t)b * SS + t0) * DD + h * KD;
            for (int i = tid; i < 64 * 16; i += 256) {
                int r  = i >> 4;
                int c4 = (i & 15) * 4;
                float4 t4 = *(const float4*)&k[kbase + (size_t)r * DD + c4];
                ks[r][c4 + 0] = t4.x; ks[r][c4 + 1] = t4.y;
                ks[r][c4 + 2] = t4.z; ks[r][c4 + 3] = t4.w;
            }
            const size_t vbase = ((size_t)b * SS + t0) * (2 * DD) + h * HD;
            for (int i = tid; i < 64 * 32; i += 256) {
                int r  = i >> 5;
                int c4 = (i & 31) * 4;
                *(float4*)&vs[r][c4] =
                    *(const float4*)&v[vbase + (size_t)r * (2 * DD) + c4];
            }
        }
        __syncthreads();

        // scores: 4x4 microtile per thread
        float dot[4][4];
#pragma unroll
        for (int i = 0; i < 4; i++)
#pragma unroll
            for (int j = 0; j < 4; j++) dot[i][j] = 0.f;
#pragma unroll 8
        for (int d = 0; d < 64; d++) {
            float qa[4], kb[4];
#pragma unroll
            for (int i = 0; i < 4; i++) qa[i] = qs[ty4 + i][d];
#pragma unroll
            for (int j = 0; j < 4; j++) kb[j] = ks[tx4 + j][d];
#pragma unroll
            for (int i = 0; i < 4; i++)
#pragma unroll
                for (int j = 0; j < 4; j++) dot[i][j] += qa[i] * kb[j];
        }
        const float E0 = expf(decay * (float)(s0 - t0));
#pragma unroll
        for (int i = 0; i < 4; i++) {
            int gs = s0 + ty4 + i;
            float ai = E0 * erow[ty4 + i];
#pragma unroll
            for (int j = 0; j < 4; j++) {
                int gt = t0 + tx4 + j;
                float m = (gt <= gs) ? ai * etab[tx4 + j] : 0.f;
                sc[ty4 + i][tx4 + j] = dot[i][j] * m;
            }
        }
        __syncthreads();

        // denominator partial (row sums of masked weights)
        if (tid < 64) {
            float s = 0.f;
#pragma unroll 8
            for (int t = 0; t < 64; t++) s += sc[tid][t];
            rowacc += s;
        }
        // accumulate out += sc @ v
#pragma unroll 4
        for (int t = 0; t < 64; t++) {
            float4 v0 = *(float4*)&vs[t][tx * 8];
            float4 v1 = *(float4*)&vs[t][tx * 8 + 4];
#pragma unroll
            for (int i = 0; i < 4; i++) {
                float a = sc[ty4 + i][t];
                acc[i][0] += a * v0.x; acc[i][1] += a * v0.y;
                acc[i][2] += a * v0.z; acc[i][3] += a * v0.w;
                acc[i][4] += a * v1.x; acc[i][5] += a * v1.y;
                acc[i][6] += a * v1.z; acc[i][7] += a * v1.w;
            }
        }
        __syncthreads();
    }

    if (tid < 64) denom_s[tid] = fmaxf(fabsf(rowacc), 1.0f);
    __syncthreads();

    // divide by denom; layernorm partials across the 16 col-threads per row
#pragma unroll
    for (int i = 0; i < 4; i++) {
        float inv = 1.0f / denom_s[ty4 + i];
        float s = 0.f, s2 = 0.f;
#pragma unroll
        for (int j = 0; j < 8; j++) {
            acc[i][j] *= inv;
            s  += acc[i][j];
            s2 += acc[i][j] * acc[i][j];
        }
        psum[ty4 + i][tx] = s;
        psq [ty4 + i][tx] = s2;
    }
    __syncthreads();

    const size_t obase = ((size_t)b * SS + s0) * (2 * DD) + h * HD;
#pragma unroll
    for (int i = 0; i < 4; i++) {
        int r = ty4 + i;
        float s = 0.f, s2 = 0.f;
#pragma unroll
        for (int p = 0; p < 16; p++) { s += psum[r][p]; s2 += psq[r][p]; }
        float mu  = s * (1.0f / 128.0f);
        float var = s2 * (1.0f / 128.0f) - mu * mu;
        float inv = rsqrtf(var + 1e-5f);

        size_t go = obase + (size_t)r * (2 * DD) + tx * 8;
        float4 g0 = *(const float4*)&g[go];
        float4 g1 = *(const float4*)&g[go + 4];
        float gg[8] = {g0.x,g0.y,g0.z,g0.w,g1.x,g1.y,g1.z,g1.w};
        float o[8];
#pragma unroll
        for (int j = 0; j < 8; j++) {
            float nv = (acc[i][j] - mu) * inv;
            float gv = gg[j];
            o[j] = nv * (gv / (1.0f + expf(-gv)));   // silu(g) * norm(out)
        }
        float4 o0 = {o[0], o[1], o[2], o[3]};
        float4 o1 = {o[4], o[5], o[6], o[7]};
        *(float4*)&outp[go]     = o0;
        *(float4*)&outp[go + 4] = o1;
    }
}

// ---------------- launch ---------------------------------------------------
extern "C" void kernel_launch(void* const* d_in, const int* in_sizes, int n_in,
                              void* d_out, int out_size)
{
    (void)in_sizes; (void)n_in; (void)out_size;
    const float* x  = (const float*)d_in[0];
    const float* Wq = (const float*)d_in[1];
    const float* bq = (const float*)d_in[2];
    const float* Wk = (const float*)d_in[3];
    const float* bk = (const float*)d_in[4];
    const float* Wv = (const float*)d_in[5];
    const float* bv = (const float*)d_in[6];
    const float* Wg = (const float*)d_in[7];
    const float* bg = (const float*)d_in[8];
    const float* Wo = (const float*)d_in[9];
    const float* bo = (const float*)d_in[10];
    float* out = (float*)d_out;

    float *q, *k, *v, *g, *pre;
    cudaGetSymbolAddress((void**)&q,   g_q);
    cudaGetSymbolAddress((void**)&k,   g_k);
    cudaGetSymbolAddress((void**)&v,   g_v);
    cudaGetSymbolAddress((void**)&g,   g_g);
    cudaGetSymbolAddress((void**)&pre, g_pre);

    cudaFuncSetAttribute(retention_kernel,
                         cudaFuncAttributeMaxDynamicSharedMemorySize,
                         RET_SMEM_BYTES);

    const float kscale = 0.125f;   // key_dim^-0.5 = 64^-0.5
    dim3 thr(256);

    gemm_tf32<<<dim3(DD / 128,     MM / 128), thr>>>(x, Wq, bq, q,  MM, DD,     DD,     1.0f);
    gemm_tf32<<<dim3(DD / 128,     MM / 128), thr>>>(x, Wk, bk, k,  MM, DD,     DD,     kscale);
    gemm_tf32<<<dim3(2 * DD / 128, MM / 128), thr>>>(x, Wv, bv, v,  MM, 2 * DD, DD,     1.0f);
    gemm_tf32<<<dim3(2 * DD / 128, MM / 128), thr>>>(x, Wg, bg, g,  MM, 2 * DD, DD,     1.0f);

    rotary_kernel<<<(MM * (DD / 2) + 255) / 256, 256>>>(q, k);

    retention_kernel<<<dim3(SS / 64, HH, BB), 256, RET_SMEM_BYTES>>>(q, k, v, g, pre);

    gemm_tf32<<<dim3(DD / 128, MM / 128), thr>>>(pre, Wo, bo, out, MM, DD, 2 * DD, 1.0f);
}

// round 4
// speedup vs baseline: 2.4421x; 1.4999x over previous
#include <cuda_runtime.h>
#include <math.h>
#include <stdint.h>

#define BB 2
#define SS 2048
#define DD 1024
#define HH 16
#define MM (BB*SS)          // 4096 rows
#define KD 64               // key dim per head
#define HD 128              // head dim per head

// ---------------- scratch (device globals; no allocation allowed) ----------
__device__ float g_q[(size_t)MM * DD];
__device__ float g_k[(size_t)MM * DD];
__device__ float g_v[(size_t)MM * 2 * DD];
__device__ float g_g[(size_t)MM * 2 * DD];
__device__ float g_pre[(size_t)MM * 2 * DD];

// ---------------- tf32 helpers ---------------------------------------------
__device__ __forceinline__ uint32_t f2tf32(float x) {
    uint32_t r;
    asm("cvt.rna.tf32.f32 %0, %1;" : "=r"(r) : "f"(x));
    return r;
}

__device__ __forceinline__ void mma_tf32(float c[4], const uint32_t a[4],
                                         const uint32_t b[2]) {
    asm volatile(
        "mma.sync.aligned.m16n8k8.row.col.f32.tf32.tf32.f32 "
        "{%0,%1,%2,%3}, {%4,%5,%6,%7}, {%8,%9}, {%0,%1,%2,%3};"
        : "+f"(c[0]), "+f"(c[1]), "+f"(c[2]), "+f"(c[3])
        : "r"(a[0]), "r"(a[1]), "r"(a[2]), "r"(a[3]),
          "r"(b[0]), "r"(b[1]));
}

// ---------------- tf32 tensor-core GEMM: C = (A@B + bias) * scale ----------
__global__ __launch_bounds__(256, 2) void gemm_tf32(
    const float* __restrict__ A, const float* __restrict__ B,
    const float* __restrict__ bias, float* __restrict__ C,
    int M, int N, int K, float scale)
{
    __shared__ uint32_t As[128][36];   // [m][k], bank = m*4+k (cf-free)
    __shared__ uint32_t Bs[32][136];   // [k][n], bank = k*8+n (cf-free)

    const int tid  = threadIdx.x;
    const int warp = tid >> 5, lane = tid & 31;
    const int wm = warp & 1, wn = warp >> 1;       // 2 x 4 warp grid
    const int row0 = blockIdx.y * 128;
    const int col0 = blockIdx.x * 128;
    const int lr = lane >> 2;      // 0..7
    const int lc = lane & 3;       // 0..3

    float acc[4][4][4];
#pragma unroll
    for (int mt = 0; mt < 4; mt++)
#pragma unroll
        for (int nt = 0; nt < 4; nt++)
#pragma unroll
            for (int r = 0; r < 4; r++) acc[mt][nt][r] = 0.f;

    for (int k0 = 0; k0 < K; k0 += 32) {
#pragma unroll
        for (int l = 0; l < 4; l++) {
            int f  = tid + 256 * l;
            int r  = f >> 3;
            int c4 = (f & 7) * 4;
            float4 a4 = *(const float4*)&A[(size_t)(row0 + r) * K + k0 + c4];
            uint4 u;
            u.x = f2tf32(a4.x); u.y = f2tf32(a4.y);
            u.z = f2tf32(a4.z); u.w = f2tf32(a4.w);
            *(uint4*)&As[r][c4] = u;
        }
#pragma unroll
        for (int l = 0; l < 4; l++) {
            int f  = tid + 256 * l;
            int r  = f >> 5;
            int c4 = (f & 31) * 4;
            float4 b4 = *(const float4*)&B[(size_t)(k0 + r) * N + col0 + c4];
            uint4 u;
            u.x = f2tf32(b4.x); u.y = f2tf32(b4.y);
            u.z = f2tf32(b4.z); u.w = f2tf32(b4.w);
            *(uint4*)&Bs[r][c4] = u;
        }
        __syncthreads();

#pragma unroll
        for (int ks = 0; ks < 4; ks++) {
            const int kb = ks * 8;
            uint32_t afr[4][4];
#pragma unroll
            for (int mt = 0; mt < 4; mt++) {
                int mrow = wm * 64 + mt * 16 + lr;
                afr[mt][0] = As[mrow    ][kb + lc];
                afr[mt][1] = As[mrow + 8][kb + lc];
                afr[mt][2] = As[mrow    ][kb + 4 + lc];
                afr[mt][3] = As[mrow + 8][kb + 4 + lc];
            }
            uint32_t bfr[4][2];
#pragma unroll
            for (int nt = 0; nt < 4; nt++) {
                int ncol = wn * 32 + nt * 8 + lr;
                bfr[nt][0] = Bs[kb + lc    ][ncol];
                bfr[nt][1] = Bs[kb + 4 + lc][ncol];
            }
#pragma unroll
            for (int mt = 0; mt < 4; mt++)
#pragma unroll
                for (int nt = 0; nt < 4; nt++)
                    mma_tf32(acc[mt][nt], afr[mt], bfr[nt]);
        }
        __syncthreads();
    }

#pragma unroll
    for (int mt = 0; mt < 4; mt++) {
        int r0 = row0 + wm * 64 + mt * 16 + lr;
        int r1 = r0 + 8;
#pragma unroll
        for (int nt = 0; nt < 4; nt++) {
            int c = col0 + wn * 32 + nt * 8 + 2 * lc;
            float b0 = bias[c], b1 = bias[c + 1];
            float2 o0 = { (acc[mt][nt][0] + b0) * scale,
                          (acc[mt][nt][1] + b1) * scale };
            float2 o1 = { (acc[mt][nt][2] + b0) * scale,
                          (acc[mt][nt][3] + b1) * scale };
            *(float2*)&C[(size_t)r0 * N + c] = o0;
            *(float2*)&C[(size_t)r1 * N + c] = o1;
        }
    }
}

// ---------------- rotary (applied in place to q and k) ---------------------
__global__ void rotary_kernel(float* __restrict__ q, float* __restrict__ k)
{
    int idx = blockIdx.x * blockDim.x + threadIdx.x;
    if (idx >= MM * (DD / 2)) return;
    int m  = idx >> 9;
    int pp = idx & 511;
    int d  = pp * 2;
    int s  = m & (SS - 1);
    int p  = pp & 31;
    double ang = pow(10000.0, -(double)p / 31.0);
    double th  = (double)s * ang;
    double sd, cd;
    sincos(th, &sd, &cd);
    float c = (float)cd, sn = (float)sd;
    size_t off = (size_t)m * DD + d;
    float q0 = q[off], q1 = q[off + 1];
    q[off]     = q0 * c - q1 * sn;
    q[off + 1] = q1 * c + q0 * sn;
    float k0 = k[off], k1 = k[off + 1];
    k[off]     = k0 * c - k1 * sn;
    k[off + 1] = k1 * c + k0 * sn;
}

// ---------------- retention core (tf32 MMA, compensated) -------------------
// grid: (S/64, H, B). block: 256 threads = 8 warps.
// Warp (wm = w&3, wn = w>>2). QK: warp owns m16(wm) x n32(wn), tf32x3.
// AV: warp owns m16(wm) x n64(wn), tf32x2 (compensate weights only).
// smem layouts (stride mod 32): qs/ks/sc stride 68 (A-ops & B-op of QK),
// vs stride 136 (B-op of AV). All fragment reads bank-conflict-free.
#define RET2_SMEM_FLOATS (64*68 + 64*68 + 64*136 + 64*68)
#define RET2_SMEM_BYTES  (RET2_SMEM_FLOATS * 4)   // 87040

__global__ __launch_bounds__(256, 2) void retention_mma(
    const float* __restrict__ q, const float* __restrict__ k,
    const float* __restrict__ v, const float* __restrict__ g,
    float* __restrict__ outp)
{
    extern __shared__ float sm[];
    float (*qs)[68]  = (float(*)[68])(sm);
    float (*ks)[68]  = (float(*)[68])(sm + 64 * 68);
    float (*vs)[136] = (float(*)[136])(sm + 2 * 64 * 68);
    float (*sc)[68]  = (float(*)[68])(sm + 2 * 64 * 68 + 64 * 136);

    __shared__ float erow[64];     // exp(decay*r) * invnorm(global row)
    __shared__ float etab[64];     // exp(-decay*t_local)
    __shared__ float denom_s[64];
    __shared__ float psum[64][2], psq[64][2];

    const int sblk = blockIdx.x;
    const int h    = blockIdx.y;
    const int b    = blockIdx.z;
    const int tid  = threadIdx.x;
    const int warp = tid >> 5, lane = tid & 31;
    const int wm = warp & 3, wn = warp >> 2;
    const int lr = lane >> 2, lc = lane & 3;
    const int s0 = sblk * 64;

    const float decay = log1pf(-exp2f(-5.0f - (float)h));

    // stage q tile 64x64
    {
        const size_t qbase = ((size_t)b * SS + s0) * DD + h * KD;
#pragma unroll
        for (int l = 0; l < 4; l++) {
            int i  = tid + 256 * l;
            int r  = i >> 4;
            int c4 = (i & 15) * 4;
            *(float4*)&qs[r][c4] =
                *(const float4*)&q[qbase + (size_t)r * DD + c4];
        }
    }
    if (tid < 64) {
        int gs = s0 + tid;
        float rowsum = expm1f(decay * (float)(gs + 1)) / expm1f(decay);
        erow[tid] = expf(decay * (float)tid) * rsqrtf(rowsum);
        etab[tid] = expf(-decay * (float)tid);
    }

    float oacc[8][4];
#pragma unroll
    for (int nt = 0; nt < 8; nt++)
#pragma unroll
        for (int r = 0; r < 4; r++) oacc[nt][r] = 0.f;
    float rowacc = 0.f;

    __syncthreads();

    const int r0l = wm * 16 + lr;      // local row this thread covers (+8)

    for (int tb = 0; tb <= sblk; tb++) {
        const int t0 = tb * 64;
        // stage k tile 64x64 and v tile 64x128
        {
            const size_t kbase = ((size_t)b * SS + t0) * DD + h * KD;
#pragma unroll
            for (int l = 0; l < 4; l++) {
                int i  = tid + 256 * l;
                int r  = i >> 4;
                int c4 = (i & 15) * 4;
                *(float4*)&ks[r][c4] =
                    *(const float4*)&k[kbase + (size_t)r * DD + c4];
            }
            const size_t vbase = ((size_t)b * SS + t0) * (2 * DD) + h * HD;
#pragma unroll
            for (int l = 0; l < 8; l++) {
                int i  = tid + 256 * l;
                int r  = i >> 5;
                int c4 = (i & 31) * 4;
                *(float4*)&vs[r][c4] =
                    *(const float4*)&v[vbase + (size_t)r * (2 * DD) + c4];
            }
        }
        __syncthreads();

        // ---- QK^T (tf32x3 compensated) ----
        float qk[4][4];
#pragma unroll
        for (int nt = 0; nt < 4; nt++)
#pragma unroll
            for (int r = 0; r < 4; r++) qk[nt][r] = 0.f;

#pragma unroll
        for (int kk = 0; kk < 8; kk++) {
            const int kb = kk * 8;
            uint32_t ahi[4], alo[4];
#pragma unroll
            for (int e = 0; e < 4; e++) {
                float a = qs[r0l + (e & 1) * 8][kb + lc + (e >> 1) * 4];
                uint32_t hh = f2tf32(a);
                ahi[e] = hh;
                alo[e] = f2tf32(a - __uint_as_float(hh));
            }
#pragma unroll
            for (int nt = 0; nt < 4; nt++) {
                int ncol = wn * 32 + nt * 8 + lr;
                float b0f = ks[ncol][kb + lc];
                float b1f = ks[ncol][kb + 4 + lc];
                uint32_t bh[2] = { f2tf32(b0f), f2tf32(b1f) };
                uint32_t bl[2] = { f2tf32(b0f - __uint_as_float(bh[0])),
                                   f2tf32(b1f - __uint_as_float(bh[1])) };
                mma_tf32(qk[nt], ahi, bh);
                mma_tf32(qk[nt], alo, bh);
                mma_tf32(qk[nt], ahi, bl);
            }
        }

        // ---- mask + write scores to smem ----
        {
            const float E0  = expf(decay * (float)(s0 - t0));
            const float ai0 = E0 * erow[r0l];
            const float ai1 = E0 * erow[r0l + 8];
            const int gs0r = s0 + r0l, gs1r = gs0r + 8;
#pragma unroll
            for (int nt = 0; nt < 4; nt++) {
                int c  = wn * 32 + nt * 8 + 2 * lc;
                int gt0 = t0 + c, gt1 = gt0 + 1;
                float e0 = etab[c], e1 = etab[c + 1];
                float2 w0, w1;
                w0.x = (gt0 <= gs0r) ? qk[nt][0] * (ai0 * e0) : 0.f;
                w0.y = (gt1 <= gs0r) ? qk[nt][1] * (ai0 * e1) : 0.f;
                w1.x = (gt0 <= gs1r) ? qk[nt][2] * (ai1 * e0) : 0.f;
                w1.y = (gt1 <= gs1r) ? qk[nt][3] * (ai1 * e1) : 0.f;
                *(float2*)&sc[r0l][c]     = w0;
                *(float2*)&sc[r0l + 8][c] = w1;
            }
        }
        __syncthreads();

        // denominator partials
        if (tid < 64) {
            float s = 0.f;
#pragma unroll 8
            for (int t = 0; t < 64; t++) s += sc[tid][t];
            rowacc += s;
        }

        // ---- score @ V (tf32x2: compensate weights) ----
#pragma unroll
        for (int kk = 0; kk < 8; kk++) {
            const int kb = kk * 8;
            uint32_t ahi[4], alo[4];
#pragma unroll
            for (int e = 0; e < 4; e++) {
                float a = sc[r0l + (e & 1) * 8][kb + lc + (e >> 1) * 4];
                uint32_t hh = f2tf32(a);
                ahi[e] = hh;
                alo[e] = f2tf32(a - __uint_as_float(hh));
            }
#pragma unroll
            for (int nt = 0; nt < 8; nt++) {
                int ncol = wn * 64 + nt * 8 + lr;
                uint32_t bb[2] = { f2tf32(vs[kb + lc    ][ncol]),
                                   f2tf32(vs[kb + 4 + lc][ncol]) };
                mma_tf32(oacc[nt], ahi, bb);
                mma_tf32(oacc[nt], alo, bb);
            }
        }
        __syncthreads();
    }

    if (tid < 64) denom_s[tid] = fmaxf(fabsf(rowacc), 1.0f);
    __syncthreads();

    // ---- epilogue: /denom, layernorm (over 128 cols), silu(g) gate --------
    const float inv0 = 1.0f / denom_s[r0l];
    const float inv1 = 1.0f / denom_s[r0l + 8];
    float sa0 = 0.f, sq0 = 0.f, sa1 = 0.f, sq1 = 0.f;
#pragma unroll
    for (int nt = 0; nt < 8; nt++) {
        oacc[nt][0] *= inv0; oacc[nt][1] *= inv0;
        oacc[nt][2] *= inv1; oacc[nt][3] *= inv1;
        sa0 += oacc[nt][0] + oacc[nt][1];
        sq0 += oacc[nt][0] * oacc[nt][0] + oacc[nt][1] * oacc[nt][1];
        sa1 += oacc[nt][2] + oacc[nt][3];
        sq1 += oacc[nt][2] * oacc[nt][2] + oacc[nt][3] * oacc[nt][3];
    }
#pragma unroll
    for (int m_ = 1; m_ <= 2; m_ <<= 1) {
        sa0 += __shfl_xor_sync(0xffffffff, sa0, m_);
        sq0 += __shfl_xor_sync(0xffffffff, sq0, m_);
        sa1 += __shfl_xor_sync(0xffffffff, sa1, m_);
        sq1 += __shfl_xor_sync(0xffffffff, sq1, m_);
    }
    if (lc == 0) {
        psum[r0l][wn] = sa0; psq[r0l][wn] = sq0;
        psum[r0l + 8][wn] = sa1; psq[r0l + 8][wn] = sq1;
    }
    __syncthreads();

    float mu0, is0, mu1, is1;
    {
        float S = psum[r0l][0] + psum[r0l][1];
        float Q = psq[r0l][0] + psq[r0l][1];
        mu0 = S * (1.0f / 128.0f);
        is0 = rsqrtf(Q * (1.0f / 128.0f) - mu0 * mu0 + 1e-5f);
        S = psum[r0l + 8][0] + psum[r0l + 8][1];
        Q = psq[r0l + 8][0] + psq[r0l + 8][1];
        mu1 = S * (1.0f / 128.0f);
        is1 = rsqrtf(Q * (1.0f / 128.0f) - mu1 * mu1 + 1e-5f);
    }

    const size_t obase = ((size_t)b * SS + s0) * (2 * DD) + h * HD;
#pragma unroll
    for (int nt = 0; nt < 8; nt++) {
        int c = wn * 64 + nt * 8 + 2 * lc;
        size_t go0 = obase + (size_t)r0l * (2 * DD) + c;
        size_t go1 = go0 + 8 * (2 * DD);
        float2 g0 = *(const float2*)&g[go0];
        float2 g1 = *(const float2*)&g[go1];
        float2 o0, o1;
        float n;
        n = (oacc[nt][0] - mu0) * is0;
        o0.x = n * (g0.x / (1.0f + expf(-g0.x)));
        n = (oacc[nt][1] - mu0) * is0;
        o0.y = n * (g0.y / (1.0f + expf(-g0.y)));
        n = (oacc[nt][2] - mu1) * is1;
        o1.x = n * (g1.x / (1.0f + expf(-g1.x)));
        n = (oacc[nt][3] - mu1) * is1;
        o1.y = n * (g1.y / (1.0f + expf(-g1.y)));
        *(float2*)&outp[go0] = o0;
        *(float2*)&outp[go1] = o1;
    }
}

// ---------------- launch ---------------------------------------------------
extern "C" void kernel_launch(void* const* d_in, const int* in_sizes, int n_in,
                              void* d_out, int out_size)
{
    (void)in_sizes; (void)n_in; (void)out_size;
    const float* x  = (const float*)d_in[0];
    const float* Wq = (const float*)d_in[1];
    const float* bq = (const float*)d_in[2];
    const float* Wk = (const float*)d_in[3];
    const float* bk = (const float*)d_in[4];
    const float* Wv = (const float*)d_in[5];
    const float* bv = (const float*)d_in[6];
    const float* Wg = (const float*)d_in[7];
    const float* bg = (const float*)d_in[8];
    const float* Wo = (const float*)d_in[9];
    const float* bo = (const float*)d_in[10];
    float* out = (float*)d_out;

    float *q, *k, *v, *g, *pre;
    cudaGetSymbolAddress((void**)&q,   g_q);
    cudaGetSymbolAddress((void**)&k,   g_k);
    cudaGetSymbolAddress((void**)&v,   g_v);
    cudaGetSymbolAddress((void**)&g,   g_g);
    cudaGetSymbolAddress((void**)&pre, g_pre);

    cudaFuncSetAttribute(retention_mma,
                         cudaFuncAttributeMaxDynamicSharedMemorySize,
                         RET2_SMEM_BYTES);

    const float kscale = 0.125f;   // 64^-0.5
    dim3 thr(256);

    gemm_tf32<<<dim3(DD / 128,     MM / 128), thr>>>(x, Wq, bq, q,  MM, DD,     DD,     1.0f);
    gemm_tf32<<<dim3(DD / 128,     MM / 128), thr>>>(x, Wk, bk, k,  MM, DD,     DD,     kscale);
    gemm_tf32<<<dim3(2 * DD / 128, MM / 128), thr>>>(x, Wv, bv, v,  MM, 2 * DD, DD,     1.0f);
    gemm_tf32<<<dim3(2 * DD / 128, MM / 128), thr>>>(x, Wg, bg, g,  MM, 2 * DD, DD,     1.0f);

    rotary_kernel<<<(MM * (DD / 2) + 255) / 256, 256>>>(q, k);

    retention_mma<<<dim3(SS / 64, HH, BB), 256, RET2_SMEM_BYTES>>>(q, k, v, g, pre);

    gemm_tf32<<<dim3(DD / 128, MM / 128), thr>>>(pre, Wo, bo, out, MM, DD, 2 * DD, 1.0f);
}

// round 6
// speedup vs baseline: 2.6062x; 1.0672x over previous
#include <cuda_runtime.h>
#include <math.h>
#include <stdint.h>

#define BB 2
#define SS 2048
#define DD 1024
#define HH 16
#define MM (BB*SS)          // 4096 rows
#define KD 64               // key dim per head
#define HD 128              // head dim per head

// ---------------- scratch (device globals; no allocation allowed) ----------
__device__ float g_q[(size_t)MM * DD];
__device__ float g_k[(size_t)MM * DD];
__device__ float g_v[(size_t)MM * 2 * DD];
__device__ float g_g[(size_t)MM * 2 * DD];
__device__ float g_pre[(size_t)MM * 2 * DD];
// tf32-pre-rounded operands
__device__ float g_xt[(size_t)MM * DD];
__device__ float g_wqt[(size_t)DD * DD];
__device__ float g_wkt[(size_t)DD * DD];
__device__ float g_wvt[(size_t)DD * 2 * DD];
__device__ float g_wgt[(size_t)DD * 2 * DD];
__device__ float g_wot[(size_t)2 * DD * DD];

// ---------------- tf32 helpers ---------------------------------------------
__device__ __forceinline__ uint32_t f2tf32(float x) {
    uint32_t r;
    asm("cvt.rna.tf32.f32 %0, %1;" : "=r"(r) : "f"(x));
    return r;
}

__device__ __forceinline__ void mma_tf32(float c[4], const uint32_t a[4],
                                         const uint32_t b[2]) {
    asm volatile(
        "mma.sync.aligned.m16n8k8.row.col.f32.tf32.tf32.f32 "
        "{%0,%1,%2,%3}, {%4,%5,%6,%7}, {%8,%9}, {%0,%1,%2,%3};"
        : "+f"(c[0]), "+f"(c[1]), "+f"(c[2]), "+f"(c[3])
        : "r"(a[0]), "r"(a[1]), "r"(a[2]), "r"(a[3]),
          "r"(b[0]), "r"(b[1]));
}

__device__ __forceinline__ void cp_async16(void* smem_ptr, const void* gptr) {
    uint32_t saddr = (uint32_t)__cvta_generic_to_shared(smem_ptr);
    asm volatile("cp.async.cg.shared.global [%0], [%1], 16;\n"
                 :: "r"(saddr), "l"(gptr));
}
__device__ __forceinline__ void cp_commit() {
    asm volatile("cp.async.commit_group;\n");
}
__device__ __forceinline__ void cp_wait1() {
    asm volatile("cp.async.wait_group 1;\n");
}
__device__ __forceinline__ void cp_wait0() {
    asm volatile("cp.async.wait_group 0;\n");
}

// ---------------- pre-round fp32 -> tf32 bits (rna) ------------------------
__global__ void round_tf32(const float* __restrict__ in,
                           float* __restrict__ out, int n4)
{
    int i = blockIdx.x * blockDim.x + threadIdx.x;
    if (i >= n4) return;
    float4 v = *(const float4*)&in[(size_t)i * 4];
    uint4 u;
    u.x = f2tf32(v.x); u.y = f2tf32(v.y);
    u.z = f2tf32(v.z); u.w = f2tf32(v.w);
    *(uint4*)&out[(size_t)i * 4] = u;
}

// ---------------- cp.async double-buffered tf32 GEMM -----------------------
// A: MxK, B: KxN (both pre-rounded tf32 bits), bias fp32.
// Block tile 128x128, BK=32, 8 warps 64x32 each, 2-stage pipeline.
#define GSTG (128*36 + 32*136)               // words per stage: 8960
#define GEMM_SMEM_BYTES (2 * GSTG * 4)       // 71680

__global__ __launch_bounds__(256, 2) void gemm_tf32_pipe(
    const float* __restrict__ A, const float* __restrict__ B,
    const float* __restrict__ bias, float* __restrict__ C,
    int M, int N, int K, float scale)
{
    extern __shared__ uint32_t dsm[];

    const int tid  = threadIdx.x;
    const int warp = tid >> 5, lane = tid & 31;
    const int wm = warp & 1, wn = warp >> 1;
    const int row0 = blockIdx.y * 128;
    const int col0 = blockIdx.x * 128;
    const int lr = lane >> 2;
    const int lc = lane & 3;

    float acc[4][4][4];
#pragma unroll
    for (int mt = 0; mt < 4; mt++)
#pragma unroll
        for (int nt = 0; nt < 4; nt++)
#pragma unroll
            for (int r = 0; r < 4; r++) acc[mt][nt][r] = 0.f;

    // stage loader: issue 8 cp.async16 per thread + commit
    auto load_stage = [&](int s, int k0) {
        uint32_t* As = dsm + s * GSTG;             // [128][36]
        uint32_t* Bs = dsm + s * GSTG + 128 * 36;  // [32][136]
#pragma unroll
        for (int l = 0; l < 4; l++) {
            int f  = tid + 256 * l;
            int r  = f >> 3;
            int c4 = (f & 7) * 4;
            cp_async16(&As[r * 36 + c4],
                       &A[(size_t)(row0 + r) * K + k0 + c4]);
        }
#pragma unroll
        for (int l = 0; l < 4; l++) {
            int f  = tid + 256 * l;
            int r  = f >> 5;
            int c4 = (f & 31) * 4;
            cp_async16(&Bs[r * 136 + c4],
                       &B[(size_t)(k0 + r) * N + col0 + c4]);
        }
        cp_commit();
    };

    load_stage(0, 0);

    int s = 0;
    for (int k0 = 0; k0 < K; k0 += 32, s ^= 1) {
        const bool has_next = (k0 + 32) < K;
        if (has_next) load_stage(s ^ 1, k0 + 32);
        if (has_next) cp_wait1(); else cp_wait0();
        __syncthreads();

        const uint32_t* As = dsm + s * GSTG;
        const uint32_t* Bs = dsm + s * GSTG + 128 * 36;

#pragma unroll
        for (int ks = 0; ks < 4; ks++) {
            const int kb = ks * 8;
            uint32_t afr[4][4];
#pragma unroll
            for (int mt = 0; mt < 4; mt++) {
                int mrow = wm * 64 + mt * 16 + lr;
                afr[mt][0] = As[(mrow    ) * 36 + kb + lc];
                afr[mt][1] = As[(mrow + 8) * 36 + kb + lc];
                afr[mt][2] = As[(mrow    ) * 36 + kb + 4 + lc];
                afr[mt][3] = As[(mrow + 8) * 36 + kb + 4 + lc];
            }
            uint32_t bfr[4][2];
#pragma unroll
            for (int nt = 0; nt < 4; nt++) {
                int ncol = wn * 32 + nt * 8 + lr;
                bfr[nt][0] = Bs[(kb + lc    ) * 136 + ncol];
                bfr[nt][1] = Bs[(kb + 4 + lc) * 136 + ncol];
            }
#pragma unroll
            for (int mt = 0; mt < 4; mt++)
#pragma unroll
                for (int nt = 0; nt < 4; nt++)
                    mma_tf32(acc[mt][nt], afr[mt], bfr[nt]);
        }
        __syncthreads();
    }

#pragma unroll
    for (int mt = 0; mt < 4; mt++) {
        int r0 = row0 + wm * 64 + mt * 16 + lr;
        int r1 = r0 + 8;
#pragma unroll
        for (int nt = 0; nt < 4; nt++) {
            int c = col0 + wn * 32 + nt * 8 + 2 * lc;
            float b0 = bias[c], b1 = bias[c + 1];
            float2 o0 = { (acc[mt][nt][0] + b0) * scale,
                          (acc[mt][nt][1] + b1) * scale };
            float2 o1 = { (acc[mt][nt][2] + b0) * scale,
                          (acc[mt][nt][3] + b1) * scale };
            *(float2*)&C[(size_t)r0 * N + c] = o0;
            *(float2*)&C[(size_t)r1 * N + c] = o1;
        }
    }
}

// ---------------- rotary (applied in place to q and k) ---------------------
__global__ void rotary_kernel(float* __restrict__ q, float* __restrict__ k)
{
    int idx = blockIdx.x * blockDim.x + threadIdx.x;
    if (idx >= MM * (DD / 2)) return;
    int m  = idx >> 9;
    int pp = idx & 511;
    int d  = pp * 2;
    int s  = m & (SS - 1);
    int p  = pp & 31;
    double ang = pow(10000.0, -(double)p / 31.0);
    double th  = (double)s * ang;
    double sd, cd;
    sincos(th, &sd, &cd);
    float c = (float)cd, sn = (float)sd;
    size_t off = (size_t)m * DD + d;
    float q0 = q[off], q1 = q[off + 1];
    q[off]     = q0 * c - q1 * sn;
    q[off + 1] = q1 * c + q0 * sn;
    float k0 = k[off], k1 = k[off + 1];
    k[off]     = k0 * c - k1 * sn;
    k[off + 1] = k1 * c + k0 * sn;
}

// ---------------- retention core (tf32 MMA, compensated) -------------------
#define RET2_SMEM_FLOATS (64*68 + 64*68 + 64*136 + 64*68)
#define RET2_SMEM_BYTES  (RET2_SMEM_FLOATS * 4)   // 87040

__global__ __launch_bounds__(256, 2) void retention_mma(
    const float* __restrict__ q, const float* __restrict__ k,
    const float* __restrict__ v, const float* __restrict__ g,
    float* __restrict__ outp)
{
    extern __shared__ float sm[];
    float (*qs)[68]  = (float(*)[68])(sm);
    float (*ks)[68]  = (float(*)[68])(sm + 64 * 68);
    float (*vs)[136] = (float(*)[136])(sm + 2 * 64 * 68);
    float (*sc)[68]  = (float(*)[68])(sm + 2 * 64 * 68 + 64 * 136);

    __shared__ float erow[64];
    __shared__ float etab[64];
    __shared__ float denom_s[64];
    __shared__ float psum[64][2], psq[64][2];

    const int sblk = blockIdx.x;
    const int h    = blockIdx.y;
    const int b    = blockIdx.z;
    const int tid  = threadIdx.x;
    const int warp = tid >> 5, lane = tid & 31;
    const int wm = warp & 3, wn = warp >> 2;
    const int lr = lane >> 2, lc = lane & 3;
    const int s0 = sblk * 64;

    const float decay = log1pf(-exp2f(-5.0f - (float)h));

    {
        const size_t qbase = ((size_t)b * SS + s0) * DD + h * KD;
#pragma unroll
        for (int l = 0; l < 4; l++) {
            int i  = tid + 256 * l;
            int r  = i >> 4;
            int c4 = (i & 15) * 4;
            *(float4*)&qs[r][c4] =
                *(const float4*)&q[qbase + (size_t)r * DD + c4];
        }
    }
    if (tid < 64) {
        int gs = s0 + tid;
        float rowsum = expm1f(decay * (float)(gs + 1)) / expm1f(decay);
        erow[tid] = expf(decay * (float)tid) * rsqrtf(rowsum);
        etab[tid] = expf(-decay * (float)tid);
    }

    float oacc[8][4];
#pragma unroll
    for (int nt = 0; nt < 8; nt++)
#pragma unroll
        for (int r = 0; r < 4; r++) oacc[nt][r] = 0.f;
    float rowacc = 0.f;

    __syncthreads();

    const int r0l = wm * 16 + lr;

    for (int tb = 0; tb <= sblk; tb++) {
        const int t0 = tb * 64;
        {
            const size_t kbase = ((size_t)b * SS + t0) * DD + h * KD;
#pragma unroll
            for (int l = 0; l < 4; l++) {
                int i  = tid + 256 * l;
                int r  = i >> 4;
                int c4 = (i & 15) * 4;
                *(float4*)&ks[r][c4] =
                    *(const float4*)&k[kbase + (size_t)r * DD + c4];
            }
            const size_t vbase = ((size_t)b * SS + t0) * (2 * DD) + h * HD;
#pragma unroll
            for (int l = 0; l < 8; l++) {
                int i  = tid + 256 * l;
                int r  = i >> 5;
                int c4 = (i & 31) * 4;
                *(float4*)&vs[r][c4] =
                    *(const float4*)&v[vbase + (size_t)r * (2 * DD) + c4];
            }
        }
        __syncthreads();

        // ---- QK^T (tf32x3 compensated) ----
        float qk[4][4];
#pragma unroll
        for (int nt = 0; nt < 4; nt++)
#pragma unroll
            for (int r = 0; r < 4; r++) qk[nt][r] = 0.f;

#pragma unroll
        for (int kk = 0; kk < 8; kk++) {
            const int kb = kk * 8;
            uint32_t ahi[4], alo[4];
#pragma unroll
            for (int e = 0; e < 4; e++) {
                float a = qs[r0l + (e & 1) * 8][kb + lc + (e >> 1) * 4];
                uint32_t hh = f2tf32(a);
                ahi[e] = hh;
                alo[e] = f2tf32(a - __uint_as_float(hh));
            }
#pragma unroll
            for (int nt = 0; nt < 4; nt++) {
                int ncol = wn * 32 + nt * 8 + lr;
                float b0f = ks[ncol][kb + lc];
                float b1f = ks[ncol][kb + 4 + lc];
                uint32_t bh[2] = { f2tf32(b0f), f2tf32(b1f) };
                uint32_t bl[2] = { f2tf32(b0f - __uint_as_float(bh[0])),
                                   f2tf32(b1f - __uint_as_float(bh[1])) };
                mma_tf32(qk[nt], ahi, bh);
                mma_tf32(qk[nt], alo, bh);
                mma_tf32(qk[nt], ahi, bl);
            }
        }

        // ---- mask + write scores to smem ----
        {
            const float E0  = expf(decay * (float)(s0 - t0));
            const float ai0 = E0 * erow[r0l];
            const float ai1 = E0 * erow[r0l + 8];
            const int gs0r = s0 + r0l, gs1r = gs0r + 8;
#pragma unroll
            for (int nt = 0; nt < 4; nt++) {
                int c  = wn * 32 + nt * 8 + 2 * lc;
                int gt0 = t0 + c, gt1 = gt0 + 1;
                float e0 = etab[c], e1 = etab[c + 1];
                float2 w0, w1;
                w0.x = (gt0 <= gs0r) ? qk[nt][0] * (ai0 * e0) : 0.f;
                w0.y = (gt1 <= gs0r) ? qk[nt][1] * (ai0 * e1) : 0.f;
                w1.x = (gt0 <= gs1r) ? qk[nt][2] * (ai1 * e0) : 0.f;
                w1.y = (gt1 <= gs1r) ? qk[nt][3] * (ai1 * e1) : 0.f;
                *(float2*)&sc[r0l][c]     = w0;
                *(float2*)&sc[r0l + 8][c] = w1;
            }
        }
        __syncthreads();

        if (tid < 64) {
            float s = 0.f;
#pragma unroll 8
            for (int t = 0; t < 64; t++) s += sc[tid][t];
            rowacc += s;
        }

        // ---- score @ V (tf32x2: compensate weights) ----
#pragma unroll
        for (int kk = 0; kk < 8; kk++) {
            const int kb = kk * 8;
            uint32_t ahi[4], alo[4];
#pragma unroll
            for (int e = 0; e < 4; e++) {
                float a = sc[r0l + (e & 1) * 8][kb + lc + (e >> 1) * 4];
                uint32_t hh = f2tf32(a);
                ahi[e] = hh;
                alo[e] = f2tf32(a - __uint_as_float(hh));
            }
#pragma unroll
            for (int nt = 0; nt < 8; nt++) {
                int ncol = wn * 64 + nt * 8 + lr;
                uint32_t bb[2] = { f2tf32(vs[kb + lc    ][ncol]),
                                   f2tf32(vs[kb + 4 + lc][ncol]) };
                mma_tf32(oacc[nt], ahi, bb);
                mma_tf32(oacc[nt], alo, bb);
            }
        }
        __syncthreads();
    }

    if (tid < 64) denom_s[tid] = fmaxf(fabsf(rowacc), 1.0f);
    __syncthreads();

    const float inv0 = 1.0f / denom_s[r0l];
    const float inv1 = 1.0f / denom_s[r0l + 8];
    float sa0 = 0.f, sq0 = 0.f, sa1 = 0.f, sq1 = 0.f;
#pragma unroll
    for (int nt = 0; nt < 8; nt++) {
        oacc[nt][0] *= inv0; oacc[nt][1] *= inv0;
        oacc[nt][2] *= inv1; oacc[nt][3] *= inv1;
        sa0 += oacc[nt][0] + oacc[nt][1];
        sq0 += oacc[nt][0] * oacc[nt][0] + oacc[nt][1] * oacc[nt][1];
        sa1 += oacc[nt][2] + oacc[nt][3];
        sq1 += oacc[nt][2] * oacc[nt][2] + oacc[nt][3] * oacc[nt][3];
    }
#pragma unroll
    for (int m_ = 1; m_ <= 2; m_ <<= 1) {
        sa0 += __shfl_xor_sync(0xffffffff, sa0, m_);
        sq0 += __shfl_xor_sync(0xffffffff, sq0, m_);
        sa1 += __shfl_xor_sync(0xffffffff, sa1, m_);
        sq1 += __shfl_xor_sync(0xffffffff, sq1, m_);
    }
    if (lc == 0) {
        psum[r0l][wn] = sa0; psq[r0l][wn] = sq0;
        psum[r0l + 8][wn] = sa1; psq[r0l + 8][wn] = sq1;
    }
    __syncthreads();

    float mu0, is0, mu1, is1;
    {
        float S = psum[r0l][0] + psum[r0l][1];
        float Q = psq[r0l][0] + psq[r0l][1];
        mu0 = S * (1.0f / 128.0f);
        is0 = rsqrtf(Q * (1.0f / 128.0f) - mu0 * mu0 + 1e-5f);
        S = psum[r0l + 8][0] + psum[r0l + 8][1];
        Q = psq[r0l + 8][0] + psq[r0l + 8][1];
        mu1 = S * (1.0f / 128.0f);
        is1 = rsqrtf(Q * (1.0f / 128.0f) - mu1 * mu1 + 1e-5f);
    }

    // outputs pre-rounded to tf32 bits (identical to the rounding the
    // downstream GEMM staging would apply) so out-GEMM can cp.async them raw
    const size_t obase = ((size_t)b * SS + s0) * (2 * DD) + h * HD;
#pragma unroll
    for (int nt = 0; nt < 8; nt++) {
        int c = wn * 64 + nt * 8 + 2 * lc;
        size_t go0 = obase + (size_t)r0l * (2 * DD) + c;
        size_t go1 = go0 + 8 * (2 * DD);
        float2 g0 = *(const float2*)&g[go0];
        float2 g1 = *(const float2*)&g[go1];
        float2 o0, o1;
        float n;
        n = (oacc[nt][0] - mu0) * is0;
        o0.x = __uint_as_float(f2tf32(n * (g0.x / (1.0f + expf(-g0.x)))));
        n = (oacc[nt][1] - mu0) * is0;
        o0.y = __uint_as_float(f2tf32(n * (g0.y / (1.0f + expf(-g0.y)))));
        n = (oacc[nt][2] - mu1) * is1;
        o1.x = __uint_as_float(f2tf32(n * (g1.x / (1.0f + expf(-g1.x)))));
        n = (oacc[nt][3] - mu1) * is1;
        o1.y = __uint_as_float(f2tf32(n * (g1.y / (1.0f + expf(-g1.y)))));
        *(float2*)&outp[go0] = o0;
        *(float2*)&outp[go1] = o1;
    }
}

// ---------------- launch ---------------------------------------------------
extern "C" void kernel_launch(void* const* d_in, const int* in_sizes, int n_in,
                              void* d_out, int out_size)
{
    (void)in_sizes; (void)n_in; (void)out_size;
    const float* x  = (const float*)d_in[0];
    const float* Wq = (const float*)d_in[1];
    const float* bq = (const float*)d_in[2];
    const float* Wk = (const float*)d_in[3];
    const float* bk = (const float*)d_in[4];
    const float* Wv = (const float*)d_in[5];
    const float* bv = (const float*)d_in[6];
    const float* Wg = (const float*)d_in[7];
    const float* bg = (const float*)d_in[8];
    const float* Wo = (const float*)d_in[9];
    const float* bo = (const float*)d_in[10];
    float* out = (float*)d_out;

    float *q, *k, *v, *g, *pre;
    float *xt, *wqt, *wkt, *wvt, *wgt, *wot;
    cudaGetSymbolAddress((void**)&q,   g_q);
    cudaGetSymbolAddress((void**)&k,   g_k);
    cudaGetSymbolAddress((void**)&v,   g_v);
    cudaGetSymbolAddress((void**)&g,   g_g);
    cudaGetSymbolAddress((void**)&pre, g_pre);
    cudaGetSymbolAddress((void**)&xt,  g_xt);
    cudaGetSymbolAddress((void**)&wqt, g_wqt);
    cudaGetSymbolAddress((void**)&wkt, g_wkt);
    cudaGetSymbolAddress((void**)&wvt, g_wvt);
    cudaGetSymbolAddress((void**)&wgt, g_wgt);
    cudaGetSymbolAddress((void**)&wot, g_wot);

    cudaFuncSetAttribute(retention_mma,
                         cudaFuncAttributeMaxDynamicSharedMemorySize,
                         RET2_SMEM_BYTES);
    cudaFuncSetAttribute(gemm_tf32_pipe,
                         cudaFuncAttributeMaxDynamicSharedMemorySize,
                         GEMM_SMEM_BYTES);

    const float kscale = 0.125f;   // 64^-0.5
    dim3 thr(256);

    // pre-round operands to tf32 bits
    round_tf32<<<(MM * DD / 4 + 255) / 256, 256>>>(x,  xt,  MM * DD / 4);
    round_tf32<<<(DD * DD / 4 + 255) / 256, 256>>>(Wq, wqt, DD * DD / 4);
    round_tf32<<<(DD * DD / 4 + 255) / 256, 256>>>(Wk, wkt, DD * DD / 4);
    round_tf32<<<(DD * 2 * DD / 4 + 255) / 256, 256>>>(Wv, wvt, DD * 2 * DD / 4);
    round_tf32<<<(DD * 2 * DD / 4 + 255) / 256, 256>>>(Wg, wgt, DD * 2 * DD / 4);
    round_tf32<<<(2 * DD * DD / 4 + 255) / 256, 256>>>(Wo, wot, 2 * DD * DD / 4);

    gemm_tf32_pipe<<<dim3(DD / 128,     MM / 128), thr, GEMM_SMEM_BYTES>>>(
        xt, wqt, bq, q, MM, DD, DD, 1.0f);
    gemm_tf32_pipe<<<dim3(DD / 128,     MM / 128), thr, GEMM_SMEM_BYTES>>>(
        xt, wkt, bk, k, MM, DD, DD, kscale);
    gemm_tf32_pipe<<<dim3(2 * DD / 128, MM / 128), thr, GEMM_SMEM_BYTES>>>(
        xt, wvt, bv, v, MM, 2 * DD, DD, 1.0f);
    gemm_tf32_pipe<<<dim3(2 * DD / 128, MM / 128), thr, GEMM_SMEM_BYTES>>>(
        xt, wgt, bg, g, MM, 2 * DD, DD, 1.0f);

    rotary_kernel<<<(MM * (DD / 2) + 255) / 256, 256>>>(q, k);

    retention_mma<<<dim3(SS / 64, HH, BB), 256, RET2_SMEM_BYTES>>>(q, k, v, g, pre);

    gemm_tf32_pipe<<<dim3(DD / 128, MM / 128), thr, GEMM_SMEM_BYTES>>>(
        pre, wot, bo, out, MM, DD, 2 * DD, 1.0f);
}

// round 7
// speedup vs baseline: 4.0225x; 1.5434x over previous
#include <cuda_runtime.h>
#include <math.h>
#include <stdint.h>

#define BB 2
#define SS 2048
#define DD 1024
#define HH 16
#define MM (BB*SS)          // 4096 rows
#define KD 64               // key dim per head
#define HD 128              // head dim per head
#define NC 32               // chunks per sequence (chunk = 64)
#define CH 64               // chunk length

// ---------------- scratch (device globals; no allocation allowed) ----------
__device__ float g_q[(size_t)MM * DD];
__device__ float g_k[(size_t)MM * DD];
__device__ float g_v[(size_t)MM * 2 * DD];
__device__ float g_g[(size_t)MM * 2 * DD];
__device__ float g_pre[(size_t)MM * 2 * DD];
// tf32-pre-rounded operands
__device__ float g_xt[(size_t)MM * DD];
__device__ float g_wqt[(size_t)DD * DD];
__device__ float g_wkt[(size_t)DD * DD];
__device__ float g_wvt[(size_t)DD * 2 * DD];
__device__ float g_wgt[(size_t)DD * 2 * DD];
__device__ float g_wot[(size_t)2 * DD * DD];
// chunked-retention states: [b*HH+h][c][KD][HD] and k-sum [.][c][KD]
__device__ float g_stA[(size_t)BB * HH * NC * KD * HD];
__device__ float g_stP[(size_t)BB * HH * NC * KD * HD];
__device__ float g_ksA[(size_t)BB * HH * NC * KD];
__device__ float g_ksP[(size_t)BB * HH * NC * KD];

// ---------------- tf32 helpers ---------------------------------------------
__device__ __forceinline__ uint32_t f2tf32(float x) {
    uint32_t r;
    asm("cvt.rna.tf32.f32 %0, %1;" : "=r"(r) : "f"(x));
    return r;
}

__device__ __forceinline__ void mma_tf32(float c[4], const uint32_t a[4],
                                         const uint32_t b[2]) {
    asm volatile(
        "mma.sync.aligned.m16n8k8.row.col.f32.tf32.tf32.f32 "
        "{%0,%1,%2,%3}, {%4,%5,%6,%7}, {%8,%9}, {%0,%1,%2,%3};"
        : "+f"(c[0]), "+f"(c[1]), "+f"(c[2]), "+f"(c[3])
        : "r"(a[0]), "r"(a[1]), "r"(a[2]), "r"(a[3]),
          "r"(b[0]), "r"(b[1]));
}

__device__ __forceinline__ void cp_async16(void* smem_ptr, const void* gptr) {
    uint32_t saddr = (uint32_t)__cvta_generic_to_shared(smem_ptr);
    asm volatile("cp.async.cg.shared.global [%0], [%1], 16;\n"
                 :: "r"(saddr), "l"(gptr));
}
__device__ __forceinline__ void cp_commit() {
    asm volatile("cp.async.commit_group;\n");
}
__device__ __forceinline__ void cp_wait1() {
    asm volatile("cp.async.wait_group 1;\n");
}
__device__ __forceinline__ void cp_wait0() {
    asm volatile("cp.async.wait_group 0;\n");
}

// ---------------- pre-round fp32 -> tf32 bits (rna) ------------------------
__global__ void round_tf32(const float* __restrict__ in,
                           float* __restrict__ out, int n4)
{
    int i = blockIdx.x * blockDim.x + threadIdx.x;
    if (i >= n4) return;
    float4 v = *(const float4*)&in[(size_t)i * 4];
    uint4 u;
    u.x = f2tf32(v.x); u.y = f2tf32(v.y);
    u.z = f2tf32(v.z); u.w = f2tf32(v.w);
    *(uint4*)&out[(size_t)i * 4] = u;
}

// ---------------- cp.async double-buffered tf32 GEMM -----------------------
#define GSTG (128*36 + 32*136)               // words per stage: 8960
#define GEMM_SMEM_BYTES (2 * GSTG * 4)       // 71680

__global__ __launch_bounds__(256, 2) void gemm_tf32_pipe(
    const float* __restrict__ A, const float* __restrict__ B,
    const float* __restrict__ bias, float* __restrict__ C,
    int M, int N, int K, float scale)
{
    extern __shared__ uint32_t dsm[];

    const int tid  = threadIdx.x;
    const int warp = tid >> 5, lane = tid & 31;
    const int wm = warp & 1, wn = warp >> 1;
    const int row0 = blockIdx.y * 128;
    const int col0 = blockIdx.x * 128;
    const int lr = lane >> 2;
    const int lc = lane & 3;

    float acc[4][4][4];
#pragma unroll
    for (int mt = 0; mt < 4; mt++)
#pragma unroll
        for (int nt = 0; nt < 4; nt++)
#pragma unroll
            for (int r = 0; r < 4; r++) acc[mt][nt][r] = 0.f;

    auto load_stage = [&](int s, int k0) {
        uint32_t* As = dsm + s * GSTG;
        uint32_t* Bs = dsm + s * GSTG + 128 * 36;
#pragma unroll
        for (int l = 0; l < 4; l++) {
            int f  = tid + 256 * l;
            int r  = f >> 3;
            int c4 = (f & 7) * 4;
            cp_async16(&As[r * 36 + c4],
                       &A[(size_t)(row0 + r) * K + k0 + c4]);
        }
#pragma unroll
        for (int l = 0; l < 4; l++) {
            int f  = tid + 256 * l;
            int r  = f >> 5;
            int c4 = (f & 31) * 4;
            cp_async16(&Bs[r * 136 + c4],
                       &B[(size_t)(k0 + r) * N + col0 + c4]);
        }
        cp_commit();
    };

    load_stage(0, 0);

    int s = 0;
    for (int k0 = 0; k0 < K; k0 += 32, s ^= 1) {
        const bool has_next = (k0 + 32) < K;
        if (has_next) load_stage(s ^ 1, k0 + 32);
        if (has_next) cp_wait1(); else cp_wait0();
        __syncthreads();

        const uint32_t* As = dsm + s * GSTG;
        const uint32_t* Bs = dsm + s * GSTG + 128 * 36;

#pragma unroll
        for (int ks = 0; ks < 4; ks++) {
            const int kb = ks * 8;
            uint32_t afr[4][4];
#pragma unroll
            for (int mt = 0; mt < 4; mt++) {
                int mrow = wm * 64 + mt * 16 + lr;
                afr[mt][0] = As[(mrow    ) * 36 + kb + lc];
                afr[mt][1] = As[(mrow + 8) * 36 + kb + lc];
                afr[mt][2] = As[(mrow    ) * 36 + kb + 4 + lc];
                afr[mt][3] = As[(mrow + 8) * 36 + kb + 4 + lc];
            }
            uint32_t bfr[4][2];
#pragma unroll
            for (int nt = 0; nt < 4; nt++) {
                int ncol = wn * 32 + nt * 8 + lr;
                bfr[nt][0] = Bs[(kb + lc    ) * 136 + ncol];
                bfr[nt][1] = Bs[(kb + 4 + lc) * 136 + ncol];
            }
#pragma unroll
            for (int mt = 0; mt < 4; mt++)
#pragma unroll
                for (int nt = 0; nt < 4; nt++)
                    mma_tf32(acc[mt][nt], afr[mt], bfr[nt]);
        }
        __syncthreads();
    }

#pragma unroll
    for (int mt = 0; mt < 4; mt++) {
        int r0 = row0 + wm * 64 + mt * 16 + lr;
        int r1 = r0 + 8;
#pragma unroll
        for (int nt = 0; nt < 4; nt++) {
            int c = col0 + wn * 32 + nt * 8 + 2 * lc;
            float b0 = bias[c], b1 = bias[c + 1];
            float2 o0 = { (acc[mt][nt][0] + b0) * scale,
                          (acc[mt][nt][1] + b1) * scale };
            float2 o1 = { (acc[mt][nt][2] + b0) * scale,
                          (acc[mt][nt][3] + b1) * scale };
            *(float2*)&C[(size_t)r0 * N + c] = o0;
            *(float2*)&C[(size_t)r1 * N + c] = o1;
        }
    }
}

// ---------------- rotary (applied in place to q and k) ---------------------
__global__ void rotary_kernel(float* __restrict__ q, float* __restrict__ k)
{
    int idx = blockIdx.x * blockDim.x + threadIdx.x;
    if (idx >= MM * (DD / 2)) return;
    int m  = idx >> 9;
    int pp = idx & 511;
    int d  = pp * 2;
    int s  = m & (SS - 1);
    int p  = pp & 31;
    double ang = pow(10000.0, -(double)p / 31.0);
    double th  = (double)s * ang;
    double sd, cd;
    sincos(th, &sd, &cd);
    float c = (float)cd, sn = (float)sd;
    size_t off = (size_t)m * DD + d;
    float q0 = q[off], q1 = q[off + 1];
    q[off]     = q0 * c - q1 * sn;
    q[off + 1] = q1 * c + q0 * sn;
    float k0 = k[off], k1 = k[off + 1];
    k[off]     = k0 * c - k1 * sn;
    k[off + 1] = k1 * c + k0 * sn;
}

// ---------------- pass A: per-chunk state A_c = K^T diag(w) V --------------
// grid (NC, HH, BB), 256 threads (16x16). w[t] = exp(decay*(63-t)).
#define CSA_KW   0                    // 64 x 65
#define CSA_VS   (64*65)              // 64 x 132
#define CSA_FLOATS (64*65 + 64*132)   // 12608
#define CSA_BYTES (CSA_FLOATS * 4)    // 50432

__global__ __launch_bounds__(256, 2) void chunk_state(
    const float* __restrict__ k, const float* __restrict__ v,
    float* __restrict__ stA, float* __restrict__ ksA)
{
    extern __shared__ float sm[];
    float* kw  = sm + CSA_KW;    // [t][kd] stride 65, pre-weighted
    float* vsm = sm + CSA_VS;    // [t][hd] stride 132

    __shared__ float wsh[64];

    const int c = blockIdx.x, h = blockIdx.y, b = blockIdx.z;
    const int tid = threadIdx.x;
    const int tx = tid & 15, ty = tid >> 4;
    const float decay = log1pf(-exp2f(-5.0f - (float)h));

    if (tid < 64) wsh[tid] = expf(decay * (float)(63 - tid));
    __syncthreads();

    {
        const size_t kbase = ((size_t)b * SS + c * CH) * DD + h * KD;
#pragma unroll
        for (int l = 0; l < 4; l++) {
            int i  = tid + 256 * l;        // float4 units, 1024 total
            int r  = i >> 4;
            int c4 = (i & 15) * 4;
            float4 t4 = *(const float4*)&k[kbase + (size_t)r * DD + c4];
            float w = wsh[r];
            kw[r * 65 + c4 + 0] = t4.x * w;
            kw[r * 65 + c4 + 1] = t4.y * w;
            kw[r * 65 + c4 + 2] = t4.z * w;
            kw[r * 65 + c4 + 3] = t4.w * w;
        }
        const size_t vbase = ((size_t)b * SS + c * CH) * (2 * DD) + h * HD;
#pragma unroll
        for (int l = 0; l < 8; l++) {
            int i  = tid + 256 * l;
            int r  = i >> 5;
            int c4 = (i & 31) * 4;
            *(float4*)&vsm[r * 132 + c4] =
                *(const float4*)&v[vbase + (size_t)r * (2 * DD) + c4];
        }
    }
    __syncthreads();

    // acc[kd 4][hd 8]: kd = ty*4+i, hd = tx*8+j
    float acc[4][8];
#pragma unroll
    for (int i = 0; i < 4; i++)
#pragma unroll
        for (int j = 0; j < 8; j++) acc[i][j] = 0.f;

#pragma unroll 4
    for (int t = 0; t < 64; t++) {
        float a[4];
#pragma unroll
        for (int i = 0; i < 4; i++) a[i] = kw[t * 65 + ty * 4 + i];
        float4 v0 = *(float4*)&vsm[t * 132 + tx * 8];
        float4 v1 = *(float4*)&vsm[t * 132 + tx * 8 + 4];
#pragma unroll
        for (int i = 0; i < 4; i++) {
            acc[i][0] += a[i] * v0.x; acc[i][1] += a[i] * v0.y;
            acc[i][2] += a[i] * v0.z; acc[i][3] += a[i] * v0.w;
            acc[i][4] += a[i] * v1.x; acc[i][5] += a[i] * v1.y;
            acc[i][6] += a[i] * v1.z; acc[i][7] += a[i] * v1.w;
        }
    }

    const size_t abase = (((size_t)(b * HH + h)) * NC + c) * (KD * HD);
#pragma unroll
    for (int i = 0; i < 4; i++) {
        int kd = ty * 4 + i;
        float4 o0 = {acc[i][0], acc[i][1], acc[i][2], acc[i][3]};
        float4 o1 = {acc[i][4], acc[i][5], acc[i][6], acc[i][7]};
        *(float4*)&stA[abase + (size_t)kd * HD + tx * 8]     = o0;
        *(float4*)&stA[abase + (size_t)kd * HD + tx * 8 + 4] = o1;
    }
    if (tid < 64) {
        float s = 0.f;
#pragma unroll 8
        for (int t = 0; t < 64; t++) s += kw[t * 65 + tid];
        ksA[(((size_t)(b * HH + h)) * NC + c) * KD + tid] = s;
    }
}

// ---------------- pass B: exclusive prefix scan of chunk states ------------
// grid 32 blocks (one per b,h), 256 threads; 8192 floats/chunk as float4.
__global__ __launch_bounds__(256) void state_scan(
    const float* __restrict__ stA, float* __restrict__ stP,
    const float* __restrict__ ksA, float* __restrict__ ksP)
{
    const int bh  = blockIdx.x;        // b*HH + h
    const int h   = bh & (HH - 1);
    const int tid = threadIdx.x;
    const float decay = log1pf(-exp2f(-5.0f - (float)h));
    const float lam   = expf(decay * (float)CH);

    const size_t base4 = (size_t)bh * NC * (KD * HD) / 4;
    const float4* A4 = (const float4*)stA;
    float4* P4 = (float4*)stP;

    float4 prev[8];
#pragma unroll
    for (int e = 0; e < 8; e++) prev[e] = make_float4(0.f, 0.f, 0.f, 0.f);

    for (int c = 0; c < NC; c++) {
        const size_t cb = base4 + (size_t)c * (KD * HD / 4);
#pragma unroll
        for (int e = 0; e < 8; e++) {
            size_t idx = cb + e * 256 + tid;
            P4[idx] = prev[e];
            float4 a = A4[idx];
            prev[e].x = lam * prev[e].x + a.x;
            prev[e].y = lam * prev[e].y + a.y;
            prev[e].z = lam * prev[e].z + a.z;
            prev[e].w = lam * prev[e].w + a.w;
        }
    }
    if (tid < KD) {
        float pk = 0.f;
        const size_t kb = (size_t)bh * NC * KD + tid;
        for (int c = 0; c < NC; c++) {
            ksP[kb + (size_t)c * KD] = pk;
            pk = lam * pk + ksA[kb + (size_t)c * KD];
        }
    }
}

// ---------------- pass C: intra-chunk retention + cross + LN + SiLU --------
// grid (NC, HH, BB), 256 threads (16x16), full fp32 SIMT.
#define RF_QS 0                        // 64 x 65
#define RF_KS (64*65)                  // 64 x 65  (later reused for P staging)
#define RF_VS (2*64*65)                // 64 x 132
#define RF_SC (2*64*65 + 64*132)       // 64 x 65
#define RF_FLOATS (3*64*65 + 64*132)   // 20928
#define RF_BYTES (RF_FLOATS * 4)       // 83712
#define RF_P  RF_KS                    // P staged over ks (+vs headroom), stride 132

__global__ __launch_bounds__(256, 2) void retention_final(
    const float* __restrict__ q, const float* __restrict__ k,
    const float* __restrict__ v, const float* __restrict__ g,
    const float* __restrict__ stP, const float* __restrict__ ksP,
    float* __restrict__ outp)
{
    extern __shared__ float sm[];
    float* qs = sm + RF_QS;   // [s][d] stride 65
    float* ks = sm + RF_KS;   // [t][d] stride 65
    float* vs = sm + RF_VS;   // [t][hd] stride 132
    float* sc = sm + RF_SC;   // [s][t] stride 65

    __shared__ float erow[64];      // e^{decay*sl} * rsqrt(rowsum(gs))
    __shared__ float etab[64];      // e^{-decay*tl}
    __shared__ float pksh[64];
    __shared__ float denom_s[64];
    __shared__ float psum[64][16], psq[64][16];

    const int c = blockIdx.x, h = blockIdx.y, b = blockIdx.z;
    const int tid = threadIdx.x;
    const int tx = tid & 15, ty = tid >> 4;
    const int ty4 = ty * 4;
    const int s0 = c * CH;
    const float decay = log1pf(-exp2f(-5.0f - (float)h));
    const float ed = expf(decay);

    // stage q, k (64x64) and v (64x128) for this chunk
    {
        const size_t qbase = ((size_t)b * SS + s0) * DD + h * KD;
#pragma unroll
        for (int l = 0; l < 4; l++) {
            int i  = tid + 256 * l;
            int r  = i >> 4;
            int c4 = (i & 15) * 4;
            float4 t4 = *(const float4*)&q[qbase + (size_t)r * DD + c4];
            qs[r * 65 + c4 + 0] = t4.x; qs[r * 65 + c4 + 1] = t4.y;
            qs[r * 65 + c4 + 2] = t4.z; qs[r * 65 + c4 + 3] = t4.w;
            float4 k4 = *(const float4*)&k[qbase + (size_t)r * DD + c4];
            ks[r * 65 + c4 + 0] = k4.x; ks[r * 65 + c4 + 1] = k4.y;
            ks[r * 65 + c4 + 2] = k4.z; ks[r * 65 + c4 + 3] = k4.w;
        }
        const size_t vbase = ((size_t)b * SS + s0) * (2 * DD) + h * HD;
#pragma unroll
        for (int l = 0; l < 8; l++) {
            int i  = tid + 256 * l;
            int r  = i >> 5;
            int c4 = (i & 31) * 4;
            *(float4*)&vs[r * 132 + c4] =
                *(const float4*)&v[vbase + (size_t)r * (2 * DD) + c4];
        }
    }
    if (tid < 64) {
        int gs = s0 + tid;
        float rowsum = expm1f(decay * (float)(gs + 1)) / expm1f(decay);
        erow[tid] = expf(decay * (float)tid) * rsqrtf(rowsum);
        etab[tid] = expf(-decay * (float)tid);
        pksh[tid] = ksP[(((size_t)(b * HH + h)) * NC + c) * KD + tid];
    }
    __syncthreads();

    // ---- intra scores (causal within chunk) ----
    float dot[4][4];
#pragma unroll
    for (int i = 0; i < 4; i++)
#pragma unroll
        for (int j = 0; j < 4; j++) dot[i][j] = 0.f;
#pragma unroll 8
    for (int d = 0; d < 64; d++) {
        float qa[4], kb[4];
#pragma unroll
        for (int i = 0; i < 4; i++) qa[i] = qs[(ty4 + i) * 65 + d];
#pragma unroll
        for (int j = 0; j < 4; j++) kb[j] = ks[(tx * 4 + j) * 65 + d];
#pragma unroll
        for (int i = 0; i < 4; i++)
#pragma unroll
            for (int j = 0; j < 4; j++) dot[i][j] += qa[i] * kb[j];
    }
#pragma unroll
    for (int i = 0; i < 4; i++) {
        int sl = ty4 + i;
        float ai = erow[sl];
#pragma unroll
        for (int j = 0; j < 4; j++) {
            int tl = tx * 4 + j;
            float m = (tl <= sl) ? ai * etab[tl] : 0.f;
            sc[sl * 65 + tl] = dot[i][j] * m;
        }
    }
    __syncthreads();

    // ---- denominator: intra row-sum + cross (q . pk) ----
    float rowacc = 0.f;
    if (tid < 64) {
        float s = 0.f;
#pragma unroll 8
        for (int t = 0; t < 64; t++) s += sc[tid * 65 + t];
        float dk = 0.f;
#pragma unroll 8
        for (int d = 0; d < 64; d++) dk += qs[tid * 65 + d] * pksh[d];
        rowacc = s + erow[tid] * ed * dk;
        denom_s[tid] = fmaxf(fabsf(rowacc), 1.0f);
    }

    // ---- intra AV: acc += sc @ v ----
    float acc[4][8];
#pragma unroll
    for (int i = 0; i < 4; i++)
#pragma unroll
        for (int j = 0; j < 8; j++) acc[i][j] = 0.f;
#pragma unroll 4
    for (int t = 0; t < 64; t++) {
        float4 v0 = *(float4*)&vs[t * 132 + tx * 8];
        float4 v1 = *(float4*)&vs[t * 132 + tx * 8 + 4];
#pragma unroll
        for (int i = 0; i < 4; i++) {
            float a = sc[(ty4 + i) * 65 + t];
            acc[i][0] += a * v0.x; acc[i][1] += a * v0.y;
            acc[i][2] += a * v0.z; acc[i][3] += a * v0.w;
            acc[i][4] += a * v1.x; acc[i][5] += a * v1.y;
            acc[i][6] += a * v1.z; acc[i][7] += a * v1.w;
        }
    }
    __syncthreads();   // done with ks/vs — reuse region for P

    // ---- stage P (64 x 128, stride 132) ----
    {
        const size_t pbase = (((size_t)(b * HH + h)) * NC + c) * (KD * HD);
        float* p = sm + RF_P;
#pragma unroll
        for (int l = 0; l < 8; l++) {
            int f  = tid + 256 * l;       // float4 units, 2048 total
            int d  = f >> 5;
            int c4 = (f & 31) * 4;
            *(float4*)&p[d * 132 + c4] =
                *(const float4*)&stP[pbase + (size_t)d * HD + c4];
        }
    }
    __syncthreads();

    // ---- cross: acc += e^{decay(sl+1)} * iv * (q @ P) ----
    {
        const float* p = sm + RF_P;
        float acc2[4][8];
#pragma unroll
        for (int i = 0; i < 4; i++)
#pragma unroll
            for (int j = 0; j < 8; j++) acc2[i][j] = 0.f;
#pragma unroll 4
        for (int d = 0; d < 64; d++) {
            float qa[4];
#pragma unroll
            for (int i = 0; i < 4; i++) qa[i] = qs[(ty4 + i) * 65 + d];
            float4 p0 = *(const float4*)&p[d * 132 + tx * 8];
            float4 p1 = *(const float4*)&p[d * 132 + tx * 8 + 4];
#pragma unroll
            for (int i = 0; i < 4; i++) {
                acc2[i][0] += qa[i] * p0.x; acc2[i][1] += qa[i] * p0.y;
                acc2[i][2] += qa[i] * p0.z; acc2[i][3] += qa[i] * p0.w;
                acc2[i][4] += qa[i] * p1.x; acc2[i][5] += qa[i] * p1.y;
                acc2[i][6] += qa[i] * p1.z; acc2[i][7] += qa[i] * p1.w;
            }
        }
#pragma unroll
        for (int i = 0; i < 4; i++) {
            float cf = erow[ty4 + i] * ed;
#pragma unroll
            for (int j = 0; j < 8; j++) acc[i][j] += cf * acc2[i][j];
        }
    }
    __syncthreads();

    // ---- /denom, LN partials, SiLU gate ----
#pragma unroll
    for (int i = 0; i < 4; i++) {
        float inv = 1.0f / denom_s[ty4 + i];
        float s = 0.f, s2 = 0.f;
#pragma unroll
        for (int j = 0; j < 8; j++) {
            acc[i][j] *= inv;
            s  += acc[i][j];
            s2 += acc[i][j] * acc[i][j];
        }
        psum[ty4 + i][tx] = s;
        psq [ty4 + i][tx] = s2;
    }
    __syncthreads();

    const size_t obase = ((size_t)b * SS + s0) * (2 * DD) + h * HD;
#pragma unroll
    for (int i = 0; i < 4; i++) {
        int r = ty4 + i;
        float s = 0.f, s2 = 0.f;
#pragma unroll
        for (int pp = 0; pp < 16; pp++) { s += psum[r][pp]; s2 += psq[r][pp]; }
        float mu  = s * (1.0f / 128.0f);
        float var = s2 * (1.0f / 128.0f) - mu * mu;
        float inv = rsqrtf(var + 1e-5f);

        size_t go = obase + (size_t)r * (2 * DD) + tx * 8;
        float4 g0 = *(const float4*)&g[go];
        float4 g1 = *(const float4*)&g[go + 4];
        float gg[8] = {g0.x,g0.y,g0.z,g0.w,g1.x,g1.y,g1.z,g1.w};
        float o[8];
#pragma unroll
        for (int j = 0; j < 8; j++) {
            float nv = (acc[i][j] - mu) * inv;
            float gv = gg[j];
            // tf32-prerounded so the out-GEMM can cp.async raw
            o[j] = __uint_as_float(
                f2tf32(nv * (gv / (1.0f + expf(-gv)))));
        }
        float4 o0 = {o[0], o[1], o[2], o[3]};
        float4 o1 = {o[4], o[5], o[6], o[7]};
        *(float4*)&outp[go]     = o0;
        *(float4*)&outp[go + 4] = o1;
    }
}

// ---------------- launch ---------------------------------------------------
extern "C" void kernel_launch(void* const* d_in, const int* in_sizes, int n_in,
                              void* d_out, int out_size)
{
    (void)in_sizes; (void)n_in; (void)out_size;
    const float* x  = (const float*)d_in[0];
    const float* Wq = (const float*)d_in[1];
    const float* bq = (const float*)d_in[2];
    const float* Wk = (const float*)d_in[3];
    const float* bk = (const float*)d_in[4];
    const float* Wv = (const float*)d_in[5];
    const float* bv = (const float*)d_in[6];
    const float* Wg = (const float*)d_in[7];
    const float* bg = (const float*)d_in[8];
    const float* Wo = (const float*)d_in[9];
    const float* bo = (const float*)d_in[10];
    float* out = (float*)d_out;

    float *q, *k, *v, *g, *pre;
    float *xt, *wqt, *wkt, *wvt, *wgt, *wot;
    float *stA, *stP, *ksA, *ksP;
    cudaGetSymbolAddress((void**)&q,   g_q);
    cudaGetSymbolAddress((void**)&k,   g_k);
    cudaGetSymbolAddress((void**)&v,   g_v);
    cudaGetSymbolAddress((void**)&g,   g_g);
    cudaGetSymbolAddress((void**)&pre, g_pre);
    cudaGetSymbolAddress((void**)&xt,  g_xt);
    cudaGetSymbolAddress((void**)&wqt, g_wqt);
    cudaGetSymbolAddress((void**)&wkt, g_wkt);
    cudaGetSymbolAddress((void**)&wvt, g_wvt);
    cudaGetSymbolAddress((void**)&wgt, g_wgt);
    cudaGetSymbolAddress((void**)&wot, g_wot);
    cudaGetSymbolAddress((void**)&stA, g_stA);
    cudaGetSymbolAddress((void**)&stP, g_stP);
    cudaGetSymbolAddress((void**)&ksA, g_ksA);
    cudaGetSymbolAddress((void**)&ksP, g_ksP);

    cudaFuncSetAttribute(gemm_tf32_pipe,
                         cudaFuncAttributeMaxDynamicSharedMemorySize,
                         GEMM_SMEM_BYTES);
    cudaFuncSetAttribute(chunk_state,
                         cudaFuncAttributeMaxDynamicSharedMemorySize,
                         CSA_BYTES);
    cudaFuncSetAttribute(retention_final,
                         cudaFuncAttributeMaxDynamicSharedMemorySize,
                         RF_BYTES);

    const float kscale = 0.125f;   // 64^-0.5
    dim3 thr(256);

    // pre-round operands to tf32 bits
    round_tf32<<<(MM * DD / 4 + 255) / 256, 256>>>(x,  xt,  MM * DD / 4);
    round_tf32<<<(DD * DD / 4 + 255) / 256, 256>>>(Wq, wqt, DD * DD / 4);
    round_tf32<<<(DD * DD / 4 + 255) / 256, 256>>>(Wk, wkt, DD * DD / 4);
    round_tf32<<<(DD * 2 * DD / 4 + 255) / 256, 256>>>(Wv, wvt, DD * 2 * DD / 4);
    round_tf32<<<(DD * 2 * DD / 4 + 255) / 256, 256>>>(Wg, wgt, DD * 2 * DD / 4);
    round_tf32<<<(2 * DD * DD / 4 + 255) / 256, 256>>>(Wo, wot, 2 * DD * DD / 4);

    gemm_tf32_pipe<<<dim3(DD / 128,     MM / 128), thr, GEMM_SMEM_BYTES>>>(
        xt, wqt, bq, q, MM, DD, DD, 1.0f);
    gemm_tf32_pipe<<<dim3(DD / 128,     MM / 128), thr, GEMM_SMEM_BYTES>>>(
        xt, wkt, bk, k, MM, DD, DD, kscale);
    gemm_tf32_pipe<<<dim3(2 * DD / 128, MM / 128), thr, GEMM_SMEM_BYTES>>>(
        xt, wvt, bv, v, MM, 2 * DD, DD, 1.0f);
    gemm_tf32_pipe<<<dim3(2 * DD / 128, MM / 128), thr, GEMM_SMEM_BYTES>>>(
        xt, wgt, bg, g, MM, 2 * DD, DD, 1.0f);

    rotary_kernel<<<(MM * (DD / 2) + 255) / 256, 256>>>(q, k);

    chunk_state<<<dim3(NC, HH, BB), thr, CSA_BYTES>>>(k, v, stA, ksA);
    state_scan<<<BB * HH, thr>>>(stA, stP, ksA, ksP);
    retention_final<<<dim3(NC, HH, BB), thr, RF_BYTES>>>(
        q, k, v, g, stP, ksP, pre);

    gemm_tf32_pipe<<<dim3(DD / 128, MM / 128), thr, GEMM_SMEM_BYTES>>>(
        pre, wot, bo, out, MM, DD, 2 * DD, 1.0f);
}

// round 8
// speedup vs baseline: 4.3909x; 1.0916x over previous
#include <cuda_runtime.h>
#include <math.h>
#include <stdint.h>

#define BB 2
#define SS 2048
#define DD 1024
#define HH 16
#define MM (BB*SS)          // 4096 rows
#define KD 64               // key dim per head
#define HD 128              // head dim per head
#define NC 32               // chunks per sequence (chunk = 64)
#define CH 64               // chunk length
#define QKW 2048            // fused q|k row width
#define VGW 4096            // fused v|g row width

// ---------------- scratch (device globals; no allocation allowed) ----------
__device__ float g_qk[(size_t)MM * QKW];     // [m][ q(1024) | k(1024) ]
__device__ float g_vg[(size_t)MM * VGW];     // [m][ v(2048) | g(2048) ]
__device__ float g_pre[(size_t)MM * 2 * DD];
// tf32-pre-rounded operands
__device__ float g_xt[(size_t)MM * DD];
__device__ float g_wqkt[(size_t)DD * QKW];
__device__ float g_wvgt[(size_t)DD * VGW];
__device__ float g_wot[(size_t)2 * DD * DD];
__device__ float g_bqk[QKW];
__device__ float g_bvg[VGW];
__device__ float2 g_rot[SS * 32];
// chunked-retention states
__device__ float g_stA[(size_t)BB * HH * NC * KD * HD];
__device__ float g_stP[(size_t)BB * HH * NC * KD * HD];
__device__ float g_ksA[(size_t)BB * HH * NC * KD];
__device__ float g_ksP[(size_t)BB * HH * NC * KD];

// ---------------- tf32 helpers ---------------------------------------------
__device__ __forceinline__ uint32_t f2tf32(float x) {
    uint32_t r;
    asm("cvt.rna.tf32.f32 %0, %1;" : "=r"(r) : "f"(x));
    return r;
}

__device__ __forceinline__ void mma_tf32(float c[4], const uint32_t a[4],
                                         const uint32_t b[2]) {
    asm volatile(
        "mma.sync.aligned.m16n8k8.row.col.f32.tf32.tf32.f32 "
        "{%0,%1,%2,%3}, {%4,%5,%6,%7}, {%8,%9}, {%0,%1,%2,%3};"
        : "+f"(c[0]), "+f"(c[1]), "+f"(c[2]), "+f"(c[3])
        : "r"(a[0]), "r"(a[1]), "r"(a[2]), "r"(a[3]),
          "r"(b[0]), "r"(b[1]));
}

__device__ __forceinline__ void cp_async16(void* smem_ptr, const void* gptr) {
    uint32_t saddr = (uint32_t)__cvta_generic_to_shared(smem_ptr);
    asm volatile("cp.async.cg.shared.global [%0], [%1], 16;\n"
                 :: "r"(saddr), "l"(gptr));
}
__device__ __forceinline__ void cp_commit() {
    asm volatile("cp.async.commit_group;\n");
}
__device__ __forceinline__ void cp_wait1() {
    asm volatile("cp.async.wait_group 1;\n");
}
__device__ __forceinline__ void cp_wait0() {
    asm volatile("cp.async.wait_group 0;\n");
}

// ---------------- rounding / concat passes ---------------------------------
__global__ void round_tf32(const float* __restrict__ in,
                           float* __restrict__ out, int n4)
{
    int i = blockIdx.x * blockDim.x + threadIdx.x;
    if (i >= n4) return;
    float4 v = *(const float4*)&in[(size_t)i * 4];
    uint4 u;
    u.x = f2tf32(v.x); u.y = f2tf32(v.y);
    u.z = f2tf32(v.z); u.w = f2tf32(v.w);
    *(uint4*)&out[(size_t)i * 4] = u;
}

// round + scale + place into a wider concatenated matrix
__global__ void round_concat(const float* __restrict__ in,
                             float* __restrict__ out,
                             int rows, int cols, int ostride, int coff,
                             float scale)
{
    int i = blockIdx.x * blockDim.x + threadIdx.x;   // float4 units
    int n4 = rows * cols / 4;
    if (i >= n4) return;
    int c4pr = cols / 4;
    int r  = i / c4pr;
    int c4 = (i - r * c4pr) * 4;
    float4 v = *(const float4*)&in[(size_t)r * cols + c4];
    uint4 u;
    u.x = f2tf32(v.x * scale); u.y = f2tf32(v.y * scale);
    u.z = f2tf32(v.z * scale); u.w = f2tf32(v.w * scale);
    *(uint4*)&out[(size_t)r * ostride + coff + c4] = u;
}

__global__ void concat_bias(const float* __restrict__ b0,
                            const float* __restrict__ b1,
                            float* __restrict__ out, int n, float s1)
{
    int i = blockIdx.x * blockDim.x + threadIdx.x;
    if (i >= 2 * n) return;
    out[i] = (i < n) ? b0[i] : b1[i - n] * s1;
}

// ---------------- rotary table + apply -------------------------------------
__global__ void rot_table(float2* __restrict__ rot)
{
    int i = blockIdx.x * blockDim.x + threadIdx.x;
    if (i >= SS * 32) return;
    int s = i >> 5, p = i & 31;
    double ang = pow(10000.0, -(double)p / 31.0);
    double sd, cd;
    sincos((double)s * ang, &sd, &cd);
    rot[i] = make_float2((float)cd, (float)sd);
}

__global__ void rotary_apply(float* __restrict__ qk,
                             const float2* __restrict__ rot)
{
    int idx = blockIdx.x * blockDim.x + threadIdx.x;
    if (idx >= MM * (DD / 2)) return;
    int m  = idx >> 9;
    int pp = idx & 511;
    int s  = m & (SS - 1);
    int p  = pp & 31;
    float2 cs = rot[(s << 5) + p];
    float c = cs.x, sn = cs.y;
    size_t off = (size_t)m * QKW + 2 * pp;
    float q0 = qk[off], q1 = qk[off + 1];
    qk[off]     = q0 * c - q1 * sn;
    qk[off + 1] = q1 * c + q0 * sn;
    size_t ko = off + 1024;
    float k0 = qk[ko], k1 = qk[ko + 1];
    qk[ko]     = k0 * c - k1 * sn;
    qk[ko + 1] = k1 * c + k0 * sn;
}

// ---------------- cp.async 3-stage tf32 GEMM -------------------------------
#define GSTG (128*36 + 32*136)               // words per stage: 8960
#define GEMM_SMEM_BYTES (3 * GSTG * 4)       // 107520

__global__ __launch_bounds__(256, 2) void gemm_tf32_pipe(
    const float* __restrict__ A, const float* __restrict__ B,
    const float* __restrict__ bias, float* __restrict__ C,
    int M, int N, int K, float scale)
{
    extern __shared__ uint32_t dsm[];

    const int tid  = threadIdx.x;
    const int warp = tid >> 5, lane = tid & 31;
    const int wm = warp & 1, wn = warp >> 1;
    const int row0 = blockIdx.y * 128;
    const int col0 = blockIdx.x * 128;
    const int lr = lane >> 2;
    const int lc = lane & 3;

    float acc[4][4][4];
#pragma unroll
    for (int mt = 0; mt < 4; mt++)
#pragma unroll
        for (int nt = 0; nt < 4; nt++)
#pragma unroll
            for (int r = 0; r < 4; r++) acc[mt][nt][r] = 0.f;

    auto load_stage = [&](int s, int k0) {
        uint32_t* As = dsm + s * GSTG;
        uint32_t* Bs = dsm + s * GSTG + 128 * 36;
#pragma unroll
        for (int l = 0; l < 4; l++) {
            int f  = tid + 256 * l;
            int r  = f >> 3;
            int c4 = (f & 7) * 4;
            cp_async16(&As[r * 36 + c4],
                       &A[(size_t)(row0 + r) * K + k0 + c4]);
        }
#pragma unroll
        for (int l = 0; l < 4; l++) {
            int f  = tid + 256 * l;
            int r  = f >> 5;
            int c4 = (f & 31) * 4;
            cp_async16(&Bs[r * 136 + c4],
                       &B[(size_t)(k0 + r) * N + col0 + c4]);
        }
        cp_commit();
    };

    load_stage(0, 0);
    load_stage(1, 32);

    int s = 0;
    for (int k0 = 0; k0 < K; k0 += 32) {
        if (k0 + 32 < K) cp_wait1(); else cp_wait0();
        __syncthreads();

        const uint32_t* As = dsm + s * GSTG;
        const uint32_t* Bs = dsm + s * GSTG + 128 * 36;

#pragma unroll
        for (int ks = 0; ks < 4; ks++) {
            const int kb = ks * 8;
            uint32_t afr[4][4];
#pragma unroll
            for (int mt = 0; mt < 4; mt++) {
                int mrow = wm * 64 + mt * 16 + lr;
                afr[mt][0] = As[(mrow    ) * 36 + kb + lc];
                afr[mt][1] = As[(mrow + 8) * 36 + kb + lc];
                afr[mt][2] = As[(mrow    ) * 36 + kb + 4 + lc];
                afr[mt][3] = As[(mrow + 8) * 36 + kb + 4 + lc];
            }
            uint32_t bfr[4][2];
#pragma unroll
            for (int nt = 0; nt < 4; nt++) {
                int ncol = wn * 32 + nt * 8 + lr;
                bfr[nt][0] = Bs[(kb + lc    ) * 136 + ncol];
                bfr[nt][1] = Bs[(kb + 4 + lc) * 136 + ncol];
            }
#pragma unroll
            for (int mt = 0; mt < 4; mt++)
#pragma unroll
                for (int nt = 0; nt < 4; nt++)
                    mma_tf32(acc[mt][nt], afr[mt], bfr[nt]);
        }

        int kn = k0 + 64;
        if (kn < K) load_stage((s + 2) % 3, kn);
        s = (s + 1) % 3;
    }

#pragma unroll
    for (int mt = 0; mt < 4; mt++) {
        int r0 = row0 + wm * 64 + mt * 16 + lr;
        int r1 = r0 + 8;
#pragma unroll
        for (int nt = 0; nt < 4; nt++) {
            int c = col0 + wn * 32 + nt * 8 + 2 * lc;
            float b0 = bias[c], b1 = bias[c + 1];
            float2 o0 = { (acc[mt][nt][0] + b0) * scale,
                          (acc[mt][nt][1] + b1) * scale };
            float2 o1 = { (acc[mt][nt][2] + b0) * scale,
                          (acc[mt][nt][3] + b1) * scale };
            *(float2*)&C[(size_t)r0 * N + c] = o0;
            *(float2*)&C[(size_t)r1 * N + c] = o1;
        }
    }
}

// ---------------- pass A: per-chunk state A_c = K^T diag(w) V --------------
#define CSA_KW   0                    // 64 x 65
#define CSA_VS   (64*65)              // 64 x 132
#define CSA_FLOATS (64*65 + 64*132)   // 12608
#define CSA_BYTES (CSA_FLOATS * 4)    // 50432

__global__ __launch_bounds__(256, 2) void chunk_state(
    const float* __restrict__ qk, const float* __restrict__ vg,
    float* __restrict__ stA, float* __restrict__ ksA)
{
    extern __shared__ float sm[];
    float* kw  = sm + CSA_KW;    // [t][kd] stride 65, pre-weighted
    float* vsm = sm + CSA_VS;    // [t][hd] stride 132

    __shared__ float wsh[64];

    const int c = blockIdx.x, h = blockIdx.y, b = blockIdx.z;
    const int tid = threadIdx.x;
    const int tx = tid & 15, ty = tid >> 4;
    const float decay = log1pf(-exp2f(-5.0f - (float)h));

    if (tid < 64) wsh[tid] = expf(decay * (float)(63 - tid));
    __syncthreads();

    {
        const size_t kbase = ((size_t)b * SS + c * CH) * QKW + 1024 + h * KD;
#pragma unroll
        for (int l = 0; l < 4; l++) {
            int i  = tid + 256 * l;
            int r  = i >> 4;
            int c4 = (i & 15) * 4;
            float4 t4 = *(const float4*)&qk[kbase + (size_t)r * QKW + c4];
            float w = wsh[r];
            kw[r * 65 + c4 + 0] = t4.x * w;
            kw[r * 65 + c4 + 1] = t4.y * w;
            kw[r * 65 + c4 + 2] = t4.z * w;
            kw[r * 65 + c4 + 3] = t4.w * w;
        }
        const size_t vbase = ((size_t)b * SS + c * CH) * VGW + h * HD;
#pragma unroll
        for (int l = 0; l < 8; l++) {
            int i  = tid + 256 * l;
            int r  = i >> 5;
            int c4 = (i & 31) * 4;
            *(float4*)&vsm[r * 132 + c4] =
                *(const float4*)&vg[vbase + (size_t)r * VGW + c4];
        }
    }
    __syncthreads();

    float acc[4][8];
#pragma unroll
    for (int i = 0; i < 4; i++)
#pragma unroll
        for (int j = 0; j < 8; j++) acc[i][j] = 0.f;

#pragma unroll 4
    for (int t = 0; t < 64; t++) {
        float a[4];
#pragma unroll
        for (int i = 0; i < 4; i++) a[i] = kw[t * 65 + ty * 4 + i];
        float4 v0 = *(float4*)&vsm[t * 132 + tx * 8];
        float4 v1 = *(float4*)&vsm[t * 132 + tx * 8 + 4];
#pragma unroll
        for (int i = 0; i < 4; i++) {
            acc[i][0] += a[i] * v0.x; acc[i][1] += a[i] * v0.y;
            acc[i][2] += a[i] * v0.z; acc[i][3] += a[i] * v0.w;
            acc[i][4] += a[i] * v1.x; acc[i][5] += a[i] * v1.y;
            acc[i][6] += a[i] * v1.z; acc[i][7] += a[i] * v1.w;
        }
    }

    const size_t abase = (((size_t)(b * HH + h)) * NC + c) * (KD * HD);
#pragma unroll
    for (int i = 0; i < 4; i++) {
        int kd = ty * 4 + i;
        float4 o0 = {acc[i][0], acc[i][1], acc[i][2], acc[i][3]};
        float4 o1 = {acc[i][4], acc[i][5], acc[i][6], acc[i][7]};
        *(float4*)&stA[abase + (size_t)kd * HD + tx * 8]     = o0;
        *(float4*)&stA[abase + (size_t)kd * HD + tx * 8 + 4] = o1;
    }
    if (tid < 64) {
        float s = 0.f;
#pragma unroll 8
        for (int t = 0; t < 64; t++) s += kw[t * 65 + tid];
        ksA[(((size_t)(b * HH + h)) * NC + c) * KD + tid] = s;
    }
}

// ---------------- pass B: exclusive prefix scan of chunk states ------------
__global__ __launch_bounds__(256) void state_scan(
    const float* __restrict__ stA, float* __restrict__ stP,
    const float* __restrict__ ksA, float* __restrict__ ksP)
{
    const int bh  = blockIdx.x;
    const int h   = bh & (HH - 1);
    const int tid = threadIdx.x;
    const float decay = log1pf(-exp2f(-5.0f - (float)h));
    const float lam   = expf(decay * (float)CH);

    const size_t base4 = (size_t)bh * NC * (KD * HD) / 4;
    const float4* A4 = (const float4*)stA;
    float4* P4 = (float4*)stP;

    float4 prev[8];
#pragma unroll
    for (int e = 0; e < 8; e++) prev[e] = make_float4(0.f, 0.f, 0.f, 0.f);

    for (int c = 0; c < NC; c++) {
        const size_t cb = base4 + (size_t)c * (KD * HD / 4);
#pragma unroll
        for (int e = 0; e < 8; e++) {
            size_t idx = cb + e * 256 + tid;
            P4[idx] = prev[e];
            float4 a = A4[idx];
            prev[e].x = lam * prev[e].x + a.x;
            prev[e].y = lam * prev[e].y + a.y;
            prev[e].z = lam * prev[e].z + a.z;
            prev[e].w = lam * prev[e].w + a.w;
        }
    }
    if (tid < KD) {
        float pk = 0.f;
        const size_t kb = (size_t)bh * NC * KD + tid;
        for (int c = 0; c < NC; c++) {
            ksP[kb + (size_t)c * KD] = pk;
            pk = lam * pk + ksA[kb + (size_t)c * KD];
        }
    }
}

// ---------------- pass C: intra-chunk retention + cross + LN + SiLU --------
#define RF_QS 0                        // 64 x 65
#define RF_KS (64*65)                  // 64 x 65 (reused for P staging)
#define RF_VS (2*64*65)                // 64 x 132
#define RF_SC (2*64*65 + 64*132)       // 64 x 65
#define RF_FLOATS (3*64*65 + 64*132)   // 20928
#define RF_BYTES (RF_FLOATS * 4)       // 83712
#define RF_P  RF_KS

__global__ __launch_bounds__(256, 2) void retention_final(
    const float* __restrict__ qk, const float* __restrict__ vg,
    const float* __restrict__ stP, const float* __restrict__ ksP,
    float* __restrict__ outp)
{
    extern __shared__ float sm[];
    float* qs = sm + RF_QS;
    float* ks = sm + RF_KS;
    float* vs = sm + RF_VS;
    float* sc = sm + RF_SC;

    __shared__ float erow[64];
    __shared__ float etab[64];
    __shared__ float pksh[64];
    __shared__ float denom_s[64];
    __shared__ float psum[64][16], psq[64][16];

    const int c = blockIdx.x, h = blockIdx.y, b = blockIdx.z;
    const int tid = threadIdx.x;
    const int tx = tid & 15, ty = tid >> 4;
    const int ty4 = ty * 4;
    const int s0 = c * CH;
    const float decay = log1pf(-exp2f(-5.0f - (float)h));
    const float ed = expf(decay);

    {
        const size_t qbase = ((size_t)b * SS + s0) * QKW + h * KD;
#pragma unroll
        for (int l = 0; l < 4; l++) {
            int i  = tid + 256 * l;
            int r  = i >> 4;
            int c4 = (i & 15) * 4;
            float4 t4 = *(const float4*)&qk[qbase + (size_t)r * QKW + c4];
            qs[r * 65 + c4 + 0] = t4.x; qs[r * 65 + c4 + 1] = t4.y;
            qs[r * 65 + c4 + 2] = t4.z; qs[r * 65 + c4 + 3] = t4.w;
            float4 k4 = *(const float4*)&qk[qbase + 1024 + (size_t)r * QKW + c4];
            ks[r * 65 + c4 + 0] = k4.x; ks[r * 65 + c4 + 1] = k4.y;
            ks[r * 65 + c4 + 2] = k4.z; ks[r * 65 + c4 + 3] = k4.w;
        }
        const size_t vbase = ((size_t)b * SS + s0) * VGW + h * HD;
#pragma unroll
        for (int l = 0; l < 8; l++) {
            int i  = tid + 256 * l;
            int r  = i >> 5;
            int c4 = (i & 31) * 4;
            *(float4*)&vs[r * 132 + c4] =
                *(const float4*)&vg[vbase + (size_t)r * VGW + c4];
        }
    }
    if (tid < 64) {
        int gs = s0 + tid;
        float rowsum = expm1f(decay * (float)(gs + 1)) / expm1f(decay);
        erow[tid] = expf(decay * (float)tid) * rsqrtf(rowsum);
        etab[tid] = expf(-decay * (float)tid);
        pksh[tid] = ksP[(((size_t)(b * HH + h)) * NC + c) * KD + tid];
    }
    __syncthreads();

    float dot[4][4];
#pragma unroll
    for (int i = 0; i < 4; i++)
#pragma unroll
        for (int j = 0; j < 4; j++) dot[i][j] = 0.f;
#pragma unroll 8
    for (int d = 0; d < 64; d++) {
        float qa[4], kb[4];
#pragma unroll
        for (int i = 0; i < 4; i++) qa[i] = qs[(ty4 + i) * 65 + d];
#pragma unroll
        for (int j = 0; j < 4; j++) kb[j] = ks[(tx * 4 + j) * 65 + d];
#pragma unroll
        for (int i = 0; i < 4; i++)
#pragma unroll
            for (int j = 0; j < 4; j++) dot[i][j] += qa[i] * kb[j];
    }
#pragma unroll
    for (int i = 0; i < 4; i++) {
        int sl = ty4 + i;
        float ai = erow[sl];
#pragma unroll
        for (int j = 0; j < 4; j++) {
            int tl = tx * 4 + j;
            float m = (tl <= sl) ? ai * etab[tl] : 0.f;
            sc[sl * 65 + tl] = dot[i][j] * m;
        }
    }
    __syncthreads();

    if (tid < 64) {
        float s = 0.f;
#pragma unroll 8
        for (int t = 0; t < 64; t++) s += sc[tid * 65 + t];
        float dk = 0.f;
#pragma unroll 8
        for (int d = 0; d < 64; d++) dk += qs[tid * 65 + d] * pksh[d];
        denom_s[tid] = fmaxf(fabsf(s + erow[tid] * ed * dk), 1.0f);
    }

    float acc[4][8];
#pragma unroll
    for (int i = 0; i < 4; i++)
#pragma unroll
        for (int j = 0; j < 8; j++) acc[i][j] = 0.f;
#pragma unroll 4
    for (int t = 0; t < 64; t++) {
        float4 v0 = *(float4*)&vs[t * 132 + tx * 8];
        float4 v1 = *(float4*)&vs[t * 132 + tx * 8 + 4];
#pragma unroll
        for (int i = 0; i < 4; i++) {
            float a = sc[(ty4 + i) * 65 + t];
            acc[i][0] += a * v0.x; acc[i][1] += a * v0.y;
            acc[i][2] += a * v0.z; acc[i][3] += a * v0.w;
            acc[i][4] += a * v1.x; acc[i][5] += a * v1.y;
            acc[i][6] += a * v1.z; acc[i][7] += a * v1.w;
        }
    }
    __syncthreads();

    {
        const size_t pbase = (((size_t)(b * HH + h)) * NC + c) * (KD * HD);
        float* p = sm + RF_P;
#pragma unroll
        for (int l = 0; l < 8; l++) {
            int f  = tid + 256 * l;
            int d  = f >> 5;
            int c4 = (f & 31) * 4;
            *(float4*)&p[d * 132 + c4] =
                *(const float4*)&stP[pbase + (size_t)d * HD + c4];
        }
    }
    __syncthreads();

    {
        const float* p = sm + RF_P;
        float acc2[4][8];
#pragma unroll
        for (int i = 0; i < 4; i++)
#pragma unroll
            for (int j = 0; j < 8; j++) acc2[i][j] = 0.f;
#pragma unroll 4
        for (int d = 0; d < 64; d++) {
            float qa[4];
#pragma unroll
            for (int i = 0; i < 4; i++) qa[i] = qs[(ty4 + i) * 65 + d];
            float4 p0 = *(const float4*)&p[d * 132 + tx * 8];
            float4 p1 = *(const float4*)&p[d * 132 + tx * 8 + 4];
#pragma unroll
            for (int i = 0; i < 4; i++) {
                acc2[i][0] += qa[i] * p0.x; acc2[i][1] += qa[i] * p0.y;
                acc2[i][2] += qa[i] * p0.z; acc2[i][3] += qa[i] * p0.w;
                acc2[i][4] += qa[i] * p1.x; acc2[i][5] += qa[i] * p1.y;
                acc2[i][6] += qa[i] * p1.z; acc2[i][7] += qa[i] * p1.w;
            }
        }
#pragma unroll
        for (int i = 0; i < 4; i++) {
            float cf = erow[ty4 + i] * ed;
#pragma unroll
            for (int j = 0; j < 8; j++) acc[i][j] += cf * acc2[i][j];
        }
    }
    __syncthreads();

#pragma unroll
    for (int i = 0; i < 4; i++) {
        float inv = 1.0f / denom_s[ty4 + i];
        float s = 0.f, s2 = 0.f;
#pragma unroll
        for (int j = 0; j < 8; j++) {
            acc[i][j] *= inv;
            s  += acc[i][j];
            s2 += acc[i][j] * acc[i][j];
        }
        psum[ty4 + i][tx] = s;
        psq [ty4 + i][tx] = s2;
    }
    __syncthreads();

    const size_t obase = ((size_t)b * SS + s0) * (2 * DD) + h * HD;
    const size_t gbase = ((size_t)b * SS + s0) * VGW + 2048 + h * HD;
#pragma unroll
    for (int i = 0; i < 4; i++) {
        int r = ty4 + i;
        float s = 0.f, s2 = 0.f;
#pragma unroll
        for (int pp = 0; pp < 16; pp++) { s += psum[r][pp]; s2 += psq[r][pp]; }
        float mu  = s * (1.0f / 128.0f);
        float var = s2 * (1.0f / 128.0f) - mu * mu;
        float inv = rsqrtf(var + 1e-5f);

        size_t go = gbase + (size_t)r * VGW + tx * 8;
        size_t oo = obase + (size_t)r * (2 * DD) + tx * 8;
        float4 g0 = *(const float4*)&vg[go];
        float4 g1 = *(const float4*)&vg[go + 4];
        float gg[8] = {g0.x,g0.y,g0.z,g0.w,g1.x,g1.y,g1.z,g1.w};
        float o[8];
#pragma unroll
        for (int j = 0; j < 8; j++) {
            float nv = (acc[i][j] - mu) * inv;
            float gv = gg[j];
            o[j] = __uint_as_float(
                f2tf32(nv * (gv / (1.0f + expf(-gv)))));
        }
        float4 o0 = {o[0], o[1], o[2], o[3]};
        float4 o1 = {o[4], o[5], o[6], o[7]};
        *(float4*)&outp[oo]     = o0;
        *(float4*)&outp[oo + 4] = o1;
    }
}

// ---------------- launch ---------------------------------------------------
extern "C" void kernel_launch(void* const* d_in, const int* in_sizes, int n_in,
                              void* d_out, int out_size)
{
    (void)in_sizes; (void)n_in; (void)out_size;
    const float* x  = (const float*)d_in[0];
    const float* Wq = (const float*)d_in[1];
    const float* bq = (const float*)d_in[2];
    const float* Wk = (const float*)d_in[3];
    const float* bk = (const float*)d_in[4];
    const float* Wv = (const float*)d_in[5];
    const float* bv = (const float*)d_in[6];
    const float* Wg = (const float*)d_in[7];
    const float* bg = (const float*)d_in[8];
    const float* Wo = (const float*)d_in[9];
    const float* bo = (const float*)d_in[10];
    float* out = (float*)d_out;

    float *qkb, *vgb, *pre, *xt, *wqkt, *wvgt, *wot, *bqk, *bvg;
    float *stA, *stP, *ksA, *ksP;
    float2* rot;
    cudaGetSymbolAddress((void**)&qkb,  g_qk);
    cudaGetSymbolAddress((void**)&vgb,  g_vg);
    cudaGetSymbolAddress((void**)&pre,  g_pre);
    cudaGetSymbolAddress((void**)&xt,   g_xt);
    cudaGetSymbolAddress((void**)&wqkt, g_wqkt);
    cudaGetSymbolAddress((void**)&wvgt, g_wvgt);
    cudaGetSymbolAddress((void**)&wot,  g_wot);
    cudaGetSymbolAddress((void**)&bqk,  g_bqk);
    cudaGetSymbolAddress((void**)&bvg,  g_bvg);
    cudaGetSymbolAddress((void**)&rot,  g_rot);
    cudaGetSymbolAddress((void**)&stA,  g_stA);
    cudaGetSymbolAddress((void**)&stP,  g_stP);
    cudaGetSymbolAddress((void**)&ksA,  g_ksA);
    cudaGetSymbolAddress((void**)&ksP,  g_ksP);

    cudaFuncSetAttribute(gemm_tf32_pipe,
                         cudaFuncAttributeMaxDynamicSharedMemorySize,
                         GEMM_SMEM_BYTES);
    cudaFuncSetAttribute(chunk_state,
                         cudaFuncAttributeMaxDynamicSharedMemorySize,
                         CSA_BYTES);
    cudaFuncSetAttribute(retention_final,
                         cudaFuncAttributeMaxDynamicSharedMemorySize,
                         RF_BYTES);

    const float kscale = 0.125f;   // 64^-0.5 (power of two -> exact fold)
    dim3 thr(256);

    // pre-round + concat operands
    round_tf32<<<(MM * DD / 4 + 255) / 256, 256>>>(x,  xt,  MM * DD / 4);
    round_concat<<<(DD * DD / 4 + 255) / 256, 256>>>(Wq, wqkt, DD, DD, QKW, 0,    1.0f);
    round_concat<<<(DD * DD / 4 + 255) / 256, 256>>>(Wk, wqkt, DD, DD, QKW, 1024, kscale);
    round_concat<<<(DD * 2 * DD / 4 + 255) / 256, 256>>>(Wv, wvgt, DD, 2 * DD, VGW, 0,    1.0f);
    round_concat<<<(DD * 2 * DD / 4 + 255) / 256, 256>>>(Wg, wvgt, DD, 2 * DD, VGW, 2048, 1.0f);
    round_tf32<<<(2 * DD * DD / 4 + 255) / 256, 256>>>(Wo, wot, 2 * DD * DD / 4);
    concat_bias<<<(QKW + 255) / 256, 256>>>(bq, bk, bqk, 1024, kscale);
    concat_bias<<<(VGW + 255) / 256, 256>>>(bv, bg, bvg, 2048, 1.0f);
    rot_table<<<(SS * 32 + 255) / 256, 256>>>(rot);

    // fused projections
    gemm_tf32_pipe<<<dim3(QKW / 128, MM / 128), thr, GEMM_SMEM_BYTES>>>(
        xt, wqkt, bqk, qkb, MM, QKW, DD, 1.0f);
    gemm_tf32_pipe<<<dim3(VGW / 128, MM / 128), thr, GEMM_SMEM_BYTES>>>(
        xt, wvgt, bvg, vgb, MM, VGW, DD, 1.0f);

    rotary_apply<<<(MM * (DD / 2) + 255) / 256, 256>>>(qkb, rot);

    chunk_state<<<dim3(NC, HH, BB), thr, CSA_BYTES>>>(qkb, vgb, stA, ksA);
    state_scan<<<BB * HH, thr>>>(stA, stP, ksA, ksP);
    retention_final<<<dim3(NC, HH, BB), thr, RF_BYTES>>>(
        qkb, vgb, stP, ksP, pre);

    gemm_tf32_pipe<<<dim3(DD / 128, MM / 128), thr, GEMM_SMEM_BYTES>>>(
        pre, wot, bo, out, MM, DD, 2 * DD, 1.0f);
}

// round 10
// speedup vs baseline: 4.5724x; 1.0413x over previous
#include <cuda_runtime.h>
#include <math.h>
#include <stdint.h>

#define BB 2
#define SS 2048
#define DD 1024
#define HH 16
#define MM (BB*SS)          // 4096 rows
#define KD 64               // key dim per head
#define HD 128              // head dim per head
#define NC 32               // chunks per sequence (chunk = 64)
#define CH 64               // chunk length
#define PW 6144             // fused projection width: q|k|v|g

// ---------------- scratch (device globals; no allocation allowed) ----------
__device__ float g_proj[(size_t)MM * PW];    // [m][ q 0 | k 1024 | v 2048 | g 4096 ]
__device__ float g_pre[(size_t)MM * 2 * DD];
__device__ float g_xt[(size_t)MM * DD];
__device__ float g_wall[(size_t)DD * PW];
__device__ float g_wot[(size_t)2 * DD * DD];
__device__ float g_ball[PW];
__device__ float2 g_rot[SS * 32];
__device__ float g_stA[(size_t)BB * HH * NC * KD * HD];
__device__ float g_stP[(size_t)BB * HH * NC * KD * HD];
__device__ float g_ksA[(size_t)BB * HH * NC * KD];
__device__ float g_ksP[(size_t)BB * HH * NC * KD];

// ---------------- tf32 helpers ---------------------------------------------
__device__ __forceinline__ uint32_t f2tf32(float x) {
    uint32_t r;
    asm("cvt.rna.tf32.f32 %0, %1;" : "=r"(r) : "f"(x));
    return r;
}

__device__ __forceinline__ void mma_tf32(float c[4], const uint32_t a[4],
                                         const uint32_t b[2]) {
    asm volatile(
        "mma.sync.aligned.m16n8k8.row.col.f32.tf32.tf32.f32 "
        "{%0,%1,%2,%3}, {%4,%5,%6,%7}, {%8,%9}, {%0,%1,%2,%3};"
        : "+f"(c[0]), "+f"(c[1]), "+f"(c[2]), "+f"(c[3])
        : "r"(a[0]), "r"(a[1]), "r"(a[2]), "r"(a[3]),
          "r"(b[0]), "r"(b[1]));
}

__device__ __forceinline__ void cp_async16(void* smem_ptr, const void* gptr) {
    uint32_t saddr = (uint32_t)__cvta_generic_to_shared(smem_ptr);
    asm volatile("cp.async.cg.shared.global [%0], [%1], 16;\n"
                 :: "r"(saddr), "l"(gptr));
}
__device__ __forceinline__ void cp_commit() {
    asm volatile("cp.async.commit_group;\n");
}
__device__ __forceinline__ void cp_wait1() {
    asm volatile("cp.async.wait_group 1;\n");
}
__device__ __forceinline__ void cp_wait0() {
    asm volatile("cp.async.wait_group 0;\n");
}

// ---------------- prep passes ----------------------------------------------
__global__ void round_tf32(const float* __restrict__ in,
                           float* __restrict__ out, int n4)
{
    int i = blockIdx.x * blockDim.x + threadIdx.x;
    if (i >= n4) return;
    float4 v = *(const float4*)&in[(size_t)i * 4];
    uint4 u;
    u.x = f2tf32(v.x); u.y = f2tf32(v.y);
    u.z = f2tf32(v.z); u.w = f2tf32(v.w);
    *(uint4*)&out[(size_t)i * 4] = u;
}

// build Wall[D][6144] = [Wq | Wk*ks | Wv | Wg], tf32-rounded
__global__ void prep_wall(const float* __restrict__ Wq,
                          const float* __restrict__ Wk,
                          const float* __restrict__ Wv,
                          const float* __restrict__ Wg,
                          float* __restrict__ out, float kscale)
{
    int i = blockIdx.x * blockDim.x + threadIdx.x;   // float4 units
    if (i >= DD * PW / 4) return;
    int r  = i / (PW / 4);
    int c4 = (i - r * (PW / 4)) * 4;
    const float* src; int sc; float s = 1.0f;
    if (c4 < 1024)      { src = Wq + (size_t)r * 1024; sc = c4; }
    else if (c4 < 2048) { src = Wk + (size_t)r * 1024; sc = c4 - 1024; s = kscale; }
    else if (c4 < 4096) { src = Wv + (size_t)r * 2048; sc = c4 - 2048; }
    else                { src = Wg + (size_t)r * 2048; sc = c4 - 4096; }
    float4 v = *(const float4*)&src[sc];
    uint4 u;
    u.x = f2tf32(v.x * s); u.y = f2tf32(v.y * s);
    u.z = f2tf32(v.z * s); u.w = f2tf32(v.w * s);
    *(uint4*)&out[(size_t)r * PW + c4] = u;
}

__global__ void prep_bias(const float* __restrict__ bq,
                          const float* __restrict__ bk,
                          const float* __restrict__ bv,
                          const float* __restrict__ bg,
                          float* __restrict__ out, float kscale)
{
    int i = blockIdx.x * blockDim.x + threadIdx.x;
    if (i >= PW) return;
    float v;
    if (i < 1024)      v = bq[i];
    else if (i < 2048) v = bk[i - 1024] * kscale;
    else if (i < 4096) v = bv[i - 2048];
    else               v = bg[i - 4096];
    out[i] = v;
}

__global__ void rot_table(float2* __restrict__ rot)
{
    int i = blockIdx.x * blockDim.x + threadIdx.x;
    if (i >= SS * 32) return;
    int s = i >> 5, p = i & 31;
    double ang = pow(10000.0, -(double)p / 31.0);
    double sd, cd;
    sincos((double)s * ang, &sd, &cd);
    rot[i] = make_float2((float)cd, (float)sd);
}

// rotate a float4 (two adjacent rotary pairs) for sequence pos s, col c4
__device__ __forceinline__ float4 rot4(float4 t, int s, int c4,
                                       const float2* __restrict__ rot)
{
    int p0 = c4 >> 1;
    float2 cs0 = rot[(s << 5) + p0];
    float2 cs1 = rot[(s << 5) + p0 + 1];
    float4 o;
    o.x = t.x * cs0.x - t.y * cs0.y;
    o.y = t.y * cs0.x + t.x * cs0.y;
    o.z = t.z * cs1.x - t.w * cs1.y;
    o.w = t.w * cs1.x + t.z * cs1.y;
    return o;
}

// ---------------- cp.async 3-stage tf32 GEMM -------------------------------
#define GSTG (128*36 + 32*136)               // words per stage: 8960
#define GEMM_SMEM_BYTES (3 * GSTG * 4)       // 107520

__global__ __launch_bounds__(256, 2) void gemm_tf32_pipe(
    const float* __restrict__ A, const float* __restrict__ B,
    const float* __restrict__ bias, float* __restrict__ C,
    int M, int N, int K)
{
    extern __shared__ uint32_t dsm[];

    const int tid  = threadIdx.x;
    const int warp = tid >> 5, lane = tid & 31;
    const int wm = warp & 1, wn = warp >> 1;
    const int row0 = blockIdx.y * 128;
    const int col0 = blockIdx.x * 128;
    const int lr = lane >> 2;
    const int lc = lane & 3;

    float acc[4][4][4];
#pragma unroll
    for (int mt = 0; mt < 4; mt++)
#pragma unroll
        for (int nt = 0; nt < 4; nt++)
#pragma unroll
            for (int r = 0; r < 4; r++) acc[mt][nt][r] = 0.f;

    auto load_stage = [&](int s, int k0) {
        uint32_t* As = dsm + s * GSTG;
        uint32_t* Bs = dsm + s * GSTG + 128 * 36;
#pragma unroll
        for (int l = 0; l < 4; l++) {
            int f  = tid + 256 * l;
            int r  = f >> 3;
            int c4 = (f & 7) * 4;
            cp_async16(&As[r * 36 + c4],
                       &A[(size_t)(row0 + r) * K + k0 + c4]);
        }
#pragma unroll
        for (int l = 0; l < 4; l++) {
            int f  = tid + 256 * l;
            int r  = f >> 5;
            int c4 = (f & 31) * 4;
            cp_async16(&Bs[r * 136 + c4],
                       &B[(size_t)(k0 + r) * N + col0 + c4]);
        }
        cp_commit();
    };

    load_stage(0, 0);
    load_stage(1, 32);

    int s = 0;
    for (int k0 = 0; k0 < K; k0 += 32) {
        if (k0 + 32 < K) cp_wait1(); else cp_wait0();
        __syncthreads();

        const uint32_t* As = dsm + s * GSTG;
        const uint32_t* Bs = dsm + s * GSTG + 128 * 36;

#pragma unroll
        for (int ks = 0; ks < 4; ks++) {
            const int kb = ks * 8;
            uint32_t afr[4][4];
#pragma unroll
            for (int mt = 0; mt < 4; mt++) {
                int mrow = wm * 64 + mt * 16 + lr;
                afr[mt][0] = As[(mrow    ) * 36 + kb + lc];
                afr[mt][1] = As[(mrow + 8) * 36 + kb + lc];
                afr[mt][2] = As[(mrow    ) * 36 + kb + 4 + lc];
                afr[mt][3] = As[(mrow + 8) * 36 + kb + 4 + lc];
            }
            uint32_t bfr[4][2];
#pragma unroll
            for (int nt = 0; nt < 4; nt++) {
                int ncol = wn * 32 + nt * 8 + lr;
                bfr[nt][0] = Bs[(kb + lc    ) * 136 + ncol];
                bfr[nt][1] = Bs[(kb + 4 + lc) * 136 + ncol];
            }
#pragma unroll
            for (int mt = 0; mt < 4; mt++)
#pragma unroll
                for (int nt = 0; nt < 4; nt++)
                    mma_tf32(acc[mt][nt], afr[mt], bfr[nt]);
        }

        int kn = k0 + 64;
        if (kn < K) load_stage((s + 2) % 3, kn);
        s = (s + 1) % 3;
    }

#pragma unroll
    for (int mt = 0; mt < 4; mt++) {
        int r0 = row0 + wm * 64 + mt * 16 + lr;
        int r1 = r0 + 8;
#pragma unroll
        for (int nt = 0; nt < 4; nt++) {
            int c = col0 + wn * 32 + nt * 8 + 2 * lc;
            float b0 = bias[c], b1 = bias[c + 1];
            float2 o0 = { acc[mt][nt][0] + b0, acc[mt][nt][1] + b1 };
            float2 o1 = { acc[mt][nt][2] + b0, acc[mt][nt][3] + b1 };
            *(float2*)&C[(size_t)r0 * N + c] = o0;
            *(float2*)&C[(size_t)r1 * N + c] = o1;
        }
    }
}

// ---------------- pass A: per-chunk state A_c = K^T diag(w) V --------------
#define CSA_KW   0                    // 64 x 65
#define CSA_VS   (64*65)              // 64 x 132
#define CSA_FLOATS (64*65 + 64*132)   // 12608
#define CSA_BYTES (CSA_FLOATS * 4)    // 50432

__global__ __launch_bounds__(256, 2) void chunk_state(
    const float* __restrict__ proj, const float2* __restrict__ rot,
    float* __restrict__ stA, float* __restrict__ ksA)
{
    extern __shared__ float sm[];
    float* kw  = sm + CSA_KW;    // [t][kd] stride 65, rotated + pre-weighted
    float* vsm = sm + CSA_VS;    // [t][hd] stride 132

    __shared__ float wsh[64];

    const int c = blockIdx.x, h = blockIdx.y, b = blockIdx.z;
    const int tid = threadIdx.x;
    const int tx = tid & 15, ty = tid >> 4;
    const float decay = log1pf(-exp2f(-5.0f - (float)h));

    if (tid < 64) wsh[tid] = expf(decay * (float)(63 - tid));
    __syncthreads();

    {
        const size_t kbase = ((size_t)b * SS + c * CH) * PW + 1024 + h * KD;
#pragma unroll
        for (int l = 0; l < 4; l++) {
            int i  = tid + 256 * l;
            int r  = i >> 4;
            int c4 = (i & 15) * 4;
            float4 t4 = *(const float4*)&proj[kbase + (size_t)r * PW + c4];
            t4 = rot4(t4, c * CH + r, c4, rot);
            float w = wsh[r];
            kw[r * 65 + c4 + 0] = t4.x * w;
            kw[r * 65 + c4 + 1] = t4.y * w;
            kw[r * 65 + c4 + 2] = t4.z * w;
            kw[r * 65 + c4 + 3] = t4.w * w;
        }
        const size_t vbase = ((size_t)b * SS + c * CH) * PW + 2048 + h * HD;
#pragma unroll
        for (int l = 0; l < 8; l++) {
            int i  = tid + 256 * l;
            int r  = i >> 5;
            int c4 = (i & 31) * 4;
            *(float4*)&vsm[r * 132 + c4] =
                *(const float4*)&proj[vbase + (size_t)r * PW + c4];
        }
    }
    __syncthreads();

    float acc[4][8];
#pragma unroll
    for (int i = 0; i < 4; i++)
#pragma unroll
        for (int j = 0; j < 8; j++) acc[i][j] = 0.f;

#pragma unroll 4
    for (int t = 0; t < 64; t++) {
        float a[4];
#pragma unroll
        for (int i = 0; i < 4; i++) a[i] = kw[t * 65 + ty * 4 + i];
        float4 v0 = *(float4*)&vsm[t * 132 + tx * 8];
        float4 v1 = *(float4*)&vsm[t * 132 + tx * 8 + 4];
#pragma unroll
        for (int i = 0; i < 4; i++) {
            acc[i][0] += a[i] * v0.x; acc[i][1] += a[i] * v0.y;
            acc[i][2] += a[i] * v0.z; acc[i][3] += a[i] * v0.w;
            acc[i][4] += a[i] * v1.x; acc[i][5] += a[i] * v1.y;
            acc[i][6] += a[i] * v1.z; acc[i][7] += a[i] * v1.w;
        }
    }

    const size_t abase = (((size_t)(b * HH + h)) * NC + c) * (KD * HD);
#pragma unroll
    for (int i = 0; i < 4; i++) {
        int kd = ty * 4 + i;
        float4 o0 = {acc[i][0], acc[i][1], acc[i][2], acc[i][3]};
        float4 o1 = {acc[i][4], acc[i][5], acc[i][6], acc[i][7]};
        *(float4*)&stA[abase + (size_t)kd * HD + tx * 8]     = o0;
        *(float4*)&stA[abase + (size_t)kd * HD + tx * 8 + 4] = o1;
    }
    if (tid < 64) {
        float s = 0.f;
#pragma unroll 8
        for (int t = 0; t < 64; t++) s += kw[t * 65 + tid];
        ksA[(((size_t)(b * HH + h)) * NC + c) * KD + tid] = s;
    }
}

// ---------------- pass B: parallel exclusive prefix scan -------------------
// grid (8, BB*HH): each thread owns ONE float4 lane and scans 32 chunks.
__global__ __launch_bounds__(256) void state_scan_par(
    const float* __restrict__ stA, float* __restrict__ stP)
{
    const int bh = blockIdx.y;
    const int h  = bh & (HH - 1);
    const float decay = log1pf(-exp2f(-5.0f - (float)h));
    const float lam   = expf(decay * (float)CH);

    const size_t base4 = (size_t)bh * NC * (KD * HD / 4);
    const int idx4 = blockIdx.x * 256 + threadIdx.x;   // 0..2047
    const float4* A4 = (const float4*)stA;
    float4* P4 = (float4*)stP;

    float4 st = make_float4(0.f, 0.f, 0.f, 0.f);
    for (int c = 0; c < NC; c++) {
        size_t id = base4 + (size_t)c * (KD * HD / 4) + idx4;
        P4[id] = st;
        float4 a = A4[id];
        st.x = lam * st.x + a.x;
        st.y = lam * st.y + a.y;
        st.z = lam * st.z + a.z;
        st.w = lam * st.w + a.w;
    }
}

__global__ void ks_scan(const float* __restrict__ ksA,
                        float* __restrict__ ksP)
{
    const int bh = blockIdx.x;
    const int h  = bh & (HH - 1);
    const int tid = threadIdx.x;          // 64 threads
    const float decay = log1pf(-exp2f(-5.0f - (float)h));
    const float lam   = expf(decay * (float)CH);
    float pk = 0.f;
    const size_t kb = (size_t)bh * NC * KD + tid;
    for (int c = 0; c < NC; c++) {
        ksP[kb + (size_t)c * KD] = pk;
        pk = lam * pk + ksA[kb + (size_t)c * KD];
    }
}

// ---------------- pass C: intra-chunk retention + cross + LN + SiLU --------
#define RF_QS 0                        // 64 x 65
#define RF_KS (64*65)                  // 64 x 65 (reused for P staging)
#define RF_VS (2*64*65)                // 64 x 132
#define RF_SC (2*64*65 + 64*132)       // 64 x 65
#define RF_FLOATS (3*64*65 + 64*132)   // 20928
#define RF_BYTES (RF_FLOATS * 4)       // 83712
#define RF_P  RF_KS

__global__ __launch_bounds__(256, 2) void retention_final(
    const float* __restrict__ proj, const float2* __restrict__ rot,
    const float* __restrict__ stP, const float* __restrict__ ksP,
    float* __restrict__ outp)
{
    extern __shared__ float sm[];
    float* qs = sm + RF_QS;
    float* ks = sm + RF_KS;
    float* vs = sm + RF_VS;
    float* sc = sm + RF_SC;

    __shared__ float erow[64];
    __shared__ float etab[64];
    __shared__ float pksh[64];
    __shared__ float denom_s[64];
    __shared__ float psum[64][16], psq[64][16];

    const int c = blockIdx.x, h = blockIdx.y, b = blockIdx.z;
    const int tid = threadIdx.x;
    const int tx = tid & 15, ty = tid >> 4;
    const int ty4 = ty * 4;
    const int s0 = c * CH;
    const float decay = log1pf(-exp2f(-5.0f - (float)h));
    const float ed = expf(decay);

    {
        const size_t qbase = ((size_t)b * SS + s0) * PW + h * KD;
#pragma unroll
        for (int l = 0; l < 4; l++) {
            int i  = tid + 256 * l;
            int r  = i >> 4;
            int c4 = (i & 15) * 4;
            float4 t4 = *(const float4*)&proj[qbase + (size_t)r * PW + c4];
            t4 = rot4(t4, s0 + r, c4, rot);
            qs[r * 65 + c4 + 0] = t4.x; qs[r * 65 + c4 + 1] = t4.y;
            qs[r * 65 + c4 + 2] = t4.z; qs[r * 65 + c4 + 3] = t4.w;
            float4 k4 = *(const float4*)&proj[qbase + 1024 + (size_t)r * PW + c4];
            k4 = rot4(k4, s0 + r, c4, rot);
            ks[r * 65 + c4 + 0] = k4.x; ks[r * 65 + c4 + 1] = k4.y;
            ks[r * 65 + c4 + 2] = k4.z; ks[r * 65 + c4 + 3] = k4.w;
        }
        const size_t vbase = ((size_t)b * SS + s0) * PW + 2048 + h * HD;
#pragma unroll
        for (int l = 0; l < 8; l++) {
            int i  = tid + 256 * l;
            int r  = i >> 5;
            int c4 = (i & 31) * 4;
            *(float4*)&vs[r * 132 + c4] =
                *(const float4*)&proj[vbase + (size_t)r * PW + c4];
        }
    }
    if (tid < 64) {
        int gs = s0 + tid;
        float rowsum = expm1f(decay * (float)(gs + 1)) / expm1f(decay);
        erow[tid] = expf(decay * (float)tid) * rsqrtf(rowsum);
        etab[tid] = expf(-decay * (float)tid);
        pksh[tid] = ksP[(((size_t)(b * HH + h)) * NC + c) * KD + tid];
    }
    __syncthreads();

    float dot[4][4];
#pragma unroll
    for (int i = 0; i < 4; i++)
#pragma unroll
        for (int j = 0; j < 4; j++) dot[i][j] = 0.f;
#pragma unroll 8
    for (int d = 0; d < 64; d++) {
        float qa[4], kb[4];
#pragma unroll
        for (int i = 0; i < 4; i++) qa[i] = qs[(ty4 + i) * 65 + d];
#pragma unroll
        for (int j = 0; j < 4; j++) kb[j] = ks[(tx * 4 + j) * 65 + d];
#pragma unroll
        for (int i = 0; i < 4; i++)
#pragma unroll
            for (int j = 0; j < 4; j++) dot[i][j] += qa[i] * kb[j];
    }
#pragma unroll
    for (int i = 0; i < 4; i++) {
        int sl = ty4 + i;
        float ai = erow[sl];
#pragma unroll
        for (int j = 0; j < 4; j++) {
            int tl = tx * 4 + j;
            float m = (tl <= sl) ? ai * etab[tl] : 0.f;
            sc[sl * 65 + tl] = dot[i][j] * m;
        }
    }
    __syncthreads();

    if (tid < 64) {
        float s = 0.f;
#pragma unroll 8
        for (int t = 0; t < 64; t++) s += sc[tid * 65 + t];
        float dk = 0.f;
#pragma unroll 8
        for (int d = 0; d < 64; d++) dk += qs[tid * 65 + d] * pksh[d];
        denom_s[tid] = fmaxf(fabsf(s + erow[tid] * ed * dk), 1.0f);
    }

    float acc[4][8];
#pragma unroll
    for (int i = 0; i < 4; i++)
#pragma unroll
        for (int j = 0; j < 8; j++) acc[i][j] = 0.f;
#pragma unroll 4
    for (int t = 0; t < 64; t++) {
        float4 v0 = *(float4*)&vs[t * 132 + tx * 8];
        float4 v1 = *(float4*)&vs[t * 132 + tx * 8 + 4];
#pragma unroll
        for (int i = 0; i < 4; i++) {
            float a = sc[(ty4 + i) * 65 + t];
            acc[i][0] += a * v0.x; acc[i][1] += a * v0.y;
            acc[i][2] += a * v0.z; acc[i][3] += a * v0.w;
            acc[i][4] += a * v1.x; acc[i][5] += a * v1.y;
            acc[i][6] += a * v1.z; acc[i][7] += a * v1.w;
        }
    }
    __syncthreads();

    {
        const size_t pbase = (((size_t)(b * HH + h)) * NC + c) * (KD * HD);
        float* p = sm + RF_P;
#pragma unroll
        for (int l = 0; l < 8; l++) {
            int f  = tid + 256 * l;
            int d  = f >> 5;
            int c4 = (f & 31) * 4;
            *(float4*)&p[d * 132 + c4] =
                *(const float4*)&stP[pbase + (size_t)d * HD + c4];
        }
    }
    __syncthreads();

    {
        const float* p = sm + RF_P;
        float acc2[4][8];
#pragma unroll
        for (int i = 0; i < 4; i++)
#pragma unroll
            for (int j = 0; j < 8; j++) acc2[i][j] = 0.f;
#pragma unroll 4
        for (int d = 0; d < 64; d++) {
            float qa[4];
#pragma unroll
            for (int i = 0; i < 4; i++) qa[i] = qs[(ty4 + i) * 65 + d];
            float4 p0 = *(const float4*)&p[d * 132 + tx * 8];
            float4 p1 = *(const float4*)&p[d * 132 + tx * 8 + 4];
#pragma unroll
            for (int i = 0; i < 4; i++) {
                acc2[i][0] += qa[i] * p0.x; acc2[i][1] += qa[i] * p0.y;
                acc2[i][2] += qa[i] * p0.z; acc2[i][3] += qa[i] * p0.w;
                acc2[i][4] += qa[i] * p1.x; acc2[i][5] += qa[i] * p1.y;
                acc2[i][6] += qa[i] * p1.z; acc2[i][7] += qa[i] * p1.w;
            }
        }
#pragma unroll
        for (int i = 0; i < 4; i++) {
            float cf = erow[ty4 + i] * ed;
#pragma unroll
            for (int j = 0; j < 8; j++) acc[i][j] += cf * acc2[i][j];
        }
    }
    __syncthreads();

#pragma unroll
    for (int i = 0; i < 4; i++) {
        float inv = 1.0f / denom_s[ty4 + i];
        float s = 0.f, s2 = 0.f;
#pragma unroll
        for (int j = 0; j < 8; j++) {
            acc[i][j] *= inv;
            s  += acc[i][j];
            s2 += acc[i][j] * acc[i][j];
        }
        psum[ty4 + i][tx] = s;
        psq [ty4 + i][tx] = s2;
    }
    __syncthreads();

    const size_t obase = ((size_t)b * SS + s0) * (2 * DD) + h * HD;
    const size_t gbase = ((size_t)b * SS + s0) * PW + 4096 + h * HD;
#pragma unroll
    for (int i = 0; i < 4; i++) {
        int r = ty4 + i;
        float s = 0.f, s2 = 0.f;
#pragma unroll
        for (int pp = 0; pp < 16; pp++) { s += psum[r][pp]; s2 += psq[r][pp]; }
        float mu  = s * (1.0f / 128.0f);
        float var = s2 * (1.0f / 128.0f) - mu * mu;
        float inv = rsqrtf(var + 1e-5f);

        size_t go = gbase + (size_t)r * PW + tx * 8;
        size_t oo = obase + (size_t)r * (2 * DD) + tx * 8;
        float4 g0 = *(const float4*)&proj[go];
        float4 g1 = *(const float4*)&proj[go + 4];
        float gg[8] = {g0.x,g0.y,g0.z,g0.w,g1.x,g1.y,g1.z,g1.w};
        float o[8];
#pragma unroll
        for (int j = 0; j < 8; j++) {
            float nv = (acc[i][j] - mu) * inv;
            float gv = gg[j];
            o[j] = __uint_as_float(
                f2tf32(nv * (gv / (1.0f + expf(-gv)))));
        }
        float4 o0 = {o[0], o[1], o[2], o[3]};
        float4 o1 = {o[4], o[5], o[6], o[7]};
        *(float4*)&outp[oo]     = o0;
        *(float4*)&outp[oo + 4] = o1;
    }
}

// ---------------- launch ---------------------------------------------------
extern "C" void kernel_launch(void* const* d_in, const int* in_sizes, int n_in,
                              void* d_out, int out_size)
{
    (void)in_sizes; (void)n_in; (void)out_size;
    const float* x  = (const float*)d_in[0];
    const float* Wq = (const float*)d_in[1];
    const float* bq = (const float*)d_in[2];
    const float* Wk = (const float*)d_in[3];
    const float* bk = (const float*)d_in[4];
    const float* Wv = (const float*)d_in[5];
    const float* bv = (const float*)d_in[6];
    const float* Wg = (const float*)d_in[7];
    const float* bg = (const float*)d_in[8];
    const float* Wo = (const float*)d_in[9];
    const float* bo = (const float*)d_in[10];
    float* out = (float*)d_out;

    float *proj, *pre, *xt, *wall, *wot, *ball;
    float *stA, *stP, *ksA, *ksP;
    float2* rot;
    cudaGetSymbolAddress((void**)&proj, g_proj);
    cudaGetSymbolAddress((void**)&pre,  g_pre);
    cudaGetSymbolAddress((void**)&xt,   g_xt);
    cudaGetSymbolAddress((void**)&wall, g_wall);
    cudaGetSymbolAddress((void**)&wot,  g_wot);
    cudaGetSymbolAddress((void**)&ball, g_ball);
    cudaGetSymbolAddress((void**)&rot,  g_rot);
    cudaGetSymbolAddress((void**)&stA,  g_stA);
    cudaGetSymbolAddress((void**)&stP,  g_stP);
    cudaGetSymbolAddress((void**)&ksA,  g_ksA);
    cudaGetSymbolAddress((void**)&ksP,  g_ksP);

    cudaFuncSetAttribute(gemm_tf32_pipe,
                         cudaFuncAttributeMaxDynamicSharedMemorySize,
                         GEMM_SMEM_BYTES);
    cudaFuncSetAttribute(chunk_state,
                         cudaFuncAttributeMaxDynamicSharedMemorySize,
                         CSA_BYTES);
    cudaFuncSetAttribute(retention_final,
                         cudaFuncAttributeMaxDynamicSharedMemorySize,
                         RF_BYTES);

    const float kscale = 0.125f;   // 64^-0.5 (power of two -> exact fold)
    dim3 thr(256);

    round_tf32<<<(MM * DD / 4 + 255) / 256, 256>>>(x, xt, MM * DD / 4);
    prep_wall<<<(DD * PW / 4 + 255) / 256, 256>>>(Wq, Wk, Wv, Wg, wall, kscale);
    round_tf32<<<(2 * DD * DD / 4 + 255) / 256, 256>>>(Wo, wot, 2 * DD * DD / 4);
    prep_bias<<<(PW + 255) / 256, 256>>>(bq, bk, bv, bg, ball, kscale);
    rot_table<<<(SS * 32 + 255) / 256, 256>>>(rot);

    // single fused projection: q|k|v|g
    gemm_tf32_pipe<<<dim3(PW / 128, MM / 128), thr, GEMM_SMEM_BYTES>>>(
        xt, wall, ball, proj, MM, PW, DD);

    chunk_state<<<dim3(NC, HH, BB), thr, CSA_BYTES>>>(proj, rot, stA, ksA);
    state_scan_par<<<dim3(8, BB * HH), thr>>>(stA, stP);
    ks_scan<<<BB * HH, 64>>>(ksA, ksP);
    retention_final<<<dim3(NC, HH, BB), thr, RF_BYTES>>>(
        proj, rot, stP, ksP, pre);

    gemm_tf32_pipe<<<dim3(DD / 128, MM / 128), thr, GEMM_SMEM_BYTES>>>(
        pre, wot, bo, out, MM, DD, 2 * DD);
}

// round 14
// speedup vs baseline: 6.6176x; 1.4473x over previous
#include <cuda_runtime.h>
#include <cuda_fp16.h>
#include <math.h>
#include <stdint.h>

#define BB 2
#define SS 2048
#define DD 1024
#define HH 16
#define MM (BB*SS)          // 4096 rows
#define KD 64               // key dim per head
#define HD 128              // head dim per head
#define NC 32               // retention chunks per sequence
#define CH 64               // retention chunk length
#define PW 6144             // fused projection width: q|k|v|g
#define K2P (DD/2)          // 512  packed-K for projection
#define K2O (2*DD/2)        // 1024 packed-K for out-GEMM

// ---------------- scratch (device globals; no allocation allowed) ----------
__device__ float    g_proj[(size_t)MM * PW];
__device__ uint32_t g_xp[(size_t)MM * K2P];        // x packed half2 along K
__device__ uint32_t g_wallp[(size_t)K2P * PW];     // Wall packed [k2][n]
__device__ uint32_t g_wop[(size_t)K2O * DD];       // Wo packed [k2][n]
__device__ uint32_t g_prep[(size_t)MM * K2O];      // pre packed [m][k2]
__device__ float    g_ball[PW];
__device__ float2   g_rot[SS * 32];
__device__ float    g_stA[(size_t)BB * HH * NC * KD * HD];
__device__ float    g_stP[(size_t)BB * HH * NC * KD * HD];
__device__ float    g_ksA[(size_t)BB * HH * NC * KD];
__device__ float    g_ksP[(size_t)BB * HH * NC * KD];

// ---------------- helpers ---------------------------------------------------
__device__ __forceinline__ uint32_t packh2(float a, float b) {
    __half2 t = __floats2half2_rn(a, b);
    return *reinterpret_cast<uint32_t*>(&t);
}

__device__ __forceinline__ void mma_f16(float c[4], const uint32_t a[4],
                                        const uint32_t b[2]) {
    asm volatile(
        "mma.sync.aligned.m16n8k16.row.col.f32.f16.f16.f32 "
        "{%0,%1,%2,%3}, {%4,%5,%6,%7}, {%8,%9}, {%0,%1,%2,%3};"
        : "+f"(c[0]), "+f"(c[1]), "+f"(c[2]), "+f"(c[3])
        : "r"(a[0]), "r"(a[1]), "r"(a[2]), "r"(a[3]),
          "r"(b[0]), "r"(b[1]));
}

__device__ __forceinline__ void cp_async16(void* smem_ptr, const void* gptr) {
    uint32_t saddr = (uint32_t)__cvta_generic_to_shared(smem_ptr);
    asm volatile("cp.async.cg.shared.global [%0], [%1], 16;\n"
                 :: "r"(saddr), "l"(gptr));
}
__device__ __forceinline__ void cp_commit() {
    asm volatile("cp.async.commit_group;\n");
}
__device__ __forceinline__ void cp_wait1() {
    asm volatile("cp.async.wait_group 1;\n");
}
__device__ __forceinline__ void cp_wait0() {
    asm volatile("cp.async.wait_group 0;\n");
}

// ---------------- prep passes ----------------------------------------------
// x [M][1024] fp32 -> xp [M][512] half2-packed along K
__global__ void prep_x_pack(const float* __restrict__ x,
                            uint32_t* __restrict__ xp)
{
    int i = blockIdx.x * blockDim.x + threadIdx.x;   // quad-u32 units
    if (i >= MM * K2P / 4) return;
    int m  = i >> 7;                  // /(512/4)
    int q4 = (i & 127) * 4;           // u32 offset in row
    const float* src = x + (size_t)m * DD + q4 * 2;
    float4 v0 = *(const float4*)src;
    float4 v1 = *(const float4*)(src + 4);
    uint4 u;
    u.x = packh2(v0.x, v0.y); u.y = packh2(v0.z, v0.w);
    u.z = packh2(v1.x, v1.y); u.w = packh2(v1.z, v1.w);
    *(uint4*)&xp[(size_t)m * K2P + q4] = u;
}

// Wall packed: wallp[k2][n] = half2(W*[2k2][n], W*[2k2+1][n]); q|k*ks|v|g cols
__global__ void prep_wall_pack(const float* __restrict__ Wq,
                               const float* __restrict__ Wk,
                               const float* __restrict__ Wv,
                               const float* __restrict__ Wg,
                               uint32_t* __restrict__ out, float kscale)
{
    int i = blockIdx.x * blockDim.x + threadIdx.x;   // (k2, n4) quads
    if (i >= K2P * PW / 4) return;
    int k2 = i / (PW / 4);
    int n4 = (i - k2 * (PW / 4)) * 4;
    const float* src; int sc; float s = 1.0f; int ld;
    if (n4 < 1024)      { src = Wq; sc = n4;        ld = 1024; }
    else if (n4 < 2048) { src = Wk; sc = n4 - 1024; ld = 1024; s = kscale; }
    else if (n4 < 4096) { src = Wv; sc = n4 - 2048; ld = 2048; }
    else                { src = Wg; sc = n4 - 4096; ld = 2048; }
    float4 r0 = *(const float4*)&src[(size_t)(2 * k2)     * ld + sc];
    float4 r1 = *(const float4*)&src[(size_t)(2 * k2 + 1) * ld + sc];
    uint4 u;
    u.x = packh2(r0.x * s, r1.x * s); u.y = packh2(r0.y * s, r1.y * s);
    u.z = packh2(r0.z * s, r1.z * s); u.w = packh2(r0.w * s, r1.w * s);
    *(uint4*)&out[(size_t)k2 * PW + n4] = u;
}

// Wo [2048][1024] -> wop [1024][1024] half2-packed along K
__global__ void prep_wo_pack(const float* __restrict__ Wo,
                             uint32_t* __restrict__ out)
{
    int i = blockIdx.x * blockDim.x + threadIdx.x;
    if (i >= K2O * DD / 4) return;
    int k2 = i >> 8;                  // /(1024/4)
    int n4 = (i & 255) * 4;
    float4 r0 = *(const float4*)&Wo[(size_t)(2 * k2)     * DD + n4];
    float4 r1 = *(const float4*)&Wo[(size_t)(2 * k2 + 1) * DD + n4];
    uint4 u;
    u.x = packh2(r0.x, r1.x); u.y = packh2(r0.y, r1.y);
    u.z = packh2(r0.z, r1.z); u.w = packh2(r0.w, r1.w);
    *(uint4*)&out[(size_t)k2 * DD + n4] = u;
}

__global__ void prep_bias(const float* __restrict__ bq,
                          const float* __restrict__ bk,
                          const float* __restrict__ bv,
                          const float* __restrict__ bg,
                          float* __restrict__ out, float kscale)
{
    int i = blockIdx.x * blockDim.x + threadIdx.x;
    if (i >= PW) return;
    float v;
    if (i < 1024)      v = bq[i];
    else if (i < 2048) v = bk[i - 1024] * kscale;
    else if (i < 4096) v = bv[i - 2048];
    else               v = bg[i - 4096];
    out[i] = v;
}

__global__ void rot_table(float2* __restrict__ rot)
{
    int i = blockIdx.x * blockDim.x + threadIdx.x;
    if (i >= SS * 32) return;
    int s = i >> 5, p = i & 31;
    double ang = pow(10000.0, -(double)p / 31.0);
    double sd, cd;
    sincos((double)s * ang, &sd, &cd);
    rot[i] = make_float2((float)cd, (float)sd);
}

__device__ __forceinline__ float4 rot4(float4 t, int s, int c4,
                                       const float2* __restrict__ rot)
{
    int p0 = c4 >> 1;
    float2 cs0 = rot[(s << 5) + p0];
    float2 cs1 = rot[(s << 5) + p0 + 1];
    float4 o;
    o.x = t.x * cs0.x - t.y * cs0.y;
    o.y = t.y * cs0.x + t.x * cs0.y;
    o.z = t.z * cs1.x - t.w * cs1.y;
    o.w = t.w * cs1.x + t.z * cs1.y;
    return o;
}

// ---------------- cp.async 3-stage fp16 GEMM (m16n8k16) --------------------
// A: [M][K2] half2-packed, B: [K2][N] half2-packed, bias fp32, C fp32.
// Block tile 128x128, chunk = 16 k-pairs (K=32). 8 warps, 64x32 each.
#define ASTG (128*20)                        // u32 per A stage (pad 16->20)
#define BSTG (16*136)                        // u32 per B stage (pad 128->136)
#define GSTG2 (ASTG + BSTG)                  // 4736 u32 = 18944 B
#define GEMM_SMEM_BYTES (3 * GSTG2 * 4)      // 56832

__global__ __launch_bounds__(256, 2) void gemm_f16_pipe(
    const uint32_t* __restrict__ A, const uint32_t* __restrict__ B,
    const float* __restrict__ bias, float* __restrict__ C,
    int N, int K2)
{
    extern __shared__ uint32_t dsm[];

    const int tid  = threadIdx.x;
    const int warp = tid >> 5, lane = tid & 31;
    const int wm = warp & 1, wn = warp >> 1;
    const int row0 = blockIdx.y * 128;
    const int col0 = blockIdx.x * 128;
    const int lr = lane >> 2;
    const int lc = lane & 3;

    float acc[4][4][4];
#pragma unroll
    for (int mt = 0; mt < 4; mt++)
#pragma unroll
        for (int nt = 0; nt < 4; nt++)
#pragma unroll
            for (int r = 0; r < 4; r++) acc[mt][nt][r] = 0.f;

    // stage loader: A 128 rows x 16 u32 (4 cp/row), B 16 rows x 128 u32
    auto load_stage = [&](int s, int k0_2) {
        uint32_t* As = dsm + s * GSTG2;
        uint32_t* Bs = dsm + s * GSTG2 + ASTG;
#pragma unroll
        for (int l = 0; l < 2; l++) {
            int f  = tid + 256 * l;          // 0..511
            int r  = f >> 2;                 // 0..127
            int c4 = (f & 3) * 4;            // 0,4,8,12
            cp_async16(&As[r * 20 + c4],
                       &A[(size_t)(row0 + r) * K2 + k0_2 + c4]);
        }
#pragma unroll
        for (int l = 0; l < 2; l++) {
            int f  = tid + 256 * l;
            int r  = f >> 5;                 // 0..15
            int c4 = (f & 31) * 4;           // 0..124
            cp_async16(&Bs[r * 136 + c4],
                       &B[(size_t)(k0_2 + r) * N + col0 + c4]);
        }
        cp_commit();
    };

    load_stage(0, 0);
    load_stage(1, 16);

    int s = 0;
    for (int k0 = 0; k0 < K2; k0 += 16) {
        if (k0 + 16 < K2) cp_wait1(); else cp_wait0();
        __syncthreads();

        const uint32_t* As = dsm + s * GSTG2;
        const uint32_t* Bs = dsm + s * GSTG2 + ASTG;

#pragma unroll
        for (int ks = 0; ks < 2; ks++) {
            const int kb = ks * 8;           // k-pair offset
            uint32_t afr[4][4];
#pragma unroll
            for (int mt = 0; mt < 4; mt++) {
                int mrow = wm * 64 + mt * 16 + lr;
                afr[mt][0] = As[(mrow    ) * 20 + kb + lc];
                afr[mt][1] = As[(mrow + 8) * 20 + kb + lc];
                afr[mt][2] = As[(mrow    ) * 20 + kb + 4 + lc];
                afr[mt][3] = As[(mrow + 8) * 20 + kb + 4 + lc];
            }
            uint32_t bfr[4][2];
#pragma unroll
            for (int nt = 0; nt < 4; nt++) {
                int ncol = wn * 32 + nt * 8 + lr;
                bfr[nt][0] = Bs[(kb + lc    ) * 136 + ncol];
                bfr[nt][1] = Bs[(kb + 4 + lc) * 136 + ncol];
            }
#pragma unroll
            for (int mt = 0; mt < 4; mt++)
#pragma unroll
                for (int nt = 0; nt < 4; nt++)
                    mma_f16(acc[mt][nt], afr[mt], bfr[nt]);
        }

        int kn = k0 + 32;
        if (kn < K2) load_stage((s + 2) % 3, kn);
        s = (s + 1) % 3;
    }

#pragma unroll
    for (int mt = 0; mt < 4; mt++) {
        int r0 = row0 + wm * 64 + mt * 16 + lr;
        int r1 = r0 + 8;
#pragma unroll
        for (int nt = 0; nt < 4; nt++) {
            int c = col0 + wn * 32 + nt * 8 + 2 * lc;
            float b0 = bias[c], b1 = bias[c + 1];
            float2 o0 = { acc[mt][nt][0] + b0, acc[mt][nt][1] + b1 };
            float2 o1 = { acc[mt][nt][2] + b0, acc[mt][nt][3] + b1 };
            *(float2*)&C[(size_t)r0 * N + c] = o0;
            *(float2*)&C[(size_t)r1 * N + c] = o1;
        }
    }
}

// ---------------- retention: pass A (chunk states) --------------------------
#define CSA_KW   0
#define CSA_VS   (64*65)
#define CSA_BYTES ((64*65 + 64*132) * 4)

__global__ __launch_bounds__(256, 2) void chunk_state(
    const float* __restrict__ proj, const float2* __restrict__ rot,
    float* __restrict__ stA, float* __restrict__ ksA)
{
    extern __shared__ float sm[];
    float* kw  = sm + CSA_KW;
    float* vsm = sm + CSA_VS;
    __shared__ float wsh[64];

    const int c = blockIdx.x, h = blockIdx.y, b = blockIdx.z;
    const int tid = threadIdx.x;
    const int tx = tid & 15, ty = tid >> 4;
    const float decay = log1pf(-exp2f(-5.0f - (float)h));

    if (tid < 64) wsh[tid] = expf(decay * (float)(63 - tid));
    __syncthreads();

    {
        const size_t kbase = ((size_t)b * SS + c * CH) * PW + 1024 + h * KD;
#pragma unroll
        for (int l = 0; l < 4; l++) {
            int i  = tid + 256 * l;
            int r  = i >> 4;
            int c4 = (i & 15) * 4;
            float4 t4 = *(const float4*)&proj[kbase + (size_t)r * PW + c4];
            t4 = rot4(t4, c * CH + r, c4, rot);
            float w = wsh[r];
            kw[r * 65 + c4 + 0] = t4.x * w;
            kw[r * 65 + c4 + 1] = t4.y * w;
            kw[r * 65 + c4 + 2] = t4.z * w;
            kw[r * 65 + c4 + 3] = t4.w * w;
        }
        const size_t vbase = ((size_t)b * SS + c * CH) * PW + 2048 + h * HD;
#pragma unroll
        for (int l = 0; l < 8; l++) {
            int i  = tid + 256 * l;
            int r  = i >> 5;
            int c4 = (i & 31) * 4;
            *(float4*)&vsm[r * 132 + c4] =
                *(const float4*)&proj[vbase + (size_t)r * PW + c4];
        }
    }
    __syncthreads();

    float acc[4][8];
#pragma unroll
    for (int i = 0; i < 4; i++)
#pragma unroll
        for (int j = 0; j < 8; j++) acc[i][j] = 0.f;

#pragma unroll 4
    for (int t = 0; t < 64; t++) {
        float a[4];
#pragma unroll
        for (int i = 0; i < 4; i++) a[i] = kw[t * 65 + ty * 4 + i];
        float4 v0 = *(float4*)&vsm[t * 132 + tx * 8];
        float4 v1 = *(float4*)&vsm[t * 132 + tx * 8 + 4];
#pragma unroll
        for (int i = 0; i < 4; i++) {
            acc[i][0] += a[i] * v0.x; acc[i][1] += a[i] * v0.y;
            acc[i][2] += a[i] * v0.z; acc[i][3] += a[i] * v0.w;
            acc[i][4] += a[i] * v1.x; acc[i][5] += a[i] * v1.y;
            acc[i][6] += a[i] * v1.z; acc[i][7] += a[i] * v1.w;
        }
    }

    const size_t abase = (((size_t)(b * HH + h)) * NC + c) * (KD * HD);
#pragma unroll
    for (int i = 0; i < 4; i++) {
        int kd = ty * 4 + i;
        float4 o0 = {acc[i][0], acc[i][1], acc[i][2], acc[i][3]};
        float4 o1 = {acc[i][4], acc[i][5], acc[i][6], acc[i][7]};
        *(float4*)&stA[abase + (size_t)kd * HD + tx * 8]     = o0;
        *(float4*)&stA[abase + (size_t)kd * HD + tx * 8 + 4] = o1;
    }
    if (tid < 64) {
        float s = 0.f;
#pragma unroll 8
        for (int t = 0; t < 64; t++) s += kw[t * 65 + tid];
        ksA[(((size_t)(b * HH + h)) * NC + c) * KD + tid] = s;
    }
}

// ---------------- retention: pass B (parallel prefix scans) ------------------
__global__ __launch_bounds__(256) void state_scan_par(
    const float* __restrict__ stA, float* __restrict__ stP)
{
    const int bh = blockIdx.y;
    const int h  = bh & (HH - 1);
    const float decay = log1pf(-exp2f(-5.0f - (float)h));
    const float lam   = expf(decay * (float)CH);

    const size_t base4 = (size_t)bh * NC * (KD * HD / 4);
    const int idx4 = blockIdx.x * 256 + threadIdx.x;
    const float4* A4 = (const float4*)stA;
    float4* P4 = (float4*)stP;

    float4 st = make_float4(0.f, 0.f, 0.f, 0.f);
    for (int c = 0; c < NC; c++) {
        size_t id = base4 + (size_t)c * (KD * HD / 4) + idx4;
        P4[id] = st;
        float4 a = A4[id];
        st.x = lam * st.x + a.x;
        st.y = lam * st.y + a.y;
        st.z = lam * st.z + a.z;
        st.w = lam * st.w + a.w;
    }
}

__global__ void ks_scan(const float* __restrict__ ksA,
                        float* __restrict__ ksP)
{
    const int bh = blockIdx.x;
    const int h  = bh & (HH - 1);
    const int tid = threadIdx.x;
    const float decay = log1pf(-exp2f(-5.0f - (float)h));
    const float lam   = expf(decay * (float)CH);
    float pk = 0.f;
    const size_t kb = (size_t)bh * NC * KD + tid;
    for (int c = 0; c < NC; c++) {
        ksP[kb + (size_t)c * KD] = pk;
        pk = lam * pk + ksA[kb + (size_t)c * KD];
    }
}

// ---------------- retention: pass C (+LN+SiLU, emits packed pre) ------------
#define RF_QS 0
#define RF_KS (64*65)
#define RF_VS (2*64*65)
#define RF_SC (2*64*65 + 64*132)
#define RF_BYTES ((3*64*65 + 64*132) * 4)
#define RF_P  RF_KS

__global__ __launch_bounds__(256, 2) void retention_final(
    const float* __restrict__ proj, const float2* __restrict__ rot,
    const float* __restrict__ stP, const float* __restrict__ ksP,
    uint32_t* __restrict__ prep)
{
    extern __shared__ float sm[];
    float* qs = sm + RF_QS;
    float* ks = sm + RF_KS;
    float* vs = sm + RF_VS;
    float* sc = sm + RF_SC;

    __shared__ float erow[64];
    __shared__ float etab[64];
    __shared__ float pksh[64];
    __shared__ float denom_s[64];
    __shared__ float psum[64][16], psq[64][16];

    const int c = blockIdx.x, h = blockIdx.y, b = blockIdx.z;
    const int tid = threadIdx.x;
    const int tx = tid & 15, ty = tid >> 4;
    const int ty4 = ty * 4;
    const int s0 = c * CH;
    const float decay = log1pf(-exp2f(-5.0f - (float)h));
    const float ed = expf(decay);

    {
        const size_t qbase = ((size_t)b * SS + s0) * PW + h * KD;
#pragma unroll
        for (int l = 0; l < 4; l++) {
            int i  = tid + 256 * l;
            int r  = i >> 4;
            int c4 = (i & 15) * 4;
            float4 t4 = *(const float4*)&proj[qbase + (size_t)r * PW + c4];
            t4 = rot4(t4, s0 + r, c4, rot);
            qs[r * 65 + c4 + 0] = t4.x; qs[r * 65 + c4 + 1] = t4.y;
            qs[r * 65 + c4 + 2] = t4.z; qs[r * 65 + c4 + 3] = t4.w;
            float4 k4 = *(const float4*)&proj[qbase + 1024 + (size_t)r * PW + c4];
            k4 = rot4(k4, s0 + r, c4, rot);
            ks[r * 65 + c4 + 0] = k4.x; ks[r * 65 + c4 + 1] = k4.y;
            ks[r * 65 + c4 + 2] = k4.z; ks[r * 65 + c4 + 3] = k4.w;
        }
        const size_t vbase = ((size_t)b * SS + s0) * PW + 2048 + h * HD;
#pragma unroll
        for (int l = 0; l < 8; l++) {
            int i  = tid + 256 * l;
            int r  = i >> 5;
            int c4 = (i & 31) * 4;
            *(float4*)&vs[r * 132 + c4] =
                *(const float4*)&proj[vbase + (size_t)r * PW + c4];
        }
    }
    if (tid < 64) {
        int gs = s0 + tid;
        float rowsum = expm1f(decay * (float)(gs + 1)) / expm1f(decay);
        erow[tid] = expf(decay * (float)tid) * rsqrtf(rowsum);
        etab[tid] = expf(-decay * (float)tid);
        pksh[tid] = ksP[(((size_t)(b * HH + h)) * NC + c) * KD + tid];
    }
    __syncthreads();

    float dot[4][4];
#pragma unroll
    for (int i = 0; i < 4; i++)
#pragma unroll
        for (int j = 0; j < 4; j++) dot[i][j] = 0.f;
#pragma unroll 8
    for (int d = 0; d < 64; d++) {
        float qa[4], kb[4];
#pragma unroll
        for (int i = 0; i < 4; i++) qa[i] = qs[(ty4 + i) * 65 + d];
#pragma unroll
        for (int j = 0; j < 4; j++) kb[j] = ks[(tx * 4 + j) * 65 + d];
#pragma unroll
        for (int i = 0; i < 4; i++)
#pragma unroll
            for (int j = 0; j < 4; j++) dot[i][j] += qa[i] * kb[j];
    }
#pragma unroll
    for (int i = 0; i < 4; i++) {
        int sl = ty4 + i;
        float ai = erow[sl];
#pragma unroll
        for (int j = 0; j < 4; j++) {
            int tl = tx * 4 + j;
            float m = (tl <= sl) ? ai * etab[tl] : 0.f;
            sc[sl * 65 + tl] = dot[i][j] * m;
        }
    }
    __syncthreads();

    if (tid < 64) {
        float s = 0.f;
#pragma unroll 8
        for (int t = 0; t < 64; t++) s += sc[tid * 65 + t];
        float dk = 0.f;
#pragma unroll 8
        for (int d = 0; d < 64; d++) dk += qs[tid * 65 + d] * pksh[d];
        denom_s[tid] = fmaxf(fabsf(s + erow[tid] * ed * dk), 1.0f);
    }

    float acc[4][8];
#pragma unroll
    for (int i = 0; i < 4; i++)
#pragma unroll
        for (int j = 0; j < 8; j++) acc[i][j] = 0.f;
#pragma unroll 4
    for (int t = 0; t < 64; t++) {
        float4 v0 = *(float4*)&vs[t * 132 + tx * 8];
        float4 v1 = *(float4*)&vs[t * 132 + tx * 8 + 4];
#pragma unroll
        for (int i = 0; i < 4; i++) {
            float a = sc[(ty4 + i) * 65 + t];
            acc[i][0] += a * v0.x; acc[i][1] += a * v0.y;
            acc[i][2] += a * v0.z; acc[i][3] += a * v0.w;
            acc[i][4] += a * v1.x; acc[i][5] += a * v1.y;
            acc[i][6] += a * v1.z; acc[i][7] += a * v1.w;
        }
    }
    __syncthreads();

    {
        const size_t pbase = (((size_t)(b * HH + h)) * NC + c) * (KD * HD);
        float* p = sm + RF_P;
#pragma unroll
        for (int l = 0; l < 8; l++) {
            int f  = tid + 256 * l;
            int d  = f >> 5;
            int c4 = (f & 31) * 4;
            *(float4*)&p[d * 132 + c4] =
                *(const float4*)&stP[pbase + (size_t)d * HD + c4];
        }
    }
    __syncthreads();

    {
        const float* p = sm + RF_P;
        float acc2[4][8];
#pragma unroll
        for (int i = 0; i < 4; i++)
#pragma unroll
            for (int j = 0; j < 8; j++) acc2[i][j] = 0.f;
#pragma unroll 4
        for (int d = 0; d < 64; d++) {
            float qa[4];
#pragma unroll
            for (int i = 0; i < 4; i++) qa[i] = qs[(ty4 + i) * 65 + d];
            float4 p0 = *(const float4*)&p[d * 132 + tx * 8];
            float4 p1 = *(const float4*)&p[d * 132 + tx * 8 + 4];
#pragma unroll
            for (int i = 0; i < 4; i++) {
                acc2[i][0] += qa[i] * p0.x; acc2[i][1] += qa[i] * p0.y;
                acc2[i][2] += qa[i] * p0.z; acc2[i][3] += qa[i] * p0.w;
                acc2[i][4] += qa[i] * p1.x; acc2[i][5] += qa[i] * p1.y;
                acc2[i][6] += qa[i] * p1.z; acc2[i][7] += qa[i] * p1.w;
            }
        }
#pragma unroll
        for (int i = 0; i < 4; i++) {
            float cf = erow[ty4 + i] * ed;
#pragma unroll
            for (int j = 0; j < 8; j++) acc[i][j] += cf * acc2[i][j];
        }
    }
    __syncthreads();

#pragma unroll
    for (int i = 0; i < 4; i++) {
        float inv = 1.0f / denom_s[ty4 + i];
        float s = 0.f, s2 = 0.f;
#pragma unroll
        for (int j = 0; j < 8; j++) {
            acc[i][j] *= inv;
            s  += acc[i][j];
            s2 += acc[i][j] * acc[i][j];
        }
        psum[ty4 + i][tx] = s;
        psq [ty4 + i][tx] = s2;
    }
    __syncthreads();

    const size_t gbase = ((size_t)b * SS + s0) * PW + 4096 + h * HD;
#pragma unroll
    for (int i = 0; i < 4; i++) {
        int r = ty4 + i;
        float s = 0.f, s2 = 0.f;
#pragma unroll
        for (int pp = 0; pp < 16; pp++) { s += psum[r][pp]; s2 += psq[r][pp]; }
        float mu  = s * (1.0f / 128.0f);
        float var = s2 * (1.0f / 128.0f) - mu * mu;
        float inv = rsqrtf(var + 1e-5f);

        size_t go = gbase + (size_t)r * PW + tx * 8;
        float4 g0 = *(const float4*)&proj[go];
        float4 g1 = *(const float4*)&proj[go + 4];
        float gg[8] = {g0.x,g0.y,g0.z,g0.w,g1.x,g1.y,g1.z,g1.w};
        float o[8];
#pragma unroll
        for (int j = 0; j < 8; j++) {
            float nv = (acc[i][j] - mu) * inv;
            float gv = gg[j];
            o[j] = nv * (gv / (1.0f + expf(-gv)));
        }
        // emit pre packed as half2 pairs along K for the out-GEMM A operand
        uint4 u;
        u.x = packh2(o[0], o[1]); u.y = packh2(o[2], o[3]);
        u.z = packh2(o[4], o[5]); u.w = packh2(o[6], o[7]);
        size_t mrow = (size_t)b * SS + s0 + r;
        *(uint4*)&prep[mrow * K2O + h * (HD / 2) + tx * 4] = u;
    }
}

// ---------------- launch ---------------------------------------------------
extern "C" void kernel_launch(void* const* d_in, const int* in_sizes, int n_in,
                              void* d_out, int out_size)
{
    (void)in_sizes; (void)n_in; (void)out_size;
    const float* x  = (const float*)d_in[0];
    const float* Wq = (const float*)d_in[1];
    const float* bq = (const float*)d_in[2];
    const float* Wk = (const float*)d_in[3];
    const float* bk = (const float*)d_in[4];
    const float* Wv = (const float*)d_in[5];
    const float* bv = (const float*)d_in[6];
    const float* Wg = (const float*)d_in[7];
    const float* bg = (const float*)d_in[8];
    const float* Wo = (const float*)d_in[9];
    const float* bo = (const float*)d_in[10];
    float* out = (float*)d_out;

    float *proj, *ball, *stA, *stP, *ksA, *ksP;
    uint32_t *xp, *wallp, *wop, *prep;
    float2* rot;
    cudaGetSymbolAddress((void**)&proj,  g_proj);
    cudaGetSymbolAddress((void**)&xp,    g_xp);
    cudaGetSymbolAddress((void**)&wallp, g_wallp);
    cudaGetSymbolAddress((void**)&wop,   g_wop);
    cudaGetSymbolAddress((void**)&prep,  g_prep);
    cudaGetSymbolAddress((void**)&ball,  g_ball);
    cudaGetSymbolAddress((void**)&rot,   g_rot);
    cudaGetSymbolAddress((void**)&stA,   g_stA);
    cudaGetSymbolAddress((void**)&stP,   g_stP);
    cudaGetSymbolAddress((void**)&ksA,   g_ksA);
    cudaGetSymbolAddress((void**)&ksP,   g_ksP);

    cudaFuncSetAttribute(gemm_f16_pipe,
                         cudaFuncAttributeMaxDynamicSharedMemorySize,
                         GEMM_SMEM_BYTES);
    cudaFuncSetAttribute(chunk_state,
                         cudaFuncAttributeMaxDynamicSharedMemorySize, CSA_BYTES);
    cudaFuncSetAttribute(retention_final,
                         cudaFuncAttributeMaxDynamicSharedMemorySize, RF_BYTES);

    const float kscale = 0.125f;   // 64^-0.5 (power of two -> exact fold)
    dim3 thr(256);

    // prep: fp16 packing + bias + rotary table
    prep_x_pack<<<(MM * K2P / 4 + 255) / 256, 256>>>(x, xp);
    prep_wall_pack<<<(K2P * PW / 4 + 255) / 256, 256>>>(
        Wq, Wk, Wv, Wg, wallp, kscale);
    prep_wo_pack<<<(K2O * DD / 4 + 255) / 256, 256>>>(Wo, wop);
    prep_bias<<<(PW + 255) / 256, 256>>>(bq, bk, bv, bg, ball, kscale);
    rot_table<<<(SS * 32 + 255) / 256, 256>>>(rot);

    // fused projection q|k|v|g (fp16 m16n8k16)
    gemm_f16_pipe<<<dim3(PW / 128, MM / 128), thr, GEMM_SMEM_BYTES>>>(
        xp, wallp, ball, proj, PW, K2P);

    // chunked retention (fp32)
    chunk_state<<<dim3(NC, HH, BB), thr, CSA_BYTES>>>(proj, rot, stA, ksA);
    state_scan_par<<<dim3(8, BB * HH), thr>>>(stA, stP);
    ks_scan<<<BB * HH, 64>>>(ksA, ksP);
    retention_final<<<dim3(NC, HH, BB), thr, RF_BYTES>>>(
        proj, rot, stP, ksP, prep);

    // output GEMM (fp16 m16n8k16)
    gemm_f16_pipe<<<dim3(DD / 128, MM / 128), thr, GEMM_SMEM_BYTES>>>(
        prep, wop, bo, out, DD, K2O);
}

// round 15
// speedup vs baseline: 7.7616x; 1.1729x over previous
#include <cuda_runtime.h>
#include <cuda_fp16.h>
#include <math.h>
#include <stdint.h>

#define BB 2
#define SS 2048
#define DD 1024
#define HH 16
#define MM (BB*SS)          // 4096 rows
#define KD 64               // key dim per head
#define HD 128              // head dim per head
#define NC 32               // retention chunks per sequence
#define CH 64               // retention chunk length
#define PW 6144             // fused projection width: q|k|v|g
#define K2P (DD/2)          // 512  packed-K for projection
#define K2O (2*DD/2)        // 1024 packed-K for out-GEMM

// ---------------- scratch (device globals; no allocation allowed) ----------
__device__ float    g_proj[(size_t)MM * PW];
__device__ uint32_t g_xp[(size_t)MM * K2P];
__device__ uint32_t g_wallp[(size_t)K2P * PW];
__device__ uint32_t g_wop[(size_t)K2O * DD];
__device__ uint32_t g_prep[(size_t)MM * K2O];
__device__ float    g_ball[PW];
__device__ float2   g_rot[SS * 32];
__device__ float    g_stA[(size_t)BB * HH * NC * KD * HD];
__device__ float    g_stP[(size_t)BB * HH * NC * KD * HD];
__device__ float    g_ksA[(size_t)BB * HH * NC * KD];
__device__ float    g_ksP[(size_t)BB * HH * NC * KD];

// ---------------- helpers ---------------------------------------------------
__device__ __forceinline__ uint32_t packh2(float a, float b) {
    __half2 t = __floats2half2_rn(a, b);
    return *reinterpret_cast<uint32_t*>(&t);
}
__device__ __forceinline__ float2 unpackh2(uint32_t u) {
    __half2 h = *reinterpret_cast<__half2*>(&u);
    return __half22float2(h);
}

__device__ __forceinline__ void mma_f16(float c[4], const uint32_t a[4],
                                        const uint32_t b[2]) {
    asm volatile(
        "mma.sync.aligned.m16n8k16.row.col.f32.f16.f16.f32 "
        "{%0,%1,%2,%3}, {%4,%5,%6,%7}, {%8,%9}, {%0,%1,%2,%3};"
        : "+f"(c[0]), "+f"(c[1]), "+f"(c[2]), "+f"(c[3])
        : "r"(a[0]), "r"(a[1]), "r"(a[2]), "r"(a[3]),
          "r"(b[0]), "r"(b[1]));
}

__device__ __forceinline__ void cp_async16(void* smem_ptr, const void* gptr) {
    uint32_t saddr = (uint32_t)__cvta_generic_to_shared(smem_ptr);
    asm volatile("cp.async.cg.shared.global [%0], [%1], 16;\n"
                 :: "r"(saddr), "l"(gptr));
}
__device__ __forceinline__ void cp_commit() {
    asm volatile("cp.async.commit_group;\n");
}
__device__ __forceinline__ void cp_wait1() {
    asm volatile("cp.async.wait_group 1;\n");
}
__device__ __forceinline__ void cp_wait0() {
    asm volatile("cp.async.wait_group 0;\n");
}

// ---------------- prep passes ----------------------------------------------
__global__ void prep_x_pack(const float* __restrict__ x,
                            uint32_t* __restrict__ xp)
{
    int i = blockIdx.x * blockDim.x + threadIdx.x;
    if (i >= MM * K2P / 4) return;
    int m  = i >> 7;
    int q4 = (i & 127) * 4;
    const float* src = x + (size_t)m * DD + q4 * 2;
    float4 v0 = *(const float4*)src;
    float4 v1 = *(const float4*)(src + 4);
    uint4 u;
    u.x = packh2(v0.x, v0.y); u.y = packh2(v0.z, v0.w);
    u.z = packh2(v1.x, v1.y); u.w = packh2(v1.z, v1.w);
    *(uint4*)&xp[(size_t)m * K2P + q4] = u;
}

__global__ void prep_wall_pack(const float* __restrict__ Wq,
                               const float* __restrict__ Wk,
                               const float* __restrict__ Wv,
                               const float* __restrict__ Wg,
                               uint32_t* __restrict__ out, float kscale)
{
    int i = blockIdx.x * blockDim.x + threadIdx.x;
    if (i >= K2P * PW / 4) return;
    int k2 = i / (PW / 4);
    int n4 = (i - k2 * (PW / 4)) * 4;
    const float* src; int sc; float s = 1.0f; int ld;
    if (n4 < 1024)      { src = Wq; sc = n4;        ld = 1024; }
    else if (n4 < 2048) { src = Wk; sc = n4 - 1024; ld = 1024; s = kscale; }
    else if (n4 < 4096) { src = Wv; sc = n4 - 2048; ld = 2048; }
    else                { src = Wg; sc = n4 - 4096; ld = 2048; }
    float4 r0 = *(const float4*)&src[(size_t)(2 * k2)     * ld + sc];
    float4 r1 = *(const float4*)&src[(size_t)(2 * k2 + 1) * ld + sc];
    uint4 u;
    u.x = packh2(r0.x * s, r1.x * s); u.y = packh2(r0.y * s, r1.y * s);
    u.z = packh2(r0.z * s, r1.z * s); u.w = packh2(r0.w * s, r1.w * s);
    *(uint4*)&out[(size_t)k2 * PW + n4] = u;
}

__global__ void prep_wo_pack(const float* __restrict__ Wo,
                             uint32_t* __restrict__ out)
{
    int i = blockIdx.x * blockDim.x + threadIdx.x;
    if (i >= K2O * DD / 4) return;
    int k2 = i >> 8;
    int n4 = (i & 255) * 4;
    float4 r0 = *(const float4*)&Wo[(size_t)(2 * k2)     * DD + n4];
    float4 r1 = *(const float4*)&Wo[(size_t)(2 * k2 + 1) * DD + n4];
    uint4 u;
    u.x = packh2(r0.x, r1.x); u.y = packh2(r0.y, r1.y);
    u.z = packh2(r0.z, r1.z); u.w = packh2(r0.w, r1.w);
    *(uint4*)&out[(size_t)k2 * DD + n4] = u;
}

__global__ void prep_bias(const float* __restrict__ bq,
                          const float* __restrict__ bk,
                          const float* __restrict__ bv,
                          const float* __restrict__ bg,
                          float* __restrict__ out, float kscale)
{
    int i = blockIdx.x * blockDim.x + threadIdx.x;
    if (i >= PW) return;
    float v;
    if (i < 1024)      v = bq[i];
    else if (i < 2048) v = bk[i - 1024] * kscale;
    else if (i < 4096) v = bv[i - 2048];
    else               v = bg[i - 4096];
    out[i] = v;
}

__global__ void rot_table(float2* __restrict__ rot)
{
    int i = blockIdx.x * blockDim.x + threadIdx.x;
    if (i >= SS * 32) return;
    int s = i >> 5, p = i & 31;
    double ang = pow(10000.0, -(double)p / 31.0);
    double sd, cd;
    sincos((double)s * ang, &sd, &cd);
    rot[i] = make_float2((float)cd, (float)sd);
}

__device__ __forceinline__ float4 rot4(float4 t, int s, int c4,
                                       const float2* __restrict__ rot)
{
    int p0 = c4 >> 1;
    float2 cs0 = rot[(s << 5) + p0];
    float2 cs1 = rot[(s << 5) + p0 + 1];
    float4 o;
    o.x = t.x * cs0.x - t.y * cs0.y;
    o.y = t.y * cs0.x + t.x * cs0.y;
    o.z = t.z * cs1.x - t.w * cs1.y;
    o.w = t.w * cs1.x + t.z * cs1.y;
    return o;
}

// ---------------- cp.async 3-stage fp16 GEMM (m16n8k16) --------------------
#define ASTG (128*20)
#define BSTG (16*136)
#define GSTG2 (ASTG + BSTG)
#define GEMM_SMEM_BYTES (3 * GSTG2 * 4)

__global__ __launch_bounds__(256, 2) void gemm_f16_pipe(
    const uint32_t* __restrict__ A, const uint32_t* __restrict__ B,
    const float* __restrict__ bias, float* __restrict__ C,
    int N, int K2)
{
    extern __shared__ uint32_t dsm[];

    const int tid  = threadIdx.x;
    const int warp = tid >> 5, lane = tid & 31;
    const int wm = warp & 1, wn = warp >> 1;
    const int row0 = blockIdx.y * 128;
    const int col0 = blockIdx.x * 128;
    const int lr = lane >> 2;
    const int lc = lane & 3;

    float acc[4][4][4];
#pragma unroll
    for (int mt = 0; mt < 4; mt++)
#pragma unroll
        for (int nt = 0; nt < 4; nt++)
#pragma unroll
            for (int r = 0; r < 4; r++) acc[mt][nt][r] = 0.f;

    auto load_stage = [&](int s, int k0_2) {
        uint32_t* As = dsm + s * GSTG2;
        uint32_t* Bs = dsm + s * GSTG2 + ASTG;
#pragma unroll
        for (int l = 0; l < 2; l++) {
            int f  = tid + 256 * l;
            int r  = f >> 2;
            int c4 = (f & 3) * 4;
            cp_async16(&As[r * 20 + c4],
                       &A[(size_t)(row0 + r) * K2 + k0_2 + c4]);
        }
#pragma unroll
        for (int l = 0; l < 2; l++) {
            int f  = tid + 256 * l;
            int r  = f >> 5;
            int c4 = (f & 31) * 4;
            cp_async16(&Bs[r * 136 + c4],
                       &B[(size_t)(k0_2 + r) * N + col0 + c4]);
        }
        cp_commit();
    };

    load_stage(0, 0);
    load_stage(1, 16);

    int s = 0;
    for (int k0 = 0; k0 < K2; k0 += 16) {
        if (k0 + 16 < K2) cp_wait1(); else cp_wait0();
        __syncthreads();

        const uint32_t* As = dsm + s * GSTG2;
        const uint32_t* Bs = dsm + s * GSTG2 + ASTG;

#pragma unroll
        for (int ks = 0; ks < 2; ks++) {
            const int kb = ks * 8;
            uint32_t afr[4][4];
#pragma unroll
            for (int mt = 0; mt < 4; mt++) {
                int mrow = wm * 64 + mt * 16 + lr;
                afr[mt][0] = As[(mrow    ) * 20 + kb + lc];
                afr[mt][1] = As[(mrow + 8) * 20 + kb + lc];
                afr[mt][2] = As[(mrow    ) * 20 + kb + 4 + lc];
                afr[mt][3] = As[(mrow + 8) * 20 + kb + 4 + lc];
            }
            uint32_t bfr[4][2];
#pragma unroll
            for (int nt = 0; nt < 4; nt++) {
                int ncol = wn * 32 + nt * 8 + lr;
                bfr[nt][0] = Bs[(kb + lc    ) * 136 + ncol];
                bfr[nt][1] = Bs[(kb + 4 + lc) * 136 + ncol];
            }
#pragma unroll
            for (int mt = 0; mt < 4; mt++)
#pragma unroll
                for (int nt = 0; nt < 4; nt++)
                    mma_f16(acc[mt][nt], afr[mt], bfr[nt]);
        }

        int kn = k0 + 32;
        if (kn < K2) load_stage((s + 2) % 3, kn);
        s = (s + 1) % 3;
    }

#pragma unroll
    for (int mt = 0; mt < 4; mt++) {
        int r0 = row0 + wm * 64 + mt * 16 + lr;
        int r1 = r0 + 8;
#pragma unroll
        for (int nt = 0; nt < 4; nt++) {
            int c = col0 + wn * 32 + nt * 8 + 2 * lc;
            float b0 = bias[c], b1 = bias[c + 1];
            float2 o0 = { acc[mt][nt][0] + b0, acc[mt][nt][1] + b1 };
            float2 o1 = { acc[mt][nt][2] + b0, acc[mt][nt][3] + b1 };
            *(float2*)&C[(size_t)r0 * N + c] = o0;
            *(float2*)&C[(size_t)r1 * N + c] = o1;
        }
    }
}

// ---------------- retention: pass A (chunk states, SIMT fp32) ---------------
#define CSA_KW   0
#define CSA_VS   (64*65)
#define CSA_BYTES ((64*65 + 64*132) * 4)

__global__ __launch_bounds__(256, 2) void chunk_state(
    const float* __restrict__ proj, const float2* __restrict__ rot,
    float* __restrict__ stA, float* __restrict__ ksA)
{
    extern __shared__ float sm[];
    float* kw  = sm + CSA_KW;
    float* vsm = sm + CSA_VS;
    __shared__ float wsh[64];

    const int c = blockIdx.x, h = blockIdx.y, b = blockIdx.z;
    const int tid = threadIdx.x;
    const int tx = tid & 15, ty = tid >> 4;
    const float decay = log1pf(-exp2f(-5.0f - (float)h));

    if (tid < 64) wsh[tid] = expf(decay * (float)(63 - tid));
    __syncthreads();

    {
        const size_t kbase = ((size_t)b * SS + c * CH) * PW + 1024 + h * KD;
#pragma unroll
        for (int l = 0; l < 4; l++) {
            int i  = tid + 256 * l;
            int r  = i >> 4;
            int c4 = (i & 15) * 4;
            float4 t4 = *(const float4*)&proj[kbase + (size_t)r * PW + c4];
            t4 = rot4(t4, c * CH + r, c4, rot);
            float w = wsh[r];
            kw[r * 65 + c4 + 0] = t4.x * w;
            kw[r * 65 + c4 + 1] = t4.y * w;
            kw[r * 65 + c4 + 2] = t4.z * w;
            kw[r * 65 + c4 + 3] = t4.w * w;
        }
        const size_t vbase = ((size_t)b * SS + c * CH) * PW + 2048 + h * HD;
#pragma unroll
        for (int l = 0; l < 8; l++) {
            int i  = tid + 256 * l;
            int r  = i >> 5;
            int c4 = (i & 31) * 4;
            *(float4*)&vsm[r * 132 + c4] =
                *(const float4*)&proj[vbase + (size_t)r * PW + c4];
        }
    }
    __syncthreads();

    float acc[4][8];
#pragma unroll
    for (int i = 0; i < 4; i++)
#pragma unroll
        for (int j = 0; j < 8; j++) acc[i][j] = 0.f;

#pragma unroll 4
    for (int t = 0; t < 64; t++) {
        float a[4];
#pragma unroll
        for (int i = 0; i < 4; i++) a[i] = kw[t * 65 + ty * 4 + i];
        float4 v0 = *(float4*)&vsm[t * 132 + tx * 8];
        float4 v1 = *(float4*)&vsm[t * 132 + tx * 8 + 4];
#pragma unroll
        for (int i = 0; i < 4; i++) {
            acc[i][0] += a[i] * v0.x; acc[i][1] += a[i] * v0.y;
            acc[i][2] += a[i] * v0.z; acc[i][3] += a[i] * v0.w;
            acc[i][4] += a[i] * v1.x; acc[i][5] += a[i] * v1.y;
            acc[i][6] += a[i] * v1.z; acc[i][7] += a[i] * v1.w;
        }
    }

    const size_t abase = (((size_t)(b * HH + h)) * NC + c) * (KD * HD);
#pragma unroll
    for (int i = 0; i < 4; i++) {
        int kd = ty * 4 + i;
        float4 o0 = {acc[i][0], acc[i][1], acc[i][2], acc[i][3]};
        float4 o1 = {acc[i][4], acc[i][5], acc[i][6], acc[i][7]};
        *(float4*)&stA[abase + (size_t)kd * HD + tx * 8]     = o0;
        *(float4*)&stA[abase + (size_t)kd * HD + tx * 8 + 4] = o1;
    }
    if (tid < 64) {
        float s = 0.f;
#pragma unroll 8
        for (int t = 0; t < 64; t++) s += kw[t * 65 + tid];
        ksA[(((size_t)(b * HH + h)) * NC + c) * KD + tid] = s;
    }
}

// ---------------- retention: pass B (parallel prefix scans) ------------------
__global__ __launch_bounds__(256) void state_scan_par(
    const float* __restrict__ stA, float* __restrict__ stP)
{
    const int bh = blockIdx.y;
    const int h  = bh & (HH - 1);
    const float decay = log1pf(-exp2f(-5.0f - (float)h));
    const float lam   = expf(decay * (float)CH);

    const size_t base4 = (size_t)bh * NC * (KD * HD / 4);
    const int idx4 = blockIdx.x * 256 + threadIdx.x;
    const float4* A4 = (const float4*)stA;
    float4* P4 = (float4*)stP;

    float4 st = make_float4(0.f, 0.f, 0.f, 0.f);
    for (int c = 0; c < NC; c++) {
        size_t id = base4 + (size_t)c * (KD * HD / 4) + idx4;
        P4[id] = st;
        float4 a = A4[id];
        st.x = lam * st.x + a.x;
        st.y = lam * st.y + a.y;
        st.z = lam * st.z + a.z;
        st.w = lam * st.w + a.w;
    }
}

__global__ void ks_scan(const float* __restrict__ ksA,
                        float* __restrict__ ksP)
{
    const int bh = blockIdx.x;
    const int h  = bh & (HH - 1);
    const int tid = threadIdx.x;
    const float decay = log1pf(-exp2f(-5.0f - (float)h));
    const float lam   = expf(decay * (float)CH);
    float pk = 0.f;
    const size_t kb = (size_t)bh * NC * KD + tid;
    for (int c = 0; c < NC; c++) {
        ksP[kb + (size_t)c * KD] = pk;
        pk = lam * pk + ksA[kb + (size_t)c * KD];
    }
}

// ---------------- retention: pass C — fp16-MMA version ----------------------
// smem (u32): QH 64x36 | KH 64x36 (reused for q*cf) | VH 128x36 (reused for P)
//             | SCH 64x36
#define RQH 0
#define RKH (64*36)
#define RVH (2*64*36)
#define RSCH (2*64*36 + 128*36)
#define RF2_U32 (3*64*36 + 128*36)          // 11520
#define RF2_BYTES (RF2_U32 * 4)             // 46080

__global__ __launch_bounds__(256, 2) void retention_final(
    const float* __restrict__ proj, const float2* __restrict__ rot,
    const float* __restrict__ stP, const float* __restrict__ ksP,
    uint32_t* __restrict__ prep)
{
    extern __shared__ uint32_t smu[];
    uint32_t* QH  = smu + RQH;
    uint32_t* KH  = smu + RKH;    // later holds q*cf packed
    uint32_t* VH  = smu + RVH;    // later holds P^T packed
    uint32_t* SCH = smu + RSCH;

    __shared__ float erow[64];
    __shared__ float etab[64];
    __shared__ float pksh[64];
    __shared__ float denom_s[64];
    __shared__ float rowsum2[64][2];
    __shared__ float psum[64][2], psq[64][2];

    const int c = blockIdx.x, h = blockIdx.y, b = blockIdx.z;
    const int tid = threadIdx.x;
    const int warp = tid >> 5, lane = tid & 31;
    const int lr = lane >> 2, lc = lane & 3;
    const int mt = warp & 3;          // 16-row tile
    const int wn = warp >> 2;         // half (scores: 32 cols; AV: 64 cols)
    const int s0 = c * CH;
    const float decay = log1pf(-exp2f(-5.0f - (float)h));
    const float ed = expf(decay);

    // ---- stage q/k rotated + packed (half2 along d) ----
    {
        const size_t qbase = ((size_t)b * SS + s0) * PW + h * KD;
#pragma unroll
        for (int l = 0; l < 4; l++) {
            int i  = tid + 256 * l;       // 0..1023 float4 units
            int r  = i >> 4;
            int c4 = (i & 15) * 4;
            float4 t4 = *(const float4*)&proj[qbase + (size_t)r * PW + c4];
            t4 = rot4(t4, s0 + r, c4, rot);
            QH[r * 36 + (c4 >> 1)]     = packh2(t4.x, t4.y);
            QH[r * 36 + (c4 >> 1) + 1] = packh2(t4.z, t4.w);
            float4 k4 = *(const float4*)&proj[qbase + 1024 + (size_t)r * PW + c4];
            k4 = rot4(k4, s0 + r, c4, rot);
            KH[r * 36 + (c4 >> 1)]     = packh2(k4.x, k4.y);
            KH[r * 36 + (c4 >> 1) + 1] = packh2(k4.z, k4.w);
        }
        // v^T packed: VH[n][t2] = half2(v[2t2][n], v[2t2+1][n])
        const size_t vbase = ((size_t)b * SS + s0) * PW + 2048 + h * HD;
#pragma unroll
        for (int l = 0; l < 16; l++) {
            int i  = tid + 256 * l;       // 0..4095: t2*128 + n
            int t2 = i >> 7;
            int n  = i & 127;
            float v0 = proj[vbase + (size_t)(2 * t2)     * PW + n];
            float v1 = proj[vbase + (size_t)(2 * t2 + 1) * PW + n];
            VH[n * 36 + t2] = packh2(v0, v1);
        }
    }
    if (tid < 64) {
        int gs = s0 + tid;
        float rowsum = expm1f(decay * (float)(gs + 1)) / expm1f(decay);
        erow[tid] = expf(decay * (float)tid) * rsqrtf(rowsum);
        etab[tid] = expf(-decay * (float)tid);
        pksh[tid] = ksP[(((size_t)(b * HH + h)) * NC + c) * KD + tid];
    }
    __syncthreads();

    // ---- scores: S = Q K^T (fp16 MMA), mask+scale, pack, row sums ----
    {
        float accS[4][4];
#pragma unroll
        for (int nt = 0; nt < 4; nt++)
#pragma unroll
            for (int r = 0; r < 4; r++) accS[nt][r] = 0.f;

#pragma unroll
        for (int ks = 0; ks < 4; ks++) {
            const int kb = ks * 8;
            uint32_t afr[4];
            afr[0] = QH[(mt * 16 + lr)     * 36 + kb + lc];
            afr[1] = QH[(mt * 16 + 8 + lr) * 36 + kb + lc];
            afr[2] = QH[(mt * 16 + lr)     * 36 + kb + 4 + lc];
            afr[3] = QH[(mt * 16 + 8 + lr) * 36 + kb + 4 + lc];
#pragma unroll
            for (int nt = 0; nt < 4; nt++) {
                int tl = wn * 32 + nt * 8 + lr;
                uint32_t bfr[2] = { KH[tl * 36 + kb + lc],
                                    KH[tl * 36 + kb + 4 + lc] };
                mma_f16(accS[nt], afr, bfr);
            }
        }
        const int r0 = mt * 16 + lr, r1 = r0 + 8;
        const float a0 = erow[r0], a1 = erow[r1];
        float sr0 = 0.f, sr1 = 0.f;
#pragma unroll
        for (int nt = 0; nt < 4; nt++) {
            int c0 = wn * 32 + nt * 8 + 2 * lc;
            float e0 = etab[c0], e1 = etab[c0 + 1];
            float m00 = (c0     <= r0) ? accS[nt][0] * a0 * e0 : 0.f;
            float m01 = (c0 + 1 <= r0) ? accS[nt][1] * a0 * e1 : 0.f;
            float m10 = (c0     <= r1) ? accS[nt][2] * a1 * e0 : 0.f;
            float m11 = (c0 + 1 <= r1) ? accS[nt][3] * a1 * e1 : 0.f;
            SCH[r0 * 36 + (c0 >> 1)] = packh2(m00, m01);
            SCH[r1 * 36 + (c0 >> 1)] = packh2(m10, m11);
            sr0 += m00 + m01;
            sr1 += m10 + m11;
        }
        sr0 += __shfl_xor_sync(0xffffffff, sr0, 1);
        sr0 += __shfl_xor_sync(0xffffffff, sr0, 2);
        sr1 += __shfl_xor_sync(0xffffffff, sr1, 1);
        sr1 += __shfl_xor_sync(0xffffffff, sr1, 2);
        if (lc == 0) { rowsum2[r0][wn] = sr0; rowsum2[r1][wn] = sr1; }
    }
    __syncthreads();

    // ---- denominators (fp32; q from fp16 unpack, consistent w/ scores) ----
    if (tid < 64) {
        float dk = 0.f;
#pragma unroll 8
        for (int d2 = 0; d2 < 32; d2++) {
            float2 qv = unpackh2(QH[tid * 36 + d2]);
            dk += qv.x * pksh[2 * d2] + qv.y * pksh[2 * d2 + 1];
        }
        float tot = rowsum2[tid][0] + rowsum2[tid][1] + erow[tid] * ed * dk;
        denom_s[tid] = fmaxf(fabsf(tot), 1.0f);
    }

    // ---- AV: O = S_masked @ V (fp16 MMA); warp covers 64 cols (wn half) ----
    float acc[8][4];
#pragma unroll
    for (int nt = 0; nt < 8; nt++)
#pragma unroll
        for (int r = 0; r < 4; r++) acc[nt][r] = 0.f;

#pragma unroll
    for (int ks = 0; ks < 4; ks++) {
        const int kb = ks * 8;
        uint32_t afr[4];
        afr[0] = SCH[(mt * 16 + lr)     * 36 + kb + lc];
        afr[1] = SCH[(mt * 16 + 8 + lr) * 36 + kb + lc];
        afr[2] = SCH[(mt * 16 + lr)     * 36 + kb + 4 + lc];
        afr[3] = SCH[(mt * 16 + 8 + lr) * 36 + kb + 4 + lc];
#pragma unroll
        for (int nt = 0; nt < 8; nt++) {
            int ncol = wn * 64 + nt * 8 + lr;
            uint32_t bfr[2] = { VH[ncol * 36 + kb + lc],
                                VH[ncol * 36 + kb + 4 + lc] };
            mma_f16(acc[nt], afr, bfr);
        }
    }
    __syncthreads();   // VH/KH free now

    // ---- stage q*cf over KH, P^T packed over VH ----
    {
#pragma unroll
        for (int l = 0; l < 8; l++) {
            int i  = tid + 256 * l;       // 0..2047: r*32 + d2
            int r  = i >> 5;
            int d2 = i & 31;
            float2 qv = unpackh2(QH[r * 36 + d2]);
            float cf = erow[r] * ed;
            KH[r * 36 + d2] = packh2(qv.x * cf, qv.y * cf);
        }
        const size_t pbase = (((size_t)(b * HH + h)) * NC + c) * (KD * HD);
#pragma unroll
        for (int l = 0; l < 16; l++) {
            int i  = tid + 256 * l;       // 0..4095: d2*128 + n
            int d2 = i >> 7;
            int n  = i & 127;
            float p0 = stP[pbase + (size_t)(2 * d2)     * HD + n];
            float p1 = stP[pbase + (size_t)(2 * d2 + 1) * HD + n];
            VH[n * 36 + d2] = packh2(p0, p1);
        }
    }
    __syncthreads();

    // ---- cross: O += (q*cf) @ P (fp16 MMA, accumulate into acc) ----
#pragma unroll
    for (int ks = 0; ks < 4; ks++) {
        const int kb = ks * 8;
        uint32_t afr[4];
        afr[0] = KH[(mt * 16 + lr)     * 36 + kb + lc];
        afr[1] = KH[(mt * 16 + 8 + lr) * 36 + kb + lc];
        afr[2] = KH[(mt * 16 + lr)     * 36 + kb + 4 + lc];
        afr[3] = KH[(mt * 16 + 8 + lr) * 36 + kb + 4 + lc];
#pragma unroll
        for (int nt = 0; nt < 8; nt++) {
            int ncol = wn * 64 + nt * 8 + lr;
            uint32_t bfr[2] = { VH[ncol * 36 + kb + lc],
                                VH[ncol * 36 + kb + 4 + lc] };
            mma_f16(acc[nt], afr, bfr);
        }
    }

    // ---- epilogue: /denom, LN (128 cols), SiLU gate, pack pre --------------
    const int r0 = mt * 16 + lr, r1 = r0 + 8;
    {
        const float inv0 = 1.0f / denom_s[r0];
        const float inv1 = 1.0f / denom_s[r1];
        float s0 = 0.f, q0 = 0.f, s1 = 0.f, q1 = 0.f;
#pragma unroll
        for (int nt = 0; nt < 8; nt++) {
            acc[nt][0] *= inv0; acc[nt][1] *= inv0;
            acc[nt][2] *= inv1; acc[nt][3] *= inv1;
            s0 += acc[nt][0] + acc[nt][1];
            q0 += acc[nt][0] * acc[nt][0] + acc[nt][1] * acc[nt][1];
            s1 += acc[nt][2] + acc[nt][3];
            q1 += acc[nt][2] * acc[nt][2] + acc[nt][3] * acc[nt][3];
        }
#pragma unroll
        for (int m_ = 1; m_ <= 2; m_ <<= 1) {
            s0 += __shfl_xor_sync(0xffffffff, s0, m_);
            q0 += __shfl_xor_sync(0xffffffff, q0, m_);
            s1 += __shfl_xor_sync(0xffffffff, s1, m_);
            q1 += __shfl_xor_sync(0xffffffff, q1, m_);
        }
        if (lc == 0) {
            psum[r0][wn] = s0; psq[r0][wn] = q0;
            psum[r1][wn] = s1; psq[r1][wn] = q1;
        }
    }
    __syncthreads();

    float mu0, is0, mu1, is1;
    {
        float S = psum[r0][0] + psum[r0][1];
        float Q = psq[r0][0] + psq[r0][1];
        mu0 = S * (1.0f / 128.0f);
        is0 = rsqrtf(Q * (1.0f / 128.0f) - mu0 * mu0 + 1e-5f);
        S = psum[r1][0] + psum[r1][1];
        Q = psq[r1][0] + psq[r1][1];
        mu1 = S * (1.0f / 128.0f);
        is1 = rsqrtf(Q * (1.0f / 128.0f) - mu1 * mu1 + 1e-5f);
    }

    const size_t gbase = ((size_t)b * SS + s0) * PW + 4096 + h * HD;
    const size_t mrow0 = (size_t)b * SS + s0 + r0;
    const size_t mrow1 = mrow0 + 8;
#pragma unroll
    for (int nt = 0; nt < 8; nt++) {
        int c0 = wn * 64 + nt * 8 + 2 * lc;
        float2 g0 = *(const float2*)&proj[gbase + (size_t)r0 * PW + c0];
        float2 g1 = *(const float2*)&proj[gbase + (size_t)r1 * PW + c0];
        float o00 = (acc[nt][0] - mu0) * is0 * (g0.x / (1.0f + expf(-g0.x)));
        float o01 = (acc[nt][1] - mu0) * is0 * (g0.y / (1.0f + expf(-g0.y)));
        float o10 = (acc[nt][2] - mu1) * is1 * (g1.x / (1.0f + expf(-g1.x)));
        float o11 = (acc[nt][3] - mu1) * is1 * (g1.y / (1.0f + expf(-g1.y)));
        prep[mrow0 * K2O + h * (HD / 2) + (c0 >> 1)] = packh2(o00, o01);
        prep[mrow1 * K2O + h * (HD / 2) + (c0 >> 1)] = packh2(o10, o11);
    }
}

// ---------------- launch ---------------------------------------------------
extern "C" void kernel_launch(void* const* d_in, const int* in_sizes, int n_in,
                              void* d_out, int out_size)
{
    (void)in_sizes; (void)n_in; (void)out_size;
    const float* x  = (const float*)d_in[0];
    const float* Wq = (const float*)d_in[1];
    const float* bq = (const float*)d_in[2];
    const float* Wk = (const float*)d_in[3];
    const float* bk = (const float*)d_in[4];
    const float* Wv = (const float*)d_in[5];
    const float* bv = (const float*)d_in[6];
    const float* Wg = (const float*)d_in[7];
    const float* bg = (const float*)d_in[8];
    const float* Wo = (const float*)d_in[9];
    const float* bo = (const float*)d_in[10];
    float* out = (float*)d_out;

    float *proj, *ball, *stA, *stP, *ksA, *ksP;
    uint32_t *xp, *wallp, *wop, *prep;
    float2* rot;
    cudaGetSymbolAddress((void**)&proj,  g_proj);
    cudaGetSymbolAddress((void**)&xp,    g_xp);
    cudaGetSymbolAddress((void**)&wallp, g_wallp);
    cudaGetSymbolAddress((void**)&wop,   g_wop);
    cudaGetSymbolAddress((void**)&prep,  g_prep);
    cudaGetSymbolAddress((void**)&ball,  g_ball);
    cudaGetSymbolAddress((void**)&rot,   g_rot);
    cudaGetSymbolAddress((void**)&stA,   g_stA);
    cudaGetSymbolAddress((void**)&stP,   g_stP);
    cudaGetSymbolAddress((void**)&ksA,   g_ksA);
    cudaGetSymbolAddress((void**)&ksP,   g_ksP);

    cudaFuncSetAttribute(gemm_f16_pipe,
                         cudaFuncAttributeMaxDynamicSharedMemorySize,
                         GEMM_SMEM_BYTES);
    cudaFuncSetAttribute(chunk_state,
                         cudaFuncAttributeMaxDynamicSharedMemorySize, CSA_BYTES);
    cudaFuncSetAttribute(retention_final,
                         cudaFuncAttributeMaxDynamicSharedMemorySize, RF2_BYTES);

    const float kscale = 0.125f;   // 64^-0.5 (power of two -> exact fold)
    dim3 thr(256);

    prep_x_pack<<<(MM * K2P / 4 + 255) / 256, 256>>>(x, xp);
    prep_wall_pack<<<(K2P * PW / 4 + 255) / 256, 256>>>(
        Wq, Wk, Wv, Wg, wallp, kscale);
    prep_wo_pack<<<(K2O * DD / 4 + 255) / 256, 256>>>(Wo, wop);
    prep_bias<<<(PW + 255) / 256, 256>>>(bq, bk, bv, bg, ball, kscale);
    rot_table<<<(SS * 32 + 255) / 256, 256>>>(rot);

    gemm_f16_pipe<<<dim3(PW / 128, MM / 128), thr, GEMM_SMEM_BYTES>>>(
        xp, wallp, ball, proj, PW, K2P);

    chunk_state<<<dim3(NC, HH, BB), thr, CSA_BYTES>>>(proj, rot, stA, ksA);
    state_scan_par<<<dim3(8, BB * HH), thr>>>(stA, stP);
    ks_scan<<<BB * HH, 64>>>(ksA, ksP);
    retention_final<<<dim3(NC, HH, BB), thr, RF2_BYTES>>>(
        proj, rot, stP, ksP, prep);

    gemm_f16_pipe<<<dim3(DD / 128, MM / 128), thr, GEMM_SMEM_BYTES>>>(
        prep, wop, bo, out, DD, K2O);
}

// round 16
// speedup vs baseline: 8.5445x; 1.1009x over previous
#include <cuda_runtime.h>
#include <cuda_fp16.h>
#include <math.h>
#include <stdint.h>

#define BB 2
#define SS 2048
#define DD 1024
#define HH 16
#define MM (BB*SS)          // 4096 rows
#define KD 64               // key dim per head
#define HD 128              // head dim per head
#define NC 32               // retention chunks per sequence
#define CH 64               // retention chunk length
#define PW 6144             // fused projection width: q|k|v|g
#define K2P (DD/2)          // 512  packed-K for projection
#define K2O (2*DD/2)        // 1024 packed-K for out-GEMM

// ---------------- scratch (device globals; no allocation allowed) ----------
__device__ float    g_proj[(size_t)MM * PW];
__device__ uint32_t g_xp[(size_t)MM * K2P];
__device__ uint32_t g_wallp[(size_t)K2P * PW];
__device__ uint32_t g_wop[(size_t)K2O * DD];
__device__ uint32_t g_prep[(size_t)MM * K2O];
__device__ float    g_ball[PW];
__device__ float2   g_rot[SS * 32];
__device__ float    g_stA[(size_t)BB * HH * NC * KD * HD];
__device__ float    g_stP[(size_t)BB * HH * NC * KD * HD];
__device__ float    g_ksA[(size_t)BB * HH * NC * KD];
__device__ float    g_ksP[(size_t)BB * HH * NC * KD];

// ---------------- helpers ---------------------------------------------------
__device__ __forceinline__ uint32_t packh2(float a, float b) {
    __half2 t = __floats2half2_rn(a, b);
    return *reinterpret_cast<uint32_t*>(&t);
}
__device__ __forceinline__ float2 unpackh2(uint32_t u) {
    __half2 h = *reinterpret_cast<__half2*>(&u);
    return __half22float2(h);
}

__device__ __forceinline__ void mma_f16(float c[4], const uint32_t a[4],
                                        const uint32_t b[2]) {
    asm volatile(
        "mma.sync.aligned.m16n8k16.row.col.f32.f16.f16.f32 "
        "{%0,%1,%2,%3}, {%4,%5,%6,%7}, {%8,%9}, {%0,%1,%2,%3};"
        : "+f"(c[0]), "+f"(c[1]), "+f"(c[2]), "+f"(c[3])
        : "r"(a[0]), "r"(a[1]), "r"(a[2]), "r"(a[3]),
          "r"(b[0]), "r"(b[1]));
}

__device__ __forceinline__ void cp_async16(void* smem_ptr, const void* gptr) {
    uint32_t saddr = (uint32_t)__cvta_generic_to_shared(smem_ptr);
    asm volatile("cp.async.cg.shared.global [%0], [%1], 16;\n"
                 :: "r"(saddr), "l"(gptr));
}
__device__ __forceinline__ void cp_commit() {
    asm volatile("cp.async.commit_group;\n");
}
__device__ __forceinline__ void cp_wait1() {
    asm volatile("cp.async.wait_group 1;\n");
}
__device__ __forceinline__ void cp_wait0() {
    asm volatile("cp.async.wait_group 0;\n");
}

// ---------------- prep passes ----------------------------------------------
__global__ void prep_x_pack(const float* __restrict__ x,
                            uint32_t* __restrict__ xp)
{
    int i = blockIdx.x * blockDim.x + threadIdx.x;
    if (i >= MM * K2P / 4) return;
    int m  = i >> 7;
    int q4 = (i & 127) * 4;
    const float* src = x + (size_t)m * DD + q4 * 2;
    float4 v0 = *(const float4*)src;
    float4 v1 = *(const float4*)(src + 4);
    uint4 u;
    u.x = packh2(v0.x, v0.y); u.y = packh2(v0.z, v0.w);
    u.z = packh2(v1.x, v1.y); u.w = packh2(v1.z, v1.w);
    *(uint4*)&xp[(size_t)m * K2P + q4] = u;
}

__global__ void prep_wall_pack(const float* __restrict__ Wq,
                               const float* __restrict__ Wk,
                               const float* __restrict__ Wv,
                               const float* __restrict__ Wg,
                               uint32_t* __restrict__ out, float kscale)
{
    int i = blockIdx.x * blockDim.x + threadIdx.x;
    if (i >= K2P * PW / 4) return;
    int k2 = i / (PW / 4);
    int n4 = (i - k2 * (PW / 4)) * 4;
    const float* src; int sc; float s = 1.0f; int ld;
    if (n4 < 1024)      { src = Wq; sc = n4;        ld = 1024; }
    else if (n4 < 2048) { src = Wk; sc = n4 - 1024; ld = 1024; s = kscale; }
    else if (n4 < 4096) { src = Wv; sc = n4 - 2048; ld = 2048; }
    else                { src = Wg; sc = n4 - 4096; ld = 2048; }
    float4 r0 = *(const float4*)&src[(size_t)(2 * k2)     * ld + sc];
    float4 r1 = *(const float4*)&src[(size_t)(2 * k2 + 1) * ld + sc];
    uint4 u;
    u.x = packh2(r0.x * s, r1.x * s); u.y = packh2(r0.y * s, r1.y * s);
    u.z = packh2(r0.z * s, r1.z * s); u.w = packh2(r0.w * s, r1.w * s);
    *(uint4*)&out[(size_t)k2 * PW + n4] = u;
}

__global__ void prep_wo_pack(const float* __restrict__ Wo,
                             uint32_t* __restrict__ out)
{
    int i = blockIdx.x * blockDim.x + threadIdx.x;
    if (i >= K2O * DD / 4) return;
    int k2 = i >> 8;
    int n4 = (i & 255) * 4;
    float4 r0 = *(const float4*)&Wo[(size_t)(2 * k2)     * DD + n4];
    float4 r1 = *(const float4*)&Wo[(size_t)(2 * k2 + 1) * DD + n4];
    uint4 u;
    u.x = packh2(r0.x, r1.x); u.y = packh2(r0.y, r1.y);
    u.z = packh2(r0.z, r1.z); u.w = packh2(r0.w, r1.w);
    *(uint4*)&out[(size_t)k2 * DD + n4] = u;
}

__global__ void prep_bias(const float* __restrict__ bq,
                          const float* __restrict__ bk,
                          const float* __restrict__ bv,
                          const float* __restrict__ bg,
                          float* __restrict__ out, float kscale)
{
    int i = blockIdx.x * blockDim.x + threadIdx.x;
    if (i >= PW) return;
    float v;
    if (i < 1024)      v = bq[i];
    else if (i < 2048) v = bk[i - 1024] * kscale;
    else if (i < 4096) v = bv[i - 2048];
    else               v = bg[i - 4096];
    out[i] = v;
}

__global__ void rot_table(float2* __restrict__ rot)
{
    int i = blockIdx.x * blockDim.x + threadIdx.x;
    if (i >= SS * 32) return;
    int s = i >> 5, p = i & 31;
    double ang = pow(10000.0, -(double)p / 31.0);
    double sd, cd;
    sincos((double)s * ang, &sd, &cd);
    rot[i] = make_float2((float)cd, (float)sd);
}

__device__ __forceinline__ float4 rot4(float4 t, int s, int c4,
                                       const float2* __restrict__ rot)
{
    int p0 = c4 >> 1;
    float2 cs0 = rot[(s << 5) + p0];
    float2 cs1 = rot[(s << 5) + p0 + 1];
    float4 o;
    o.x = t.x * cs0.x - t.y * cs0.y;
    o.y = t.y * cs0.x + t.x * cs0.y;
    o.z = t.z * cs1.x - t.w * cs1.y;
    o.w = t.w * cs1.x + t.z * cs1.y;
    return o;
}

// ---------------- cp.async 3-stage fp16 GEMM (m16n8k16) --------------------
#define ASTG (128*20)
#define BSTG (16*136)
#define GSTG2 (ASTG + BSTG)
#define GEMM_SMEM_BYTES (3 * GSTG2 * 4)

__global__ __launch_bounds__(256, 2) void gemm_f16_pipe(
    const uint32_t* __restrict__ A, const uint32_t* __restrict__ B,
    const float* __restrict__ bias, float* __restrict__ C,
    int N, int K2)
{
    extern __shared__ uint32_t dsm[];

    const int tid  = threadIdx.x;
    const int warp = tid >> 5, lane = tid & 31;
    const int wm = warp & 1, wn = warp >> 1;
    const int row0 = blockIdx.y * 128;
    const int col0 = blockIdx.x * 128;
    const int lr = lane >> 2;
    const int lc = lane & 3;

    float acc[4][4][4];
#pragma unroll
    for (int mt = 0; mt < 4; mt++)
#pragma unroll
        for (int nt = 0; nt < 4; nt++)
#pragma unroll
            for (int r = 0; r < 4; r++) acc[mt][nt][r] = 0.f;

    auto load_stage = [&](int s, int k0_2) {
        uint32_t* As = dsm + s * GSTG2;
        uint32_t* Bs = dsm + s * GSTG2 + ASTG;
#pragma unroll
        for (int l = 0; l < 2; l++) {
            int f  = tid + 256 * l;
            int r  = f >> 2;
            int c4 = (f & 3) * 4;
            cp_async16(&As[r * 20 + c4],
                       &A[(size_t)(row0 + r) * K2 + k0_2 + c4]);
        }
#pragma unroll
        for (int l = 0; l < 2; l++) {
            int f  = tid + 256 * l;
            int r  = f >> 5;
            int c4 = (f & 31) * 4;
            cp_async16(&Bs[r * 136 + c4],
                       &B[(size_t)(k0_2 + r) * N + col0 + c4]);
        }
        cp_commit();
    };

    load_stage(0, 0);
    load_stage(1, 16);

    int s = 0;
    for (int k0 = 0; k0 < K2; k0 += 16) {
        if (k0 + 16 < K2) cp_wait1(); else cp_wait0();
        __syncthreads();

        const uint32_t* As = dsm + s * GSTG2;
        const uint32_t* Bs = dsm + s * GSTG2 + ASTG;

#pragma unroll
        for (int ks = 0; ks < 2; ks++) {
            const int kb = ks * 8;
            uint32_t afr[4][4];
#pragma unroll
            for (int mt = 0; mt < 4; mt++) {
                int mrow = wm * 64 + mt * 16 + lr;
                afr[mt][0] = As[(mrow    ) * 20 + kb + lc];
                afr[mt][1] = As[(mrow + 8) * 20 + kb + lc];
                afr[mt][2] = As[(mrow    ) * 20 + kb + 4 + lc];
                afr[mt][3] = As[(mrow + 8) * 20 + kb + 4 + lc];
            }
            uint32_t bfr[4][2];
#pragma unroll
            for (int nt = 0; nt < 4; nt++) {
                int ncol = wn * 32 + nt * 8 + lr;
                bfr[nt][0] = Bs[(kb + lc    ) * 136 + ncol];
                bfr[nt][1] = Bs[(kb + 4 + lc) * 136 + ncol];
            }
#pragma unroll
            for (int mt = 0; mt < 4; mt++)
#pragma unroll
                for (int nt = 0; nt < 4; nt++)
                    mma_f16(acc[mt][nt], afr[mt], bfr[nt]);
        }

        int kn = k0 + 32;
        if (kn < K2) load_stage((s + 2) % 3, kn);
        s = (s + 1) % 3;
    }

#pragma unroll
    for (int mt = 0; mt < 4; mt++) {
        int r0 = row0 + wm * 64 + mt * 16 + lr;
        int r1 = r0 + 8;
#pragma unroll
        for (int nt = 0; nt < 4; nt++) {
            int c = col0 + wn * 32 + nt * 8 + 2 * lc;
            float b0 = bias[c], b1 = bias[c + 1];
            float2 o0 = { acc[mt][nt][0] + b0, acc[mt][nt][1] + b1 };
            float2 o1 = { acc[mt][nt][2] + b0, acc[mt][nt][3] + b1 };
            *(float2*)&C[(size_t)r0 * N + c] = o0;
            *(float2*)&C[(size_t)r1 * N + c] = o1;
        }
    }
}

// ---------------- retention: pass A (chunk states, fp16 MMA) ----------------
// A_c[kd][hd] = sum_t kw[t][kd] * v[t][hd]; M=64(kd), N=128(hd), K=64(t).
// smem: kw fp32 [64][65] | KWH u32 [64*36] (kw^T packed along t)
//       | VH u32 [128*36] (v^T packed along t)
#define CS_KW  0                               // floats
#define CS_KWH (64*65)                         // u32 units from base
#define CS_VH  (64*65 + 64*36)
#define CS_U32 (64*65 + 64*36 + 128*36)        // 11072
#define CS_BYTES (CS_U32 * 4)                  // 44288

__global__ __launch_bounds__(256, 2) void chunk_state(
    const float* __restrict__ proj, const float2* __restrict__ rot,
    float* __restrict__ stA, float* __restrict__ ksA)
{
    extern __shared__ uint32_t smu[];
    float*    kw  = (float*)(smu + CS_KW);
    uint32_t* KWH = smu + CS_KWH;
    uint32_t* VH  = smu + CS_VH;
    __shared__ float wsh[64];

    const int c = blockIdx.x, h = blockIdx.y, b = blockIdx.z;
    const int tid = threadIdx.x;
    const int warp = tid >> 5, lane = tid & 31;
    const int lr = lane >> 2, lc = lane & 3;
    const int mt = warp & 3, wn = warp >> 2;
    const float decay = log1pf(-exp2f(-5.0f - (float)h));

    if (tid < 64) wsh[tid] = expf(decay * (float)(63 - tid));
    __syncthreads();

    // stage kw (rotated + weighted, fp32) and v^T packed
    {
        const size_t kbase = ((size_t)b * SS + c * CH) * PW + 1024 + h * KD;
#pragma unroll
        for (int l = 0; l < 4; l++) {
            int i  = tid + 256 * l;
            int r  = i >> 4;
            int c4 = (i & 15) * 4;
            float4 t4 = *(const float4*)&proj[kbase + (size_t)r * PW + c4];
            t4 = rot4(t4, c * CH + r, c4, rot);
            float w = wsh[r];
            kw[r * 65 + c4 + 0] = t4.x * w;
            kw[r * 65 + c4 + 1] = t4.y * w;
            kw[r * 65 + c4 + 2] = t4.z * w;
            kw[r * 65 + c4 + 3] = t4.w * w;
        }
        const size_t vbase = ((size_t)b * SS + c * CH) * PW + 2048 + h * HD;
#pragma unroll
        for (int l = 0; l < 16; l++) {
            int i  = tid + 256 * l;       // 0..4095: t2*128 + n
            int t2 = i >> 7;
            int n  = i & 127;
            float v0 = proj[vbase + (size_t)(2 * t2)     * PW + n];
            float v1 = proj[vbase + (size_t)(2 * t2 + 1) * PW + n];
            VH[n * 36 + t2] = packh2(v0, v1);
        }
    }
    __syncthreads();

    // repack kw^T along t; ksA from fp32 kw
    {
#pragma unroll
        for (int l = 0; l < 8; l++) {
            int i  = tid + 256 * l;       // 0..2047: kd*32 + t2
            int kd = i >> 5;
            int t2 = i & 31;
            KWH[kd * 36 + t2] = packh2(kw[(2 * t2) * 65 + kd],
                                       kw[(2 * t2 + 1) * 65 + kd]);
        }
        if (tid < 64) {
            float s = 0.f;
#pragma unroll 8
            for (int t = 0; t < 64; t++) s += kw[t * 65 + tid];
            ksA[(((size_t)(b * HH + h)) * NC + c) * KD + tid] = s;
        }
    }
    __syncthreads();

    // MMA: acc over 16 kd-rows (mt) x 64 hd-cols (wn)
    float acc[8][4];
#pragma unroll
    for (int nt = 0; nt < 8; nt++)
#pragma unroll
        for (int r = 0; r < 4; r++) acc[nt][r] = 0.f;

#pragma unroll
    for (int ks = 0; ks < 4; ks++) {
        const int kb = ks * 8;
        uint32_t afr[4];
        afr[0] = KWH[(mt * 16 + lr)     * 36 + kb + lc];
        afr[1] = KWH[(mt * 16 + 8 + lr) * 36 + kb + lc];
        afr[2] = KWH[(mt * 16 + lr)     * 36 + kb + 4 + lc];
        afr[3] = KWH[(mt * 16 + 8 + lr) * 36 + kb + 4 + lc];
#pragma unroll
        for (int nt = 0; nt < 8; nt++) {
            int ncol = wn * 64 + nt * 8 + lr;
            uint32_t bfr[2] = { VH[ncol * 36 + kb + lc],
                                VH[ncol * 36 + kb + 4 + lc] };
            mma_f16(acc[nt], afr, bfr);
        }
    }

    const size_t abase = (((size_t)(b * HH + h)) * NC + c) * (KD * HD);
    const int r0 = mt * 16 + lr, r1 = r0 + 8;
#pragma unroll
    for (int nt = 0; nt < 8; nt++) {
        int c0 = wn * 64 + nt * 8 + 2 * lc;
        float2 o0 = { acc[nt][0], acc[nt][1] };
        float2 o1 = { acc[nt][2], acc[nt][3] };
        *(float2*)&stA[abase + (size_t)r0 * HD + c0] = o0;
        *(float2*)&stA[abase + (size_t)r1 * HD + c0] = o1;
    }
}

// ---------------- retention: pass B (prefix scans; ks fused) ----------------
__global__ __launch_bounds__(256) void state_scan_par(
    const float* __restrict__ stA, float* __restrict__ stP,
    const float* __restrict__ ksA, float* __restrict__ ksP)
{
    const int bh = blockIdx.y;
    const int h  = bh & (HH - 1);
    const float decay = log1pf(-exp2f(-5.0f - (float)h));
    const float lam   = expf(decay * (float)CH);
    const int tid = threadIdx.x;

    const size_t base4 = (size_t)bh * NC * (KD * HD / 4);
    const int idx4 = blockIdx.x * 256 + tid;
    const float4* A4 = (const float4*)stA;
    float4* P4 = (float4*)stP;

    float4 st = make_float4(0.f, 0.f, 0.f, 0.f);
    for (int c = 0; c < NC; c++) {
        size_t id = base4 + (size_t)c * (KD * HD / 4) + idx4;
        P4[id] = st;
        float4 a = A4[id];
        st.x = lam * st.x + a.x;
        st.y = lam * st.y + a.y;
        st.z = lam * st.z + a.z;
        st.w = lam * st.w + a.w;
    }

    if (blockIdx.x == 0 && tid < KD) {
        float pk = 0.f;
        const size_t kb = (size_t)bh * NC * KD + tid;
        for (int c = 0; c < NC; c++) {
            ksP[kb + (size_t)c * KD] = pk;
            pk = lam * pk + ksA[kb + (size_t)c * KD];
        }
    }
}

// ---------------- retention: pass C — fp16-MMA version ----------------------
#define RQH 0
#define RKH (64*36)
#define RVH (2*64*36)
#define RSCH (2*64*36 + 128*36)
#define RF2_U32 (3*64*36 + 128*36)
#define RF2_BYTES (RF2_U32 * 4)

__global__ __launch_bounds__(256, 2) void retention_final(
    const float* __restrict__ proj, const float2* __restrict__ rot,
    const float* __restrict__ stP, const float* __restrict__ ksP,
    uint32_t* __restrict__ prep)
{
    extern __shared__ uint32_t smu[];
    uint32_t* QH  = smu + RQH;
    uint32_t* KH  = smu + RKH;
    uint32_t* VH  = smu + RVH;
    uint32_t* SCH = smu + RSCH;

    __shared__ float erow[64];
    __shared__ float etab[64];
    __shared__ float pksh[64];
    __shared__ float denom_s[64];
    __shared__ float rowsum2[64][2];
    __shared__ float psum[64][2], psq[64][2];

    const int c = blockIdx.x, h = blockIdx.y, b = blockIdx.z;
    const int tid = threadIdx.x;
    const int warp = tid >> 5, lane = tid & 31;
    const int lr = lane >> 2, lc = lane & 3;
    const int mt = warp & 3;
    const int wn = warp >> 2;
    const int s0 = c * CH;
    const float decay = log1pf(-exp2f(-5.0f - (float)h));
    const float ed = expf(decay);

    {
        const size_t qbase = ((size_t)b * SS + s0) * PW + h * KD;
#pragma unroll
        for (int l = 0; l < 4; l++) {
            int i  = tid + 256 * l;
            int r  = i >> 4;
            int c4 = (i & 15) * 4;
            float4 t4 = *(const float4*)&proj[qbase + (size_t)r * PW + c4];
            t4 = rot4(t4, s0 + r, c4, rot);
            QH[r * 36 + (c4 >> 1)]     = packh2(t4.x, t4.y);
            QH[r * 36 + (c4 >> 1) + 1] = packh2(t4.z, t4.w);
            float4 k4 = *(const float4*)&proj[qbase + 1024 + (size_t)r * PW + c4];
            k4 = rot4(k4, s0 + r, c4, rot);
            KH[r * 36 + (c4 >> 1)]     = packh2(k4.x, k4.y);
            KH[r * 36 + (c4 >> 1) + 1] = packh2(k4.z, k4.w);
        }
        const size_t vbase = ((size_t)b * SS + s0) * PW + 2048 + h * HD;
#pragma unroll
        for (int l = 0; l < 16; l++) {
            int i  = tid + 256 * l;
            int t2 = i >> 7;
            int n  = i & 127;
            float v0 = proj[vbase + (size_t)(2 * t2)     * PW + n];
            float v1 = proj[vbase + (size_t)(2 * t2 + 1) * PW + n];
            VH[n * 36 + t2] = packh2(v0, v1);
        }
    }
    if (tid < 64) {
        int gs = s0 + tid;
        float rowsum = expm1f(decay * (float)(gs + 1)) / expm1f(decay);
        erow[tid] = expf(decay * (float)tid) * rsqrtf(rowsum);
        etab[tid] = expf(-decay * (float)tid);
        pksh[tid] = ksP[(((size_t)(b * HH + h)) * NC + c) * KD + tid];
    }
    __syncthreads();

    {
        float accS[4][4];
#pragma unroll
        for (int nt = 0; nt < 4; nt++)
#pragma unroll
            for (int r = 0; r < 4; r++) accS[nt][r] = 0.f;

#pragma unroll
        for (int ks = 0; ks < 4; ks++) {
            const int kb = ks * 8;
            uint32_t afr[4];
            afr[0] = QH[(mt * 16 + lr)     * 36 + kb + lc];
            afr[1] = QH[(mt * 16 + 8 + lr) * 36 + kb + lc];
            afr[2] = QH[(mt * 16 + lr)     * 36 + kb + 4 + lc];
            afr[3] = QH[(mt * 16 + 8 + lr) * 36 + kb + 4 + lc];
#pragma unroll
            for (int nt = 0; nt < 4; nt++) {
                int tl = wn * 32 + nt * 8 + lr;
                uint32_t bfr[2] = { KH[tl * 36 + kb + lc],
                                    KH[tl * 36 + kb + 4 + lc] };
                mma_f16(accS[nt], afr, bfr);
            }
        }
        const int r0 = mt * 16 + lr, r1 = r0 + 8;
        const float a0 = erow[r0], a1 = erow[r1];
        float sr0 = 0.f, sr1 = 0.f;
#pragma unroll
        for (int nt = 0; nt < 4; nt++) {
            int c0 = wn * 32 + nt * 8 + 2 * lc;
            float e0 = etab[c0], e1 = etab[c0 + 1];
            float m00 = (c0     <= r0) ? accS[nt][0] * a0 * e0 : 0.f;
            float m01 = (c0 + 1 <= r0) ? accS[nt][1] * a0 * e1 : 0.f;
            float m10 = (c0     <= r1) ? accS[nt][2] * a1 * e0 : 0.f;
            float m11 = (c0 + 1 <= r1) ? accS[nt][3] * a1 * e1 : 0.f;
            SCH[r0 * 36 + (c0 >> 1)] = packh2(m00, m01);
            SCH[r1 * 36 + (c0 >> 1)] = packh2(m10, m11);
            sr0 += m00 + m01;
            sr1 += m10 + m11;
        }
        sr0 += __shfl_xor_sync(0xffffffff, sr0, 1);
        sr0 += __shfl_xor_sync(0xffffffff, sr0, 2);
        sr1 += __shfl_xor_sync(0xffffffff, sr1, 1);
        sr1 += __shfl_xor_sync(0xffffffff, sr1, 2);
        if (lc == 0) { rowsum2[r0][wn] = sr0; rowsum2[r1][wn] = sr1; }
    }
    __syncthreads();

    if (tid < 64) {
        float dk = 0.f;
#pragma unroll 8
        for (int d2 = 0; d2 < 32; d2++) {
            float2 qv = unpackh2(QH[tid * 36 + d2]);
            dk += qv.x * pksh[2 * d2] + qv.y * pksh[2 * d2 + 1];
        }
        float tot = rowsum2[tid][0] + rowsum2[tid][1] + erow[tid] * ed * dk;
        denom_s[tid] = fmaxf(fabsf(tot), 1.0f);
    }

    float acc[8][4];
#pragma unroll
    for (int nt = 0; nt < 8; nt++)
#pragma unroll
        for (int r = 0; r < 4; r++) acc[nt][r] = 0.f;

#pragma unroll
    for (int ks = 0; ks < 4; ks++) {
        const int kb = ks * 8;
        uint32_t afr[4];
        afr[0] = SCH[(mt * 16 + lr)     * 36 + kb + lc];
        afr[1] = SCH[(mt * 16 + 8 + lr) * 36 + kb + lc];
        afr[2] = SCH[(mt * 16 + lr)     * 36 + kb + 4 + lc];
        afr[3] = SCH[(mt * 16 + 8 + lr) * 36 + kb + 4 + lc];
#pragma unroll
        for (int nt = 0; nt < 8; nt++) {
            int ncol = wn * 64 + nt * 8 + lr;
            uint32_t bfr[2] = { VH[ncol * 36 + kb + lc],
                                VH[ncol * 36 + kb + 4 + lc] };
            mma_f16(acc[nt], afr, bfr);
        }
    }
    __syncthreads();

    {
#pragma unroll
        for (int l = 0; l < 8; l++) {
            int i  = tid + 256 * l;
            int r  = i >> 5;
            int d2 = i & 31;
            float2 qv = unpackh2(QH[r * 36 + d2]);
            float cf = erow[r] * ed;
            KH[r * 36 + d2] = packh2(qv.x * cf, qv.y * cf);
        }
        const size_t pbase = (((size_t)(b * HH + h)) * NC + c) * (KD * HD);
#pragma unroll
        for (int l = 0; l < 16; l++) {
            int i  = tid + 256 * l;
            int d2 = i >> 7;
            int n  = i & 127;
            float p0 = stP[pbase + (size_t)(2 * d2)     * HD + n];
            float p1 = stP[pbase + (size_t)(2 * d2 + 1) * HD + n];
            VH[n * 36 + d2] = packh2(p0, p1);
        }
    }
    __syncthreads();

#pragma unroll
    for (int ks = 0; ks < 4; ks++) {
        const int kb = ks * 8;
        uint32_t afr[4];
        afr[0] = KH[(mt * 16 + lr)     * 36 + kb + lc];
        afr[1] = KH[(mt * 16 + 8 + lr) * 36 + kb + lc];
        afr[2] = KH[(mt * 16 + lr)     * 36 + kb + 4 + lc];
        afr[3] = KH[(mt * 16 + 8 + lr) * 36 + kb + 4 + lc];
#pragma unroll
        for (int nt = 0; nt < 8; nt++) {
            int ncol = wn * 64 + nt * 8 + lr;
            uint32_t bfr[2] = { VH[ncol * 36 + kb + lc],
                                VH[ncol * 36 + kb + 4 + lc] };
            mma_f16(acc[nt], afr, bfr);
        }
    }

    const int r0 = mt * 16 + lr, r1 = r0 + 8;
    {
        const float inv0 = 1.0f / denom_s[r0];
        const float inv1 = 1.0f / denom_s[r1];
        float s0 = 0.f, q0 = 0.f, s1 = 0.f, q1 = 0.f;
#pragma unroll
        for (int nt = 0; nt < 8; nt++) {
            acc[nt][0] *= inv0; acc[nt][1] *= inv0;
            acc[nt][2] *= inv1; acc[nt][3] *= inv1;
            s0 += acc[nt][0] + acc[nt][1];
            q0 += acc[nt][0] * acc[nt][0] + acc[nt][1] * acc[nt][1];
            s1 += acc[nt][2] + acc[nt][3];
            q1 += acc[nt][2] * acc[nt][2] + acc[nt][3] * acc[nt][3];
        }
#pragma unroll
        for (int m_ = 1; m_ <= 2; m_ <<= 1) {
            s0 += __shfl_xor_sync(0xffffffff, s0, m_);
            q0 += __shfl_xor_sync(0xffffffff, q0, m_);
            s1 += __shfl_xor_sync(0xffffffff, s1, m_);
            q1 += __shfl_xor_sync(0xffffffff, q1, m_);
        }
        if (lc == 0) {
            psum[r0][wn] = s0; psq[r0][wn] = q0;
            psum[r1][wn] = s1; psq[r1][wn] = q1;
        }
    }
    __syncthreads();

    float mu0, is0, mu1, is1;
    {
        float S = psum[r0][0] + psum[r0][1];
        float Q = psq[r0][0] + psq[r0][1];
        mu0 = S * (1.0f / 128.0f);
        is0 = rsqrtf(Q * (1.0f / 128.0f) - mu0 * mu0 + 1e-5f);
        S = psum[r1][0] + psum[r1][1];
        Q = psq[r1][0] + psq[r1][1];
        mu1 = S * (1.0f / 128.0f);
        is1 = rsqrtf(Q * (1.0f / 128.0f) - mu1 * mu1 + 1e-5f);
    }

    const size_t gbase = ((size_t)b * SS + s0) * PW + 4096 + h * HD;
    const size_t mrow0 = (size_t)b * SS + s0 + r0;
    const size_t mrow1 = mrow0 + 8;
#pragma unroll
    for (int nt = 0; nt < 8; nt++) {
        int c0 = wn * 64 + nt * 8 + 2 * lc;
        float2 g0 = *(const float2*)&proj[gbase + (size_t)r0 * PW + c0];
        float2 g1 = *(const float2*)&proj[gbase + (size_t)r1 * PW + c0];
        float o00 = (acc[nt][0] - mu0) * is0 * (g0.x / (1.0f + expf(-g0.x)));
        float o01 = (acc[nt][1] - mu0) * is0 * (g0.y / (1.0f + expf(-g0.y)));
        float o10 = (acc[nt][2] - mu1) * is1 * (g1.x / (1.0f + expf(-g1.x)));
        float o11 = (acc[nt][3] - mu1) * is1 * (g1.y / (1.0f + expf(-g1.y)));
        prep[mrow0 * K2O + h * (HD / 2) + (c0 >> 1)] = packh2(o00, o01);
        prep[mrow1 * K2O + h * (HD / 2) + (c0 >> 1)] = packh2(o10, o11);
    }
}

// ---------------- launch ---------------------------------------------------
extern "C" void kernel_launch(void* const* d_in, const int* in_sizes, int n_in,
                              void* d_out, int out_size)
{
    (void)in_sizes; (void)n_in; (void)out_size;
    const float* x  = (const float*)d_in[0];
    const float* Wq = (const float*)d_in[1];
    const float* bq = (const float*)d_in[2];
    const float* Wk = (const float*)d_in[3];
    const float* bk = (const float*)d_in[4];
    const float* Wv = (const float*)d_in[5];
    const float* bv = (const float*)d_in[6];
    const float* Wg = (const float*)d_in[7];
    const float* bg = (const float*)d_in[8];
    const float* Wo = (const float*)d_in[9];
    const float* bo = (const float*)d_in[10];
    float* out = (float*)d_out;

    float *proj, *ball, *stA, *stP, *ksA, *ksP;
    uint32_t *xp, *wallp, *wop, *prep;
    float2* rot;
    cudaGetSymbolAddress((void**)&proj,  g_proj);
    cudaGetSymbolAddress((void**)&xp,    g_xp);
    cudaGetSymbolAddress((void**)&wallp, g_wallp);
    cudaGetSymbolAddress((void**)&wop,   g_wop);
    cudaGetSymbolAddress((void**)&prep,  g_prep);
    cudaGetSymbolAddress((void**)&ball,  g_ball);
    cudaGetSymbolAddress((void**)&rot,   g_rot);
    cudaGetSymbolAddress((void**)&stA,   g_stA);
    cudaGetSymbolAddress((void**)&stP,   g_stP);
    cudaGetSymbolAddress((void**)&ksA,   g_ksA);
    cudaGetSymbolAddress((void**)&ksP,   g_ksP);

    cudaFuncSetAttribute(gemm_f16_pipe,
                         cudaFuncAttributeMaxDynamicSharedMemorySize,
                         GEMM_SMEM_BYTES);
    cudaFuncSetAttribute(chunk_state,
                         cudaFuncAttributeMaxDynamicSharedMemorySize, CS_BYTES);
    cudaFuncSetAttribute(retention_final,
                         cudaFuncAttributeMaxDynamicSharedMemorySize, RF2_BYTES);

    const float kscale = 0.125f;   // 64^-0.5 (power of two -> exact fold)
    dim3 thr(256);

    prep_x_pack<<<(MM * K2P / 4 + 255) / 256, 256>>>(x, xp);
    prep_wall_pack<<<(K2P * PW / 4 + 255) / 256, 256>>>(
        Wq, Wk, Wv, Wg, wallp, kscale);
    prep_wo_pack<<<(K2O * DD / 4 + 255) / 256, 256>>>(Wo, wop);
    prep_bias<<<(PW + 255) / 256, 256>>>(bq, bk, bv, bg, ball, kscale);
    rot_table<<<(SS * 32 + 255) / 256, 256>>>(rot);

    gemm_f16_pipe<<<dim3(PW / 128, MM / 128), thr, GEMM_SMEM_BYTES>>>(
        xp, wallp, ball, proj, PW, K2P);

    chunk_state<<<dim3(NC, HH, BB), thr, CS_BYTES>>>(proj, rot, stA, ksA);
    state_scan_par<<<dim3(8, BB * HH), thr>>>(stA, stP, ksA, ksP);
    retention_final<<<dim3(NC, HH, BB), thr, RF2_BYTES>>>(
        proj, rot, stP, ksP, prep);

    gemm_f16_pipe<<<dim3(DD / 128, MM / 128), thr, GEMM_SMEM_BYTES>>>(
        prep, wop, bo, out, DD, K2O);
}